// round 10
// baseline (speedup 1.0000x reference)
#include <cuda_runtime.h>
#include <cuda_fp16.h>
#include <math.h>
#include <stdint.h>

// Problem dims (fixed by the dataset)
constexpr int BATCH = 16384;
constexpr int D_IN  = 2048;
constexpr int H1D   = 1024;
constexpr int H2D   = 512;
constexpr int DLAT  = 256;
constexpr int KCODE = 1024;

// fp16 staging scales (powers of 2; exact rescale in epilogue)
constexpr float SA = 16.0f;
constexpr float SB = 32.0f;
constexpr float INVS = 1.0f / (16.0f * 32.0f);

// ---------------------------------------------------------------------------
// Scratch (allocation-free contract: __device__ globals)
// ---------------------------------------------------------------------------
__device__ float g_h1[(size_t)BATCH * H1D];     // enc h1 / VQ scores / dec h1
__device__ float g_h2[(size_t)BATCH * H2D];     // enc h2 / dec h2
__device__ float g_res[(size_t)BATCH * DLAT];   // z after LN, then running residual
__device__ float g_zq[(size_t)BATCH * DLAT];    // z_q_total
__device__ float g_vloss[BATCH];
__device__ int   g_idx[BATCH * 3];
__device__ float g_cbn[3 * KCODE];
// pre-split fp16 weights, [N,K] row-major, scaled by SB
__device__ __half g_w1h[(size_t)H1D * D_IN], g_w1l[(size_t)H1D * D_IN];
__device__ __half g_w2h[(size_t)H2D * H1D], g_w2l[(size_t)H2D * H1D];
__device__ __half g_w3h[(size_t)DLAT * H2D], g_w3l[(size_t)DLAT * H2D];
__device__ __half g_d1h[(size_t)H2D * DLAT], g_d1l[(size_t)H2D * DLAT];
__device__ __half g_d2h[(size_t)H1D * H2D], g_d2l[(size_t)H1D * H2D];
__device__ __half g_d3h[(size_t)D_IN * H1D], g_d3l[(size_t)D_IN * H1D];
__device__ __half g_cbh[(size_t)3 * KCODE * DLAT];   // hi-only, scaled by SB

// ---------------------------------------------------------------------------
// Helpers
// ---------------------------------------------------------------------------
__device__ __forceinline__ uint32_t smem_u32(const void* p) {
    uint32_t a;
    asm("{ .reg .u64 t; cvta.to.shared.u64 t, %1; cvt.u32.u64 %0, t; }"
        : "=r"(a) : "l"(p));
    return a;
}

__device__ __forceinline__ uint32_t pack_h2(__half a, __half b) {
    __half2 h = __halves2half2(a, b);
    return *(uint32_t*)&h;
}

// split x,y (pre-scaled) into packed fp16 hi and lo half2
__device__ __forceinline__ void split2(float x, float y,
                                       uint32_t& hi, uint32_t& lo) {
    __half hx = __float2half_rn(x), hy = __float2half_rn(y);
    __half lx = __float2half_rn(x - __half2float(hx));
    __half ly = __float2half_rn(y - __half2float(hy));
    hi = pack_h2(hx, hy);
    lo = pack_h2(lx, ly);
}

// m16n8k16 fp16 MMA (row.col), fp32 accumulate
__device__ __forceinline__ void mma16(float d[4], const uint32_t a[4],
                                      const uint32_t b[2]) {
    asm volatile(
        "mma.sync.aligned.m16n8k16.row.col.f32.f16.f16.f32 "
        "{%0,%1,%2,%3}, {%4,%5,%6,%7}, {%8,%9}, {%0,%1,%2,%3};\n"
        : "+f"(d[0]), "+f"(d[1]), "+f"(d[2]), "+f"(d[3])
        : "r"(a[0]), "r"(a[1]), "r"(a[2]), "r"(a[3]),
          "r"(b[0]), "r"(b[1]));
}

__device__ __forceinline__ void ldsm4(uint32_t& r0, uint32_t& r1,
                                      uint32_t& r2, uint32_t& r3, uint32_t addr) {
    asm volatile("ldmatrix.sync.aligned.m8n8.x4.shared.b16 {%0,%1,%2,%3}, [%4];"
                 : "=r"(r0), "=r"(r1), "=r"(r2), "=r"(r3) : "r"(addr));
}

// fp16 tile: [128 rows][32 halves] = 64B rows, 4 groups of 16B per row.
// Group g of row r stored at group (g ^ ((r>>1)&3)).  Conflict-free for all
// STS.128 store phases and all 8-address ldmatrix phases; (r+8) keeps the
// same flip so x4 ldmatrix is consistent.
__device__ __forceinline__ uint32_t tile_addr(uint32_t row, uint32_t g) {
    return row * 64 + ((g ^ ((row >> 1) & 3u)) << 4);
}

// ---------------------------------------------------------------------------
// fp16 mma.sync GEMM with pre-split B: C = act((A @ B^T)*INVS + bias)
//   A fp32 [M,K]; Bhi/Blo fp16 [N,K] pre-scaled by SB.
//   NTERMS==3: A split (hi+lo) x B (hi+lo), products hh + hl + lh
//   NTERMS==1: single-pass (A rounded, Bhi)
// Tile 128x128, BK=32 (two k16 MMA steps per barrier), 256 threads,
// 8 warps (2m x 4n). Stage: NT3 = 4 tiles x 8KB = 32KB; NT1 = 16KB.
// Double-buffered; 2 CTAs/SM.
// ---------------------------------------------------------------------------
template <int NTERMS, bool RELU, bool HASBIAS>
__global__ __launch_bounds__(256, 2)
void mma_gemm_h(const float* __restrict__ A, const __half* __restrict__ Bhi,
                const __half* __restrict__ Blo, const float* __restrict__ bias,
                float* __restrict__ C, int N, int Kd)
{
    extern __shared__ char smem[];
    const uint32_t smb = smem_u32(smem);
    constexpr int TILEB = 8192;
    constexpr int STAGE = (NTERMS == 3) ? 32768 : 16384;

    const int tid  = threadIdx.x;
    const int wid  = tid >> 5;
    const int lane = tid & 31;
    const int wm   = wid & 1;       // 0..1 -> 64 rows
    const int wn   = wid >> 1;      // 0..3 -> 32 cols

    const int nk = Kd >> 5;         // BK=32 chunks (nk >= 8)
    const float* Ag  = A   + (size_t)(blockIdx.y * 128) * Kd;
    const __half* Bh = Bhi + (size_t)(blockIdx.x * 128) * Kd;
    const __half* Bl = (NTERMS == 3) ? Blo + (size_t)(blockIdx.x * 128) * Kd : nullptr;

    // staging role: thread -> (row r, 16-half group pair {2hf, 2hf+1})
    const int r  = tid >> 1;
    const int hf = tid & 1;
    const uint32_t soff0 = tile_addr((uint32_t)r, (uint32_t)(2 * hf));
    const uint32_t soff1 = tile_addr((uint32_t)r, (uint32_t)(2 * hf + 1));

    // ldmatrix per-lane address components
    const uint32_t amat   = (uint32_t)lane >> 3;
    const uint32_t arow_l = (uint32_t)(lane & 7) + ((amat & 1u) << 3);
    const uint32_t ag     = amat >> 1;          // k sub-group within k16
    const uint32_t bmat   = (uint32_t)lane >> 3;
    const uint32_t brow_l = (uint32_t)(lane & 7) + ((bmat >> 1) << 3);
    const uint32_t bg     = bmat & 1u;

    float acc[4][4][4];
#pragma unroll
    for (int i = 0; i < 4; i++)
#pragma unroll
        for (int j = 0; j < 4; j++)
#pragma unroll
            for (int q = 0; q < 4; q++) acc[i][j][q] = 0.0f;

    float4 va[4];
    uint4 vbh[2], vbl[2];

    auto ldg = [&](int k0) {
        const float4* pa = (const float4*)(Ag + (size_t)r * Kd + k0 * 32 + hf * 16);
        va[0] = pa[0]; va[1] = pa[1]; va[2] = pa[2]; va[3] = pa[3];
        const uint4* pbh = (const uint4*)(Bh + (size_t)r * Kd + k0 * 32 + hf * 16);
        vbh[0] = pbh[0]; vbh[1] = pbh[1];
        if (NTERMS == 3) {
            const uint4* pbl = (const uint4*)(Bl + (size_t)r * Kd + k0 * 32 + hf * 16);
            vbl[0] = pbl[0]; vbl[1] = pbl[1];
        }
    };

    auto stage_store = [&](int s) {
        char* st = smem + s * STAGE;
        if (NTERMS == 3) {
            uint4 h0, h1, l0, l1;
            split2(SA * va[0].x, SA * va[0].y, h0.x, l0.x);
            split2(SA * va[0].z, SA * va[0].w, h0.y, l0.y);
            split2(SA * va[1].x, SA * va[1].y, h0.z, l0.z);
            split2(SA * va[1].z, SA * va[1].w, h0.w, l0.w);
            split2(SA * va[2].x, SA * va[2].y, h1.x, l1.x);
            split2(SA * va[2].z, SA * va[2].w, h1.y, l1.y);
            split2(SA * va[3].x, SA * va[3].y, h1.z, l1.z);
            split2(SA * va[3].z, SA * va[3].w, h1.w, l1.w);
            *(uint4*)(st + soff0)             = h0;
            *(uint4*)(st + soff1)             = h1;
            *(uint4*)(st + TILEB + soff0)     = vbh[0];
            *(uint4*)(st + TILEB + soff1)     = vbh[1];
            *(uint4*)(st + 2 * TILEB + soff0) = l0;
            *(uint4*)(st + 2 * TILEB + soff1) = l1;
            *(uint4*)(st + 3 * TILEB + soff0) = vbl[0];
            *(uint4*)(st + 3 * TILEB + soff1) = vbl[1];
        } else {
            uint4 h0, h1;
            h0.x = pack_h2(__float2half_rn(SA * va[0].x), __float2half_rn(SA * va[0].y));
            h0.y = pack_h2(__float2half_rn(SA * va[0].z), __float2half_rn(SA * va[0].w));
            h0.z = pack_h2(__float2half_rn(SA * va[1].x), __float2half_rn(SA * va[1].y));
            h0.w = pack_h2(__float2half_rn(SA * va[1].z), __float2half_rn(SA * va[1].w));
            h1.x = pack_h2(__float2half_rn(SA * va[2].x), __float2half_rn(SA * va[2].y));
            h1.y = pack_h2(__float2half_rn(SA * va[2].z), __float2half_rn(SA * va[2].w));
            h1.z = pack_h2(__float2half_rn(SA * va[3].x), __float2half_rn(SA * va[3].y));
            h1.w = pack_h2(__float2half_rn(SA * va[3].z), __float2half_rn(SA * va[3].w));
            *(uint4*)(st + soff0)         = h0;
            *(uint4*)(st + soff1)         = h1;
            *(uint4*)(st + TILEB + soff0) = vbh[0];
            *(uint4*)(st + TILEB + soff1) = vbh[1];
        }
    };

    ldg(0);
    stage_store(0);
    __syncthreads();

    for (int k0 = 0; k0 < nk; k0++) {
        if (k0 + 1 < nk) ldg(k0 + 1);

        const uint32_t stb = smb + (uint32_t)((k0 & 1) * STAGE);

#pragma unroll
        for (int ks = 0; ks < 2; ks++) {
            // B fragments for this k16 step
            uint32_t bhf[4][2], blf[4][2];
#pragma unroll
            for (int p = 0; p < 2; p++) {
                uint32_t nrow = (uint32_t)(wn * 32 + p * 16) + brow_l;
                uint32_t ba = stb + TILEB + tile_addr(nrow, 2 * ks + bg);
                ldsm4(bhf[p * 2][0], bhf[p * 2][1], bhf[p * 2 + 1][0], bhf[p * 2 + 1][1], ba);
                if (NTERMS == 3)
                    ldsm4(blf[p * 2][0], blf[p * 2][1], blf[p * 2 + 1][0], blf[p * 2 + 1][1],
                          ba + 2 * TILEB);
            }
#pragma unroll
            for (int mt = 0; mt < 4; mt++) {
                uint32_t arow = (uint32_t)(wm * 64 + mt * 16) + arow_l;
                uint32_t aa = stb + tile_addr(arow, 2 * ks + ag);
                uint32_t ah[4], al[4];
                ldsm4(ah[0], ah[1], ah[2], ah[3], aa);
                if (NTERMS == 3)
                    ldsm4(al[0], al[1], al[2], al[3], aa + 2 * TILEB);
                // per-accumulator order hh, hl, lh (bit-identical numerics)
#pragma unroll
                for (int nt = 0; nt < 4; nt++) mma16(acc[mt][nt], ah, bhf[nt]);
                if (NTERMS == 3) {
#pragma unroll
                    for (int nt = 0; nt < 4; nt++) mma16(acc[mt][nt], ah, blf[nt]);
#pragma unroll
                    for (int nt = 0; nt < 4; nt++) mma16(acc[mt][nt], al, bhf[nt]);
                }
            }
        }

        if (k0 + 1 < nk) stage_store((k0 + 1) & 1);
        __syncthreads();
    }

    // ---- epilogue (rescale by INVS, then bias/ReLU) ----
    const int row0 = blockIdx.y * 128 + wm * 64 + (lane >> 2);
    const int col0 = blockIdx.x * 128 + wn * 32 + (lane & 3) * 2;
#pragma unroll
    for (int mt = 0; mt < 4; mt++) {
#pragma unroll
        for (int nt = 0; nt < 4; nt++) {
            int rr = row0 + mt * 16;
            int cc = col0 + nt * 8;
            float b0 = 0.f, b1 = 0.f;
            if (HASBIAS) { b0 = __ldg(bias + cc); b1 = __ldg(bias + cc + 1); }
            float2 v0, v1;
            v0.x = acc[mt][nt][0] * INVS + b0; v0.y = acc[mt][nt][1] * INVS + b1;
            v1.x = acc[mt][nt][2] * INVS + b0; v1.y = acc[mt][nt][3] * INVS + b1;
            if (RELU) {
                v0.x = fmaxf(v0.x, 0.f); v0.y = fmaxf(v0.y, 0.f);
                v1.x = fmaxf(v1.x, 0.f); v1.y = fmaxf(v1.y, 0.f);
            }
            *(float2*)(C + (size_t)rr * N + cc)       = v0;
            *(float2*)(C + (size_t)(rr + 8) * N + cc) = v1;
        }
    }
}

// ---------------------------------------------------------------------------
// Prep: transpose + scale + split  W[K,N] f32 -> Thi/Tlo[N,K] half (x SB)
// ---------------------------------------------------------------------------
__global__ __launch_bounds__(256)
void transpose_convert(const float* __restrict__ W, __half* __restrict__ Thi,
                       __half* __restrict__ Tlo, int K, int N)
{
    __shared__ float tile[32][33];
    int n0 = blockIdx.x * 32;
    int k0 = blockIdx.y * 32;
#pragma unroll
    for (int i = 0; i < 32; i += 8)
        tile[threadIdx.y + i][threadIdx.x] =
            W[(size_t)(k0 + threadIdx.y + i) * N + n0 + threadIdx.x];
    __syncthreads();
#pragma unroll
    for (int i = 0; i < 32; i += 8) {
        float v = SB * tile[threadIdx.x][threadIdx.y + i];
        __half h = __float2half_rn(v);
        __half l = __float2half_rn(v - __half2float(h));
        size_t o = (size_t)(n0 + threadIdx.y + i) * K + k0 + threadIdx.x;
        Thi[o] = h;
        Tlo[o] = l;
    }
}

// Codebooks are already [N,K]; scores only need hi (NT=1).
__global__ __launch_bounds__(256)
void convert_cb_kernel(const float* __restrict__ cb0, const float* __restrict__ cb1,
                       const float* __restrict__ cb2, __half* __restrict__ out)
{
    int i = blockIdx.x * 256 + threadIdx.x;       // < 3*KCODE*DLAT
    const int S = KCODE * DLAT;
    const float* src = (i < S) ? cb0 : (i < 2 * S ? cb1 : cb2);
    out[i] = __float2half_rn(SB * src[i % S]);
}

// ---------------------------------------------------------------------------
// LayerNorm over DLAT=256, warp per row
// ---------------------------------------------------------------------------
__global__ __launch_bounds__(256)
void ln_kernel(float* __restrict__ z, const float* __restrict__ g,
               const float* __restrict__ b)
{
    int row  = blockIdx.x * 8 + (threadIdx.x >> 5);
    int lane = threadIdx.x & 31;
    float* zr = z + (size_t)row * DLAT;

    float v[8];
    float s = 0.f;
#pragma unroll
    for (int i = 0; i < 8; i++) { v[i] = zr[lane + 32 * i]; s += v[i]; }
#pragma unroll
    for (int o = 16; o; o >>= 1) s += __shfl_xor_sync(0xffffffffu, s, o);
    float mu = s * (1.0f / 256.0f);

    float s2 = 0.f;
#pragma unroll
    for (int i = 0; i < 8; i++) { float d = v[i] - mu; s2 += d * d; }
#pragma unroll
    for (int o = 16; o; o >>= 1) s2 += __shfl_xor_sync(0xffffffffu, s2, o);
    float var = s2 * (1.0f / 256.0f);
    float rs  = 1.0f / sqrtf(var + 1e-5f);

#pragma unroll
    for (int i = 0; i < 8; i++) {
        int col = lane + 32 * i;
        zr[col] = (v[i] - mu) * rs * g[col] + b[col];
    }
}

// ---------------------------------------------------------------------------
// Codebook row norms: warp per code (fp32 codebooks)
// ---------------------------------------------------------------------------
__global__ __launch_bounds__(256)
void cbnorm_kernel(const float* __restrict__ cb0, const float* __restrict__ cb1,
                   const float* __restrict__ cb2, float* __restrict__ cbn)
{
    int code = blockIdx.x * 8 + (threadIdx.x >> 5);
    int lane = threadIdx.x & 31;
    const float* cb = (code < KCODE) ? cb0 : (code < 2 * KCODE ? cb1 : cb2);
    const float* c  = cb + (size_t)(code & (KCODE - 1)) * DLAT;
    float s = 0.f;
#pragma unroll
    for (int i = 0; i < 8; i++) { float v = c[lane + 32 * i]; s += v * v; }
#pragma unroll
    for (int o = 16; o; o >>= 1) s += __shfl_xor_sync(0xffffffffu, s, o);
    if (lane == 0) cbn[code] = s;
}

// ---------------------------------------------------------------------------
// Fused VQ step with exact refinement (approx scores -> exact fp32 recheck
// of all candidates within MARGIN). Warp per row.
// ---------------------------------------------------------------------------
constexpr float VQ_MARGIN = 0.05f;

__global__ __launch_bounds__(256)
void vq_step(float* __restrict__ res, const float* __restrict__ scores,
             const float* __restrict__ cbn, const float* __restrict__ cb,
             float* __restrict__ zq, float* __restrict__ vloss,
             int* __restrict__ idx_out, int stage)
{
    int row  = blockIdx.x * 8 + (threadIdx.x >> 5);
    int lane = threadIdx.x & 31;

    float* r = res + (size_t)row * DLAT;
    float rv[8];
    float s = 0.f;
#pragma unroll
    for (int i = 0; i < 8; i++) { rv[i] = r[lane + 32 * i]; s += rv[i] * rv[i]; }
#pragma unroll
    for (int o = 16; o; o >>= 1) s += __shfl_xor_sync(0xffffffffu, s, o);
    const float rnorm = s;

    // pass 1: approximate min distance (value only)
    const float* sr = scores + (size_t)row * KCODE;
    float amin = INFINITY;
    float dv[32];
#pragma unroll 4
    for (int j = 0; j < 32; j++) {
        int n = lane + 32 * j;
        float d = (rnorm - 2.0f * sr[n]) + cbn[n];
        dv[j] = d;
        amin = fminf(amin, d);
    }
#pragma unroll
    for (int o = 16; o; o >>= 1)
        amin = fminf(amin, __shfl_xor_sync(0xffffffffu, amin, o));

    // pass 2: candidate mask per lane (bit j <-> code lane + 32j)
    const float thresh = amin + VQ_MARGIN;
    uint32_t cmask = 0;
#pragma unroll
    for (int j = 0; j < 32; j++)
        if (dv[j] <= thresh) cmask |= (1u << j);

    // warp-cooperative exact refinement, one candidate per iteration
    float bestv = INFINITY;
    int   bestn = KCODE;
    for (;;) {
        uint32_t ball = __ballot_sync(0xffffffffu, cmask != 0);
        if (!ball) break;
        int src = __ffs(ball) - 1;
        uint32_t m = __shfl_sync(0xffffffffu, cmask, src);
        int j = __ffs(m) - 1;
        if (lane == src) cmask &= cmask - 1;   // clear lowest bit
        int n = src + 32 * j;

        const float* c = cb + (size_t)n * DLAT;
        float dot = 0.f;
#pragma unroll
        for (int i = 0; i < 8; i++) dot += rv[i] * c[lane + 32 * i];
#pragma unroll
        for (int o = 16; o; o >>= 1) dot += __shfl_xor_sync(0xffffffffu, dot, o);

        float d = (rnorm - 2.0f * dot) + cbn[n];
        if (d < bestv || (d == bestv && n < bestn)) { bestv = d; bestn = n; }
    }
    const int bi = bestn;
    if (lane == 0) idx_out[row * 3 + stage] = bi;

    // straight-through update (replicates JAX numerics exactly)
    const float* c = cb + (size_t)bi * DLAT;
    float* q = zq + (size_t)row * DLAT;
    float se = 0.f;
#pragma unroll
    for (int i = 0; i < 8; i++) {
        int col = lane + 32 * i;
        float ev = c[col];
        float diff = rv[i] - ev;
        se += diff * diff;
        float t   = ev - rv[i];      // sg(e - r)
        float zqe = rv[i] + t;       // straight-through z_q
        r[col] = rv[i] - zqe;        // residual - sg(z_q)
        q[col] = (stage == 0) ? zqe : (q[col] + zqe);
    }
#pragma unroll
    for (int o = 16; o; o >>= 1) se += __shfl_xor_sync(0xffffffffu, se, o);
    if (lane == 0) {
        float m = se * (1.0f / 256.0f);
        float l = m + 0.25f * m;
        vloss[row] = (stage == 0) ? l : (vloss[row] + l);
    }
}

// ---------------------------------------------------------------------------
// Finalize: recon loss, total loss, idx -> float
// ---------------------------------------------------------------------------
__global__ __launch_bounds__(256)
void finalize_kernel(const float* __restrict__ x, const float* __restrict__ xhat,
                     const float* __restrict__ vloss, const int* __restrict__ idx,
                     float* __restrict__ out_loss, float* __restrict__ out_idx)
{
    int row  = blockIdx.x * 8 + (threadIdx.x >> 5);
    int lane = threadIdx.x & 31;

    const float* xr = x    + (size_t)row * D_IN;
    const float* hr = xhat + (size_t)row * D_IN;
    float s = 0.f;
#pragma unroll 8
    for (int i = 0; i < 64; i++) {
        int col = lane + 32 * i;
        float d = hr[col] - xr[col];
        s += d * d;
    }
#pragma unroll
    for (int o = 16; o; o >>= 1) s += __shfl_xor_sync(0xffffffffu, s, o);
    if (lane == 0) {
        float recon = s * (1.0f / 2048.0f);
        out_loss[row] = vloss[row] + recon;
    }
    if (lane < 3) out_idx[row * 3 + lane] = (float)idx[row * 3 + lane];
}

// ---------------------------------------------------------------------------
// Launch
// ---------------------------------------------------------------------------
extern "C" void kernel_launch(void* const* d_in, const int* in_sizes, int n_in,
                              void* d_out, int out_size)
{
    const float* x      = (const float*)d_in[0];
    const float* encW1  = (const float*)d_in[1];
    const float* encb1  = (const float*)d_in[2];
    const float* encW2  = (const float*)d_in[3];
    const float* encb2  = (const float*)d_in[4];
    const float* encW3  = (const float*)d_in[5];
    const float* encb3  = (const float*)d_in[6];
    const float* ln_g   = (const float*)d_in[7];
    const float* ln_b   = (const float*)d_in[8];
    const float* cb0    = (const float*)d_in[9];
    const float* cb1    = (const float*)d_in[10];
    const float* cb2    = (const float*)d_in[11];
    const float* decW1  = (const float*)d_in[12];
    const float* decb1  = (const float*)d_in[13];
    const float* decW2  = (const float*)d_in[14];
    const float* decb2  = (const float*)d_in[15];
    const float* decW3  = (const float*)d_in[16];
    const float* decb3  = (const float*)d_in[17];

    float *h1, *h2, *res, *zq, *vloss, *cbn;
    __half *w1h, *w1l, *w2h, *w2l, *w3h, *w3l;
    __half *d1h, *d1l, *d2h, *d2l, *d3h, *d3l, *cbh;
    int* idx;
    cudaGetSymbolAddress((void**)&h1, g_h1);
    cudaGetSymbolAddress((void**)&h2, g_h2);
    cudaGetSymbolAddress((void**)&res, g_res);
    cudaGetSymbolAddress((void**)&zq, g_zq);
    cudaGetSymbolAddress((void**)&vloss, g_vloss);
    cudaGetSymbolAddress((void**)&cbn, g_cbn);
    cudaGetSymbolAddress((void**)&idx, g_idx);
    cudaGetSymbolAddress((void**)&w1h, g_w1h); cudaGetSymbolAddress((void**)&w1l, g_w1l);
    cudaGetSymbolAddress((void**)&w2h, g_w2h); cudaGetSymbolAddress((void**)&w2l, g_w2l);
    cudaGetSymbolAddress((void**)&w3h, g_w3h); cudaGetSymbolAddress((void**)&w3l, g_w3l);
    cudaGetSymbolAddress((void**)&d1h, g_d1h); cudaGetSymbolAddress((void**)&d1l, g_d1l);
    cudaGetSymbolAddress((void**)&d2h, g_d2h); cudaGetSymbolAddress((void**)&d2l, g_d2l);
    cudaGetSymbolAddress((void**)&d3h, g_d3h); cudaGetSymbolAddress((void**)&d3l, g_d3l);
    cudaGetSymbolAddress((void**)&cbh, g_cbh);

    float* xhat     = (float*)d_out;
    float* out_loss = xhat + (size_t)BATCH * D_IN;
    float* out_idx  = out_loss + BATCH;

    const int SMEM3 = 2 * 32768;   // 64 KB -> 2 CTAs/SM
    const int SMEM1 = 2 * 16384;   // 32 KB
    cudaFuncSetAttribute((const void*)mma_gemm_h<3, true,  true >, cudaFuncAttributeMaxDynamicSharedMemorySize, SMEM3);
    cudaFuncSetAttribute((const void*)mma_gemm_h<3, false, true >, cudaFuncAttributeMaxDynamicSharedMemorySize, SMEM3);
    cudaFuncSetAttribute((const void*)mma_gemm_h<1, false, false>, cudaFuncAttributeMaxDynamicSharedMemorySize, SMEM1);
    cudaFuncSetAttribute((const void*)mma_gemm_h<1, true,  true >, cudaFuncAttributeMaxDynamicSharedMemorySize, SMEM1);
    cudaFuncSetAttribute((const void*)mma_gemm_h<1, false, true >, cudaFuncAttributeMaxDynamicSharedMemorySize, SMEM1);

    const dim3 blk(256);
    const dim3 tblk(32, 8);
    const int MB = BATCH / 128;          // 128
    const int warpGrid = BATCH / 8;      // 2048

    // ---- prep: transpose+split weights; codebook hi; codebook norms ----
    transpose_convert<<<dim3(H1D / 32, D_IN / 32), tblk>>>(encW1, w1h, w1l, D_IN, H1D);
    transpose_convert<<<dim3(H2D / 32, H1D / 32), tblk>>>(encW2, w2h, w2l, H1D, H2D);
    transpose_convert<<<dim3(DLAT / 32, H2D / 32), tblk>>>(encW3, w3h, w3l, H2D, DLAT);
    transpose_convert<<<dim3(H2D / 32, DLAT / 32), tblk>>>(decW1, d1h, d1l, DLAT, H2D);
    transpose_convert<<<dim3(H1D / 32, H2D / 32), tblk>>>(decW2, d2h, d2l, H2D, H1D);
    transpose_convert<<<dim3(D_IN / 32, H1D / 32), tblk>>>(decW3, d3h, d3l, H1D, D_IN);
    convert_cb_kernel<<<3 * KCODE * DLAT / 256, blk>>>(cb0, cb1, cb2, cbh);
    cbnorm_kernel<<<3 * KCODE / 8, blk>>>(cb0, cb1, cb2, cbn);

    // ---- encoder (fp16 split x3 ~ fp32 accuracy; feeds argmin) ----
    mma_gemm_h<3, true,  true ><<<dim3(H1D / 128, MB), blk, SMEM3>>>(x,  w1h, w1l, encb1, h1,  H1D,  D_IN);
    mma_gemm_h<3, true,  true ><<<dim3(H2D / 128, MB), blk, SMEM3>>>(h1, w2h, w2l, encb2, h2,  H2D,  H1D);
    mma_gemm_h<3, false, true ><<<dim3(DLAT / 128, MB), blk, SMEM3>>>(h2, w3h, w3l, encb3, res, DLAT, H2D);

    ln_kernel<<<warpGrid, blk>>>(res, ln_g, ln_b);

    // ---- residual VQ: approx scores (fp16 single) + exact refinement ----
    for (int s = 0; s < 3; s++) {
        const float* cb = (s == 0) ? cb0 : (s == 1 ? cb1 : cb2);
        mma_gemm_h<1, false, false><<<dim3(KCODE / 128, MB), blk, SMEM1>>>(res, cbh + (size_t)s * KCODE * DLAT, nullptr, nullptr, h1, KCODE, DLAT);
        vq_step<<<warpGrid, blk>>>(res, h1, cbn + s * KCODE, cb, zq, vloss, idx, s);
    }

    // ---- decoder (fp16 single-pass; post-argmin, tolerance-safe) ----
    mma_gemm_h<1, true,  true ><<<dim3(H2D / 128, MB), blk, SMEM1>>>(zq, d1h, nullptr, decb1, h2,   H2D,  DLAT);
    mma_gemm_h<1, true,  true ><<<dim3(H1D / 128, MB), blk, SMEM1>>>(h2, d2h, nullptr, decb2, h1,   H1D,  H2D);
    mma_gemm_h<1, false, true ><<<dim3(D_IN / 128, MB), blk, SMEM1>>>(h1, d3h, nullptr, decb3, xhat, D_IN, H1D);

    finalize_kernel<<<warpGrid, blk>>>(x, xhat, vloss, idx, out_loss, out_idx);
}

// round 11
// speedup vs baseline: 1.1396x; 1.1396x over previous
#include <cuda_runtime.h>
#include <cuda_fp16.h>
#include <math.h>
#include <stdint.h>

// Problem dims (fixed by the dataset)
constexpr int BATCH = 16384;
constexpr int D_IN  = 2048;
constexpr int H1D   = 1024;
constexpr int H2D   = 512;
constexpr int DLAT  = 256;
constexpr int KCODE = 1024;

// fp16 staging scales (powers of 2; exact rescale in epilogue)
constexpr float SA = 16.0f;
constexpr float SB = 32.0f;
constexpr float INVS = 1.0f / (16.0f * 32.0f);

// ---------------------------------------------------------------------------
// Scratch (allocation-free contract: __device__ globals)
// ---------------------------------------------------------------------------
__device__ float g_h1[(size_t)BATCH * H1D];     // enc h1 / VQ scores / dec h1
__device__ float g_h2[(size_t)BATCH * H2D];     // enc h2 / dec h2
__device__ float g_res[(size_t)BATCH * DLAT];   // z after LN, then running residual
__device__ float g_zq[(size_t)BATCH * DLAT];    // z_q_total
__device__ float g_part[(size_t)BATCH * 64];    // per-row recon SSE partials
// pre-split fp16 weights, [N,K] row-major, scaled by SB
__device__ float g_cbn[3 * KCODE];
__device__ __half g_w1h[(size_t)H1D * D_IN], g_w1l[(size_t)H1D * D_IN];
__device__ __half g_w2h[(size_t)H2D * H1D], g_w2l[(size_t)H2D * H1D];
__device__ __half g_w3h[(size_t)DLAT * H2D], g_w3l[(size_t)DLAT * H2D];
__device__ __half g_d1h[(size_t)H2D * DLAT], g_d1l[(size_t)H2D * DLAT];
__device__ __half g_d2h[(size_t)H1D * H2D], g_d2l[(size_t)H1D * H2D];
__device__ __half g_d3h[(size_t)D_IN * H1D], g_d3l[(size_t)D_IN * H1D];
__device__ __half g_cbh[(size_t)3 * KCODE * DLAT];   // hi-only, scaled by SB

// ---------------------------------------------------------------------------
// Helpers
// ---------------------------------------------------------------------------
__device__ __forceinline__ uint32_t smem_u32(const void* p) {
    uint32_t a;
    asm("{ .reg .u64 t; cvta.to.shared.u64 t, %1; cvt.u32.u64 %0, t; }"
        : "=r"(a) : "l"(p));
    return a;
}

__device__ __forceinline__ uint32_t pack_h2(__half a, __half b) {
    __half2 h = __halves2half2(a, b);
    return *(uint32_t*)&h;
}

// split x,y (pre-scaled) into packed fp16 hi and lo half2
__device__ __forceinline__ void split2(float x, float y,
                                       uint32_t& hi, uint32_t& lo) {
    __half hx = __float2half_rn(x), hy = __float2half_rn(y);
    __half lx = __float2half_rn(x - __half2float(hx));
    __half ly = __float2half_rn(y - __half2float(hy));
    hi = pack_h2(hx, hy);
    lo = pack_h2(lx, ly);
}

// m16n8k16 fp16 MMA (row.col), fp32 accumulate
__device__ __forceinline__ void mma16(float d[4], const uint32_t a[4],
                                      const uint32_t b[2]) {
    asm volatile(
        "mma.sync.aligned.m16n8k16.row.col.f32.f16.f16.f32 "
        "{%0,%1,%2,%3}, {%4,%5,%6,%7}, {%8,%9}, {%0,%1,%2,%3};\n"
        : "+f"(d[0]), "+f"(d[1]), "+f"(d[2]), "+f"(d[3])
        : "r"(a[0]), "r"(a[1]), "r"(a[2]), "r"(a[3]),
          "r"(b[0]), "r"(b[1]));
}

__device__ __forceinline__ void ldsm4(uint32_t& r0, uint32_t& r1,
                                      uint32_t& r2, uint32_t& r3, uint32_t addr) {
    asm volatile("ldmatrix.sync.aligned.m8n8.x4.shared.b16 {%0,%1,%2,%3}, [%4];"
                 : "=r"(r0), "=r"(r1), "=r"(r2), "=r"(r3) : "r"(addr));
}

// fp16 tile: [128 rows][16 halves] = 32B rows.
// 16B group g of row r stored at group (g ^ ((r>>2)&1)).  Conflict-free for
// staging STS.128 and every 8-address ldmatrix phase.  (R8-proven layout.)
__device__ __forceinline__ uint32_t tile_addr(uint32_t row, uint32_t g) {
    return row * 32 + ((g ^ ((row >> 2) & 1u)) << 4);
}

// ---------------------------------------------------------------------------
// fp16 mma.sync GEMM with pre-split B: C = act((A @ B^T)*INVS + bias)
//   NTERMS==3: A split (hi+lo) x B (hi+lo), products hh + hl + lh
//   NTERMS==1: single-pass (A rounded, Bhi)
//   PARTIAL: also emit per-row partial SSE of (C - X) to part[row][bx*4+wn]
// Tile 128x128, BK=16, 256 threads, 8 warps (2m x 4n).  (R8-proven core.)
// ---------------------------------------------------------------------------
template <int NTERMS, bool RELU, bool HASBIAS, bool PARTIAL>
__global__ __launch_bounds__(256, 2)
void mma_gemm_h(const float* __restrict__ A, const __half* __restrict__ Bhi,
                const __half* __restrict__ Blo, const float* __restrict__ bias,
                float* __restrict__ C, int N, int Kd,
                const float* __restrict__ X, float* __restrict__ part)
{
    extern __shared__ char smem[];
    const uint32_t smb = smem_u32(smem);
    constexpr int TILEB = 4096;
    constexpr int STAGE = (NTERMS == 3) ? 16384 : 8192;

    const int tid  = threadIdx.x;
    const int wid  = tid >> 5;
    const int lane = tid & 31;
    const int wm   = wid & 1;       // 0..1 -> 64 rows
    const int wn   = wid >> 1;      // 0..3 -> 32 cols

    const int nk = Kd >> 4;         // BK=16 chunks
    const float* Ag  = A   + (size_t)(blockIdx.y * 128) * Kd;
    const __half* Bh = Bhi + (size_t)(blockIdx.x * 128) * Kd;
    const __half* Bl = (NTERMS == 3) ? Blo + (size_t)(blockIdx.x * 128) * Kd : nullptr;

    // staging role: thread -> (row r, 8-element group hf of the 16-wide chunk)
    const int r  = tid >> 1;
    const int hf = tid & 1;
    const uint32_t soff = tile_addr((uint32_t)r, (uint32_t)hf);

    // ldmatrix per-lane address components
    const uint32_t amat   = (uint32_t)lane >> 3;
    const uint32_t arow_l = (uint32_t)(lane & 7) + ((amat & 1u) << 3);
    const uint32_t ag     = amat >> 1;
    const uint32_t bmat   = (uint32_t)lane >> 3;
    const uint32_t brow_l = (uint32_t)(lane & 7) + ((bmat >> 1) << 3);
    const uint32_t bg     = bmat & 1u;

    float acc[4][4][4];
#pragma unroll
    for (int i = 0; i < 4; i++)
#pragma unroll
        for (int j = 0; j < 4; j++)
#pragma unroll
            for (int q = 0; q < 4; q++) acc[i][j][q] = 0.0f;

    float4 va[2];
    uint4 vbh, vbl;

    auto ldg = [&](int k0) {
        const float4* pa = (const float4*)(Ag + (size_t)r * Kd + k0 * 16 + hf * 8);
        va[0] = pa[0]; va[1] = pa[1];
        vbh = *(const uint4*)(Bh + (size_t)r * Kd + k0 * 16 + hf * 8);
        if (NTERMS == 3)
            vbl = *(const uint4*)(Bl + (size_t)r * Kd + k0 * 16 + hf * 8);
    };

    auto stage_store = [&](int s) {
        char* st = smem + s * STAGE;
        uint4 ha;
        if (NTERMS == 3) {
            uint4 la;
            split2(SA * va[0].x, SA * va[0].y, ha.x, la.x);
            split2(SA * va[0].z, SA * va[0].w, ha.y, la.y);
            split2(SA * va[1].x, SA * va[1].y, ha.z, la.z);
            split2(SA * va[1].z, SA * va[1].w, ha.w, la.w);
            *(uint4*)(st + soff)             = ha;
            *(uint4*)(st + TILEB + soff)     = vbh;
            *(uint4*)(st + 2 * TILEB + soff) = la;
            *(uint4*)(st + 3 * TILEB + soff) = vbl;
        } else {
            ha.x = pack_h2(__float2half_rn(SA * va[0].x), __float2half_rn(SA * va[0].y));
            ha.y = pack_h2(__float2half_rn(SA * va[0].z), __float2half_rn(SA * va[0].w));
            ha.z = pack_h2(__float2half_rn(SA * va[1].x), __float2half_rn(SA * va[1].y));
            ha.w = pack_h2(__float2half_rn(SA * va[1].z), __float2half_rn(SA * va[1].w));
            *(uint4*)(st + soff)         = ha;
            *(uint4*)(st + TILEB + soff) = vbh;
        }
    };

    ldg(0);
    stage_store(0);
    __syncthreads();

    for (int k0 = 0; k0 < nk; k0++) {
        if (k0 + 1 < nk) ldg(k0 + 1);

        const uint32_t stb = smb + (uint32_t)((k0 & 1) * STAGE);

        uint32_t bhf[4][2], blf[4][2];
#pragma unroll
        for (int p = 0; p < 2; p++) {
            uint32_t nrow = (uint32_t)(wn * 32 + p * 16) + brow_l;
            uint32_t ba = stb + TILEB + tile_addr(nrow, bg);
            ldsm4(bhf[p * 2][0], bhf[p * 2][1], bhf[p * 2 + 1][0], bhf[p * 2 + 1][1], ba);
            if (NTERMS == 3)
                ldsm4(blf[p * 2][0], blf[p * 2][1], blf[p * 2 + 1][0], blf[p * 2 + 1][1],
                      ba + 2 * TILEB);
        }
#pragma unroll
        for (int mt = 0; mt < 4; mt++) {
            uint32_t arow = (uint32_t)(wm * 64 + mt * 16) + arow_l;
            uint32_t aa = stb + tile_addr(arow, ag);
            uint32_t ah[4], al[4];
            ldsm4(ah[0], ah[1], ah[2], ah[3], aa);
            if (NTERMS == 3)
                ldsm4(al[0], al[1], al[2], al[3], aa + 2 * TILEB);
            // per-accumulator order hh, hl, lh (bit-identical numerics)
#pragma unroll
            for (int nt = 0; nt < 4; nt++) {
                mma16(acc[mt][nt], ah, bhf[nt]);
                if (NTERMS == 3) {
                    mma16(acc[mt][nt], ah, blf[nt]);
                    mma16(acc[mt][nt], al, bhf[nt]);
                }
            }
        }

        if (k0 + 1 < nk) stage_store((k0 + 1) & 1);
        __syncthreads();
    }

    // ---- epilogue (rescale by INVS, then bias/ReLU; optional SSE partials) ----
    const int row0 = blockIdx.y * 128 + wm * 64 + (lane >> 2);
    const int col0 = blockIdx.x * 128 + wn * 32 + (lane & 3) * 2;
    float psum[4][2];
    if (PARTIAL) {
#pragma unroll
        for (int mt = 0; mt < 4; mt++) { psum[mt][0] = 0.f; psum[mt][1] = 0.f; }
    }
#pragma unroll
    for (int mt = 0; mt < 4; mt++) {
#pragma unroll
        for (int nt = 0; nt < 4; nt++) {
            int rr = row0 + mt * 16;
            int cc = col0 + nt * 8;
            float b0 = 0.f, b1 = 0.f;
            if (HASBIAS) { b0 = __ldg(bias + cc); b1 = __ldg(bias + cc + 1); }
            float2 v0, v1;
            v0.x = acc[mt][nt][0] * INVS + b0; v0.y = acc[mt][nt][1] * INVS + b1;
            v1.x = acc[mt][nt][2] * INVS + b0; v1.y = acc[mt][nt][3] * INVS + b1;
            if (RELU) {
                v0.x = fmaxf(v0.x, 0.f); v0.y = fmaxf(v0.y, 0.f);
                v1.x = fmaxf(v1.x, 0.f); v1.y = fmaxf(v1.y, 0.f);
            }
            *(float2*)(C + (size_t)rr * N + cc)       = v0;
            *(float2*)(C + (size_t)(rr + 8) * N + cc) = v1;
            if (PARTIAL) {
                float2 x0 = *(const float2*)(X + (size_t)rr * N + cc);
                float2 x1 = *(const float2*)(X + (size_t)(rr + 8) * N + cc);
                float d0 = v0.x - x0.x, d1 = v0.y - x0.y;
                float d2 = v1.x - x1.x, d3 = v1.y - x1.y;
                psum[mt][0] += d0 * d0 + d1 * d1;
                psum[mt][1] += d2 * d2 + d3 * d3;
            }
        }
    }
    if (PARTIAL) {
#pragma unroll
        for (int mt = 0; mt < 4; mt++) {
#pragma unroll
            for (int h = 0; h < 2; h++) {
                float v = psum[mt][h];
                v += __shfl_xor_sync(0xffffffffu, v, 1);
                v += __shfl_xor_sync(0xffffffffu, v, 2);
                if ((lane & 3) == 0) {
                    int rr = row0 + mt * 16 + h * 8;
                    part[(size_t)rr * 64 + blockIdx.x * 4 + wn] = v;
                }
            }
        }
    }
}

// ---------------------------------------------------------------------------
// Prep: transpose + scale + split  W[K,N] f32 -> Thi/Tlo[N,K] half (x SB)
// ---------------------------------------------------------------------------
__global__ __launch_bounds__(256)
void transpose_convert(const float* __restrict__ W, __half* __restrict__ Thi,
                       __half* __restrict__ Tlo, int K, int N)
{
    __shared__ float tile[32][33];
    int n0 = blockIdx.x * 32;
    int k0 = blockIdx.y * 32;
#pragma unroll
    for (int i = 0; i < 32; i += 8)
        tile[threadIdx.y + i][threadIdx.x] =
            W[(size_t)(k0 + threadIdx.y + i) * N + n0 + threadIdx.x];
    __syncthreads();
#pragma unroll
    for (int i = 0; i < 32; i += 8) {
        float v = SB * tile[threadIdx.x][threadIdx.y + i];
        __half h = __float2half_rn(v);
        __half l = __float2half_rn(v - __half2float(h));
        size_t o = (size_t)(n0 + threadIdx.y + i) * K + k0 + threadIdx.x;
        Thi[o] = h;
        Tlo[o] = l;
    }
}

// Codebooks are already [N,K]; scores only need hi (NT=1).
__global__ __launch_bounds__(256)
void convert_cb_kernel(const float* __restrict__ cb0, const float* __restrict__ cb1,
                       const float* __restrict__ cb2, __half* __restrict__ out)
{
    int i = blockIdx.x * 256 + threadIdx.x;       // < 3*KCODE*DLAT
    const int S = KCODE * DLAT;
    const float* src = (i < S) ? cb0 : (i < 2 * S ? cb1 : cb2);
    out[i] = __float2half_rn(SB * src[i % S]);
}

// ---------------------------------------------------------------------------
// LayerNorm over DLAT=256, warp per row
// ---------------------------------------------------------------------------
__global__ __launch_bounds__(256)
void ln_kernel(float* __restrict__ z, const float* __restrict__ g,
               const float* __restrict__ b)
{
    int row  = blockIdx.x * 8 + (threadIdx.x >> 5);
    int lane = threadIdx.x & 31;
    float* zr = z + (size_t)row * DLAT;

    float v[8];
    float s = 0.f;
#pragma unroll
    for (int i = 0; i < 8; i++) { v[i] = zr[lane + 32 * i]; s += v[i]; }
#pragma unroll
    for (int o = 16; o; o >>= 1) s += __shfl_xor_sync(0xffffffffu, s, o);
    float mu = s * (1.0f / 256.0f);

    float s2 = 0.f;
#pragma unroll
    for (int i = 0; i < 8; i++) { float d = v[i] - mu; s2 += d * d; }
#pragma unroll
    for (int o = 16; o; o >>= 1) s2 += __shfl_xor_sync(0xffffffffu, s2, o);
    float var = s2 * (1.0f / 256.0f);
    float rs  = 1.0f / sqrtf(var + 1e-5f);

#pragma unroll
    for (int i = 0; i < 8; i++) {
        int col = lane + 32 * i;
        zr[col] = (v[i] - mu) * rs * g[col] + b[col];
    }
}

// ---------------------------------------------------------------------------
// Codebook row norms: warp per code (fp32 codebooks)
// ---------------------------------------------------------------------------
__global__ __launch_bounds__(256)
void cbnorm_kernel(const float* __restrict__ cb0, const float* __restrict__ cb1,
                   const float* __restrict__ cb2, float* __restrict__ cbn)
{
    int code = blockIdx.x * 8 + (threadIdx.x >> 5);
    int lane = threadIdx.x & 31;
    const float* cb = (code < KCODE) ? cb0 : (code < 2 * KCODE ? cb1 : cb2);
    const float* c  = cb + (size_t)(code & (KCODE - 1)) * DLAT;
    float s = 0.f;
#pragma unroll
    for (int i = 0; i < 8; i++) { float v = c[lane + 32 * i]; s += v * v; }
#pragma unroll
    for (int o = 16; o; o >>= 1) s += __shfl_xor_sync(0xffffffffu, s, o);
    if (lane == 0) cbn[code] = s;
}

// ---------------------------------------------------------------------------
// Fused VQ step with exact refinement; writes out_loss (vq losses) and
// out_idx (float) directly. Warp per row.
// ---------------------------------------------------------------------------
constexpr float VQ_MARGIN = 0.05f;

__global__ __launch_bounds__(256)
void vq_step(float* __restrict__ res, const float* __restrict__ scores,
             const float* __restrict__ cbn, const float* __restrict__ cb,
             float* __restrict__ zq, float* __restrict__ out_loss,
             float* __restrict__ out_idx, int stage)
{
    int row  = blockIdx.x * 8 + (threadIdx.x >> 5);
    int lane = threadIdx.x & 31;

    float* r = res + (size_t)row * DLAT;
    float rv[8];
    float s = 0.f;
#pragma unroll
    for (int i = 0; i < 8; i++) { rv[i] = r[lane + 32 * i]; s += rv[i] * rv[i]; }
#pragma unroll
    for (int o = 16; o; o >>= 1) s += __shfl_xor_sync(0xffffffffu, s, o);
    const float rnorm = s;

    // pass 1: approximate min distance (value only)
    const float* sr = scores + (size_t)row * KCODE;
    float amin = INFINITY;
    float dv[32];
#pragma unroll 4
    for (int j = 0; j < 32; j++) {
        int n = lane + 32 * j;
        float d = (rnorm - 2.0f * sr[n]) + cbn[n];
        dv[j] = d;
        amin = fminf(amin, d);
    }
#pragma unroll
    for (int o = 16; o; o >>= 1)
        amin = fminf(amin, __shfl_xor_sync(0xffffffffu, amin, o));

    // pass 2: candidate mask per lane (bit j <-> code lane + 32j)
    const float thresh = amin + VQ_MARGIN;
    uint32_t cmask = 0;
#pragma unroll
    for (int j = 0; j < 32; j++)
        if (dv[j] <= thresh) cmask |= (1u << j);

    // warp-cooperative exact refinement, one candidate per iteration
    float bestv = INFINITY;
    int   bestn = KCODE;
    for (;;) {
        uint32_t ball = __ballot_sync(0xffffffffu, cmask != 0);
        if (!ball) break;
        int src = __ffs(ball) - 1;
        uint32_t m = __shfl_sync(0xffffffffu, cmask, src);
        int j = __ffs(m) - 1;
        if (lane == src) cmask &= cmask - 1;   // clear lowest bit
        int n = src + 32 * j;

        const float* c = cb + (size_t)n * DLAT;
        float dot = 0.f;
#pragma unroll
        for (int i = 0; i < 8; i++) dot += rv[i] * c[lane + 32 * i];
#pragma unroll
        for (int o = 16; o; o >>= 1) dot += __shfl_xor_sync(0xffffffffu, dot, o);

        float d = (rnorm - 2.0f * dot) + cbn[n];
        if (d < bestv || (d == bestv && n < bestn)) { bestv = d; bestn = n; }
    }
    const int bi = bestn;
    if (lane == 0) out_idx[row * 3 + stage] = (float)bi;

    // straight-through update (replicates JAX numerics exactly)
    const float* c = cb + (size_t)bi * DLAT;
    float* q = zq + (size_t)row * DLAT;
    float se = 0.f;
#pragma unroll
    for (int i = 0; i < 8; i++) {
        int col = lane + 32 * i;
        float ev = c[col];
        float diff = rv[i] - ev;
        se += diff * diff;
        float t   = ev - rv[i];      // sg(e - r)
        float zqe = rv[i] + t;       // straight-through z_q
        r[col] = rv[i] - zqe;        // residual - sg(z_q)
        q[col] = (stage == 0) ? zqe : (q[col] + zqe);
    }
#pragma unroll
    for (int o = 16; o; o >>= 1) se += __shfl_xor_sync(0xffffffffu, se, o);
    if (lane == 0) {
        float m = se * (1.0f / 256.0f);
        float l = m + 0.25f * m;
        out_loss[row] = (stage == 0) ? l : (out_loss[row] + l);
    }
}

// ---------------------------------------------------------------------------
// Finalize2: out_loss[row] += sum(part[row][0..63]) / 2048. Warp per row.
// ---------------------------------------------------------------------------
__global__ __launch_bounds__(256)
void finalize2_kernel(const float* __restrict__ part, float* __restrict__ out_loss)
{
    int row  = blockIdx.x * 8 + (threadIdx.x >> 5);
    int lane = threadIdx.x & 31;
    const float* p = part + (size_t)row * 64;
    float s = p[lane] + p[lane + 32];
#pragma unroll
    for (int o = 16; o; o >>= 1) s += __shfl_xor_sync(0xffffffffu, s, o);
    if (lane == 0) out_loss[row] += s * (1.0f / 2048.0f);
}

// ---------------------------------------------------------------------------
// Launch
// ---------------------------------------------------------------------------
extern "C" void kernel_launch(void* const* d_in, const int* in_sizes, int n_in,
                              void* d_out, int out_size)
{
    const float* x      = (const float*)d_in[0];
    const float* encW1  = (const float*)d_in[1];
    const float* encb1  = (const float*)d_in[2];
    const float* encW2  = (const float*)d_in[3];
    const float* encb2  = (const float*)d_in[4];
    const float* encW3  = (const float*)d_in[5];
    const float* encb3  = (const float*)d_in[6];
    const float* ln_g   = (const float*)d_in[7];
    const float* ln_b   = (const float*)d_in[8];
    const float* cb0    = (const float*)d_in[9];
    const float* cb1    = (const float*)d_in[10];
    const float* cb2    = (const float*)d_in[11];
    const float* decW1  = (const float*)d_in[12];
    const float* decb1  = (const float*)d_in[13];
    const float* decW2  = (const float*)d_in[14];
    const float* decb2  = (const float*)d_in[15];
    const float* decW3  = (const float*)d_in[16];
    const float* decb3  = (const float*)d_in[17];

    float *h1, *h2, *res, *zq, *cbn, *partp;
    __half *w1h, *w1l, *w2h, *w2l, *w3h, *w3l;
    __half *d1h, *d1l, *d2h, *d2l, *d3h, *d3l, *cbh;
    cudaGetSymbolAddress((void**)&h1, g_h1);
    cudaGetSymbolAddress((void**)&h2, g_h2);
    cudaGetSymbolAddress((void**)&res, g_res);
    cudaGetSymbolAddress((void**)&zq, g_zq);
    cudaGetSymbolAddress((void**)&cbn, g_cbn);
    cudaGetSymbolAddress((void**)&partp, g_part);
    cudaGetSymbolAddress((void**)&w1h, g_w1h); cudaGetSymbolAddress((void**)&w1l, g_w1l);
    cudaGetSymbolAddress((void**)&w2h, g_w2h); cudaGetSymbolAddress((void**)&w2l, g_w2l);
    cudaGetSymbolAddress((void**)&w3h, g_w3h); cudaGetSymbolAddress((void**)&w3l, g_w3l);
    cudaGetSymbolAddress((void**)&d1h, g_d1h); cudaGetSymbolAddress((void**)&d1l, g_d1l);
    cudaGetSymbolAddress((void**)&d2h, g_d2h); cudaGetSymbolAddress((void**)&d2l, g_d2l);
    cudaGetSymbolAddress((void**)&d3h, g_d3h); cudaGetSymbolAddress((void**)&d3l, g_d3l);
    cudaGetSymbolAddress((void**)&cbh, g_cbh);

    float* xhat     = (float*)d_out;
    float* out_loss = xhat + (size_t)BATCH * D_IN;
    float* out_idx  = out_loss + BATCH;

    const int SMEM3 = 2 * 16384;   // 32 KB
    const int SMEM1 = 2 * 8192;    // 16 KB
    cudaFuncSetAttribute((const void*)mma_gemm_h<3, true,  true,  false>, cudaFuncAttributeMaxDynamicSharedMemorySize, SMEM3);
    cudaFuncSetAttribute((const void*)mma_gemm_h<3, false, true,  false>, cudaFuncAttributeMaxDynamicSharedMemorySize, SMEM3);
    cudaFuncSetAttribute((const void*)mma_gemm_h<1, false, false, false>, cudaFuncAttributeMaxDynamicSharedMemorySize, SMEM1);
    cudaFuncSetAttribute((const void*)mma_gemm_h<1, true,  true,  false>, cudaFuncAttributeMaxDynamicSharedMemorySize, SMEM1);
    cudaFuncSetAttribute((const void*)mma_gemm_h<1, false, true,  true >, cudaFuncAttributeMaxDynamicSharedMemorySize, SMEM1);

    const dim3 blk(256);
    const dim3 tblk(32, 8);
    const int MB = BATCH / 128;          // 128
    const int warpGrid = BATCH / 8;      // 2048

    // ---- prep: transpose+split weights; codebook hi; codebook norms ----
    transpose_convert<<<dim3(H1D / 32, D_IN / 32), tblk>>>(encW1, w1h, w1l, D_IN, H1D);
    transpose_convert<<<dim3(H2D / 32, H1D / 32), tblk>>>(encW2, w2h, w2l, H1D, H2D);
    transpose_convert<<<dim3(DLAT / 32, H2D / 32), tblk>>>(encW3, w3h, w3l, H2D, DLAT);
    transpose_convert<<<dim3(H2D / 32, DLAT / 32), tblk>>>(decW1, d1h, d1l, DLAT, H2D);
    transpose_convert<<<dim3(H1D / 32, H2D / 32), tblk>>>(decW2, d2h, d2l, H2D, H1D);
    transpose_convert<<<dim3(D_IN / 32, H1D / 32), tblk>>>(decW3, d3h, d3l, H1D, D_IN);
    convert_cb_kernel<<<3 * KCODE * DLAT / 256, blk>>>(cb0, cb1, cb2, cbh);
    cbnorm_kernel<<<3 * KCODE / 8, blk>>>(cb0, cb1, cb2, cbn);

    // ---- encoder (fp16 split x3 ~ fp32 accuracy; feeds argmin) ----
    mma_gemm_h<3, true,  true,  false><<<dim3(H1D / 128, MB), blk, SMEM3>>>(x,  w1h, w1l, encb1, h1,  H1D,  D_IN, nullptr, nullptr);
    mma_gemm_h<3, true,  true,  false><<<dim3(H2D / 128, MB), blk, SMEM3>>>(h1, w2h, w2l, encb2, h2,  H2D,  H1D,  nullptr, nullptr);
    mma_gemm_h<3, false, true,  false><<<dim3(DLAT / 128, MB), blk, SMEM3>>>(h2, w3h, w3l, encb3, res, DLAT, H2D,  nullptr, nullptr);

    ln_kernel<<<warpGrid, blk>>>(res, ln_g, ln_b);

    // ---- residual VQ: approx scores (fp16 single) + exact refinement ----
    for (int s = 0; s < 3; s++) {
        const float* cb = (s == 0) ? cb0 : (s == 1 ? cb1 : cb2);
        mma_gemm_h<1, false, false, false><<<dim3(KCODE / 128, MB), blk, SMEM1>>>(res, cbh + (size_t)s * KCODE * DLAT, nullptr, nullptr, h1, KCODE, DLAT, nullptr, nullptr);
        vq_step<<<warpGrid, blk>>>(res, h1, cbn + s * KCODE, cb, zq, out_loss, out_idx, s);
    }

    // ---- decoder (fp16 single-pass; L3 fuses recon-SSE partials) ----
    mma_gemm_h<1, true,  true,  false><<<dim3(H2D / 128, MB), blk, SMEM1>>>(zq, d1h, nullptr, decb1, h2,   H2D,  DLAT, nullptr, nullptr);
    mma_gemm_h<1, true,  true,  false><<<dim3(H1D / 128, MB), blk, SMEM1>>>(h2, d2h, nullptr, decb2, h1,   H1D,  H2D,  nullptr, nullptr);
    mma_gemm_h<1, false, true,  true ><<<dim3(D_IN / 128, MB), blk, SMEM1>>>(h1, d3h, nullptr, decb3, xhat, D_IN, H1D,  x, partp);

    finalize2_kernel<<<warpGrid, blk>>>(partp, out_loss);
}

// round 12
// speedup vs baseline: 1.1891x; 1.0434x over previous
#include <cuda_runtime.h>
#include <cuda_fp16.h>
#include <math.h>
#include <stdint.h>

// Problem dims (fixed by the dataset)
constexpr int BATCH = 16384;
constexpr int D_IN  = 2048;
constexpr int H1D   = 1024;
constexpr int H2D   = 512;
constexpr int DLAT  = 256;
constexpr int KCODE = 1024;

// fp16 staging scales (powers of 2; exact rescale in epilogue)
constexpr float SA = 16.0f;
constexpr float SB = 32.0f;
constexpr float INVS = 1.0f / (16.0f * 32.0f);

constexpr float VQ_MARGIN = 0.05f;

// ---------------------------------------------------------------------------
// Scratch (allocation-free contract: __device__ globals)
// ---------------------------------------------------------------------------
__device__ float g_h1[(size_t)BATCH * H1D];     // enc h1 / dec h1
__device__ float g_h2[(size_t)BATCH * H2D];     // enc h2 / dec h2
__device__ float g_res[(size_t)BATCH * DLAT];   // z after LN, then running residual
__device__ float g_zq[(size_t)BATCH * DLAT];    // z_q_total
__device__ float g_part[(size_t)BATCH * 64];    // per-row recon SSE partials
__device__ uint32_t g_mask[(size_t)BATCH * 32]; // VQ candidate bitmasks (128b x 8 blk)
__device__ float g_cbn[3 * KCODE];
// pre-split fp16 weights, [N,K] row-major, scaled by SB
__device__ __half g_w1h[(size_t)H1D * D_IN], g_w1l[(size_t)H1D * D_IN];
__device__ __half g_w2h[(size_t)H2D * H1D], g_w2l[(size_t)H2D * H1D];
__device__ __half g_w3h[(size_t)DLAT * H2D], g_w3l[(size_t)DLAT * H2D];
__device__ __half g_d1h[(size_t)H2D * DLAT], g_d1l[(size_t)H2D * DLAT];
__device__ __half g_d2h[(size_t)H1D * H2D], g_d2l[(size_t)H1D * H2D];
__device__ __half g_d3h[(size_t)D_IN * H1D], g_d3l[(size_t)D_IN * H1D];
__device__ __half g_cbh[(size_t)3 * KCODE * DLAT];   // hi-only, scaled by SB

// ---------------------------------------------------------------------------
// Helpers
// ---------------------------------------------------------------------------
__device__ __forceinline__ uint32_t smem_u32(const void* p) {
    uint32_t a;
    asm("{ .reg .u64 t; cvta.to.shared.u64 t, %1; cvt.u32.u64 %0, t; }"
        : "=r"(a) : "l"(p));
    return a;
}

__device__ __forceinline__ uint32_t pack_h2(__half a, __half b) {
    __half2 h = __halves2half2(a, b);
    return *(uint32_t*)&h;
}

// split x,y (pre-scaled) into packed fp16 hi and lo half2
__device__ __forceinline__ void split2(float x, float y,
                                       uint32_t& hi, uint32_t& lo) {
    __half hx = __float2half_rn(x), hy = __float2half_rn(y);
    __half lx = __float2half_rn(x - __half2float(hx));
    __half ly = __float2half_rn(y - __half2float(hy));
    hi = pack_h2(hx, hy);
    lo = pack_h2(lx, ly);
}

// m16n8k16 fp16 MMA (row.col), fp32 accumulate
__device__ __forceinline__ void mma16(float d[4], const uint32_t a[4],
                                      const uint32_t b[2]) {
    asm volatile(
        "mma.sync.aligned.m16n8k16.row.col.f32.f16.f16.f32 "
        "{%0,%1,%2,%3}, {%4,%5,%6,%7}, {%8,%9}, {%0,%1,%2,%3};\n"
        : "+f"(d[0]), "+f"(d[1]), "+f"(d[2]), "+f"(d[3])
        : "r"(a[0]), "r"(a[1]), "r"(a[2]), "r"(a[3]),
          "r"(b[0]), "r"(b[1]));
}

__device__ __forceinline__ void ldsm4(uint32_t& r0, uint32_t& r1,
                                      uint32_t& r2, uint32_t& r3, uint32_t addr) {
    asm volatile("ldmatrix.sync.aligned.m8n8.x4.shared.b16 {%0,%1,%2,%3}, [%4];"
                 : "=r"(r0), "=r"(r1), "=r"(r2), "=r"(r3) : "r"(addr));
}

// fp16 tile: [128 rows][16 halves] = 32B rows.
// 16B group g of row r stored at group (g ^ ((r>>2)&1)).  (R8-proven layout.)
__device__ __forceinline__ uint32_t tile_addr(uint32_t row, uint32_t g) {
    return row * 32 + ((g ^ ((row >> 2) & 1u)) << 4);
}

// identical expression used in both min-pass and flag-pass (determinism)
__device__ __forceinline__ float dd_of(float accv, float cbnv) {
    return fmaf(accv, -2.0f * INVS, cbnv);
}

// ---------------------------------------------------------------------------
// fp16 mma.sync GEMM with pre-split B: C = act((A @ B^T)*INVS + bias)
//   NTERMS==3: A split (hi+lo) x B (hi+lo), products hh + hl + lh
//   NTERMS==1: single-pass (A rounded, Bhi)
//   PARTIAL: also emit per-row partial SSE of (C - X) to part[row][bx*4+wn]
//   SCOREMIN: VQ mode — no C write; emit per-row candidate bitmask
//             (dd = cbn - 2*dot <= block_min + MARGIN) to gmask[row][bx*4+w]
// Tile 128x128, BK=16, 256 threads, 8 warps (2m x 4n).  (R8-proven core.)
// ---------------------------------------------------------------------------
template <int NTERMS, bool RELU, bool HASBIAS, bool PARTIAL, bool SCOREMIN>
__global__ __launch_bounds__(256, 2)
void mma_gemm_h(const float* __restrict__ A, const __half* __restrict__ Bhi,
                const __half* __restrict__ Blo, const float* __restrict__ bias,
                float* __restrict__ C, int N, int Kd,
                const float* __restrict__ X, float* __restrict__ part,
                const float* __restrict__ cbnb, uint32_t* __restrict__ gmask)
{
    extern __shared__ char smem[];
    const uint32_t smb = smem_u32(smem);
    constexpr int TILEB = 4096;
    constexpr int STAGE = (NTERMS == 3) ? 16384 : 8192;

    const int tid  = threadIdx.x;
    const int wid  = tid >> 5;
    const int lane = tid & 31;
    const int wm   = wid & 1;       // 0..1 -> 64 rows
    const int wn   = wid >> 1;      // 0..3 -> 32 cols

    const int nk = Kd >> 4;         // BK=16 chunks
    const float* Ag  = A   + (size_t)(blockIdx.y * 128) * Kd;
    const __half* Bh = Bhi + (size_t)(blockIdx.x * 128) * Kd;
    const __half* Bl = (NTERMS == 3) ? Blo + (size_t)(blockIdx.x * 128) * Kd : nullptr;

    // staging role: thread -> (row r, 8-element group hf of the 16-wide chunk)
    const int r  = tid >> 1;
    const int hf = tid & 1;
    const uint32_t soff = tile_addr((uint32_t)r, (uint32_t)hf);

    // ldmatrix per-lane address components
    const uint32_t amat   = (uint32_t)lane >> 3;
    const uint32_t arow_l = (uint32_t)(lane & 7) + ((amat & 1u) << 3);
    const uint32_t ag     = amat >> 1;
    const uint32_t bmat   = (uint32_t)lane >> 3;
    const uint32_t brow_l = (uint32_t)(lane & 7) + ((bmat >> 1) << 3);
    const uint32_t bg     = bmat & 1u;

    float acc[4][4][4];
#pragma unroll
    for (int i = 0; i < 4; i++)
#pragma unroll
        for (int j = 0; j < 4; j++)
#pragma unroll
            for (int q = 0; q < 4; q++) acc[i][j][q] = 0.0f;

    float4 va[2];
    uint4 vbh, vbl;

    auto ldg = [&](int k0) {
        const float4* pa = (const float4*)(Ag + (size_t)r * Kd + k0 * 16 + hf * 8);
        va[0] = pa[0]; va[1] = pa[1];
        vbh = *(const uint4*)(Bh + (size_t)r * Kd + k0 * 16 + hf * 8);
        if (NTERMS == 3)
            vbl = *(const uint4*)(Bl + (size_t)r * Kd + k0 * 16 + hf * 8);
    };

    auto stage_store = [&](int s) {
        char* st = smem + s * STAGE;
        uint4 ha;
        if (NTERMS == 3) {
            uint4 la;
            split2(SA * va[0].x, SA * va[0].y, ha.x, la.x);
            split2(SA * va[0].z, SA * va[0].w, ha.y, la.y);
            split2(SA * va[1].x, SA * va[1].y, ha.z, la.z);
            split2(SA * va[1].z, SA * va[1].w, ha.w, la.w);
            *(uint4*)(st + soff)             = ha;
            *(uint4*)(st + TILEB + soff)     = vbh;
            *(uint4*)(st + 2 * TILEB + soff) = la;
            *(uint4*)(st + 3 * TILEB + soff) = vbl;
        } else {
            ha.x = pack_h2(__float2half_rn(SA * va[0].x), __float2half_rn(SA * va[0].y));
            ha.y = pack_h2(__float2half_rn(SA * va[0].z), __float2half_rn(SA * va[0].w));
            ha.z = pack_h2(__float2half_rn(SA * va[1].x), __float2half_rn(SA * va[1].y));
            ha.w = pack_h2(__float2half_rn(SA * va[1].z), __float2half_rn(SA * va[1].w));
            *(uint4*)(st + soff)         = ha;
            *(uint4*)(st + TILEB + soff) = vbh;
        }
    };

    ldg(0);
    stage_store(0);
    __syncthreads();

    for (int k0 = 0; k0 < nk; k0++) {
        if (k0 + 1 < nk) ldg(k0 + 1);

        const uint32_t stb = smb + (uint32_t)((k0 & 1) * STAGE);

        uint32_t bhf[4][2], blf[4][2];
#pragma unroll
        for (int p = 0; p < 2; p++) {
            uint32_t nrow = (uint32_t)(wn * 32 + p * 16) + brow_l;
            uint32_t ba = stb + TILEB + tile_addr(nrow, bg);
            ldsm4(bhf[p * 2][0], bhf[p * 2][1], bhf[p * 2 + 1][0], bhf[p * 2 + 1][1], ba);
            if (NTERMS == 3)
                ldsm4(blf[p * 2][0], blf[p * 2][1], blf[p * 2 + 1][0], blf[p * 2 + 1][1],
                      ba + 2 * TILEB);
        }
#pragma unroll
        for (int mt = 0; mt < 4; mt++) {
            uint32_t arow = (uint32_t)(wm * 64 + mt * 16) + arow_l;
            uint32_t aa = stb + tile_addr(arow, ag);
            uint32_t ah[4], al[4];
            ldsm4(ah[0], ah[1], ah[2], ah[3], aa);
            if (NTERMS == 3)
                ldsm4(al[0], al[1], al[2], al[3], aa + 2 * TILEB);
            // per-accumulator order hh, hl, lh (bit-identical numerics)
#pragma unroll
            for (int nt = 0; nt < 4; nt++) {
                mma16(acc[mt][nt], ah, bhf[nt]);
                if (NTERMS == 3) {
                    mma16(acc[mt][nt], ah, blf[nt]);
                    mma16(acc[mt][nt], al, bhf[nt]);
                }
            }
        }

        if (k0 + 1 < nk) stage_store((k0 + 1) & 1);
        __syncthreads();
    }

    if (SCOREMIN) {
        // ---- VQ scoring epilogue: block-row min + candidate bitmask ----
        // smem reuse (stage buffers are dead after the final barrier above):
        float* wmin = (float*)smem;                   // [128][4]
        float* bmin = (float*)(smem + 2048);          // [128]
        uint32_t* msk = (uint32_t*)(smem + 2560);     // [128][4]
        msk[tid] = 0; msk[tid + 256] = 0;

        // cbn for this thread's 8 code columns
        const int codec0 = blockIdx.x * 128 + wn * 32 + (lane & 3) * 2;
        float cbnv[4][2];
#pragma unroll
        for (int nt = 0; nt < 4; nt++) {
            cbnv[nt][0] = __ldg(cbnb + codec0 + nt * 8);
            cbnv[nt][1] = __ldg(cbnb + codec0 + nt * 8 + 1);
        }

        // per-(mt,h) local min over nt,q; reduce over the 4 lanes of a quad
#pragma unroll
        for (int mt = 0; mt < 4; mt++) {
#pragma unroll
            for (int h = 0; h < 2; h++) {
                float lm = INFINITY;
#pragma unroll
                for (int nt = 0; nt < 4; nt++) {
                    lm = fminf(lm, dd_of(acc[mt][nt][h * 2 + 0], cbnv[nt][0]));
                    lm = fminf(lm, dd_of(acc[mt][nt][h * 2 + 1], cbnv[nt][1]));
                }
                lm = fminf(lm, __shfl_xor_sync(0xffffffffu, lm, 1));
                lm = fminf(lm, __shfl_xor_sync(0xffffffffu, lm, 2));
                if ((lane & 3) == 0) {
                    int rl = wm * 64 + mt * 16 + h * 8 + (lane >> 2);
                    wmin[rl * 4 + wn] = lm;
                }
            }
        }
        __syncthreads();
        if (tid < 128) {
            float v = fminf(fminf(wmin[tid * 4], wmin[tid * 4 + 1]),
                            fminf(wmin[tid * 4 + 2], wmin[tid * 4 + 3]));
            bmin[tid] = v + VQ_MARGIN;
        }
        __syncthreads();
        // flag candidates (dd recomputed with identical expression)
#pragma unroll
        for (int mt = 0; mt < 4; mt++) {
#pragma unroll
            for (int h = 0; h < 2; h++) {
                int rl = wm * 64 + mt * 16 + h * 8 + (lane >> 2);
                float th = bmin[rl];
#pragma unroll
                for (int nt = 0; nt < 4; nt++) {
#pragma unroll
                    for (int q = 0; q < 2; q++) {
                        float d = dd_of(acc[mt][nt][h * 2 + q], cbnv[nt][q]);
                        if (d <= th) {
                            int bit = nt * 8 + (lane & 3) * 2 + q;
                            atomicOr(&msk[rl * 4 + wn], 1u << bit);
                        }
                    }
                }
            }
        }
        __syncthreads();
        // write masks: [row][8 blocks * 4 words], this block owns words bx*4..bx*4+3
        {
            int w0 = tid;
            gmask[(size_t)(blockIdx.y * 128 + (w0 >> 2)) * 32 + blockIdx.x * 4 + (w0 & 3)] = msk[w0];
            int w1 = tid + 256;
            gmask[(size_t)(blockIdx.y * 128 + (w1 >> 2)) * 32 + blockIdx.x * 4 + (w1 & 3)] = msk[w1];
        }
        return;
    }

    // ---- standard epilogue (rescale by INVS, bias/ReLU; optional SSE partials) ----
    const int row0 = blockIdx.y * 128 + wm * 64 + (lane >> 2);
    const int col0 = blockIdx.x * 128 + wn * 32 + (lane & 3) * 2;
    float psum[4][2];
    if (PARTIAL) {
#pragma unroll
        for (int mt = 0; mt < 4; mt++) { psum[mt][0] = 0.f; psum[mt][1] = 0.f; }
    }
#pragma unroll
    for (int mt = 0; mt < 4; mt++) {
#pragma unroll
        for (int nt = 0; nt < 4; nt++) {
            int rr = row0 + mt * 16;
            int cc = col0 + nt * 8;
            float b0 = 0.f, b1 = 0.f;
            if (HASBIAS) { b0 = __ldg(bias + cc); b1 = __ldg(bias + cc + 1); }
            float2 v0, v1;
            v0.x = acc[mt][nt][0] * INVS + b0; v0.y = acc[mt][nt][1] * INVS + b1;
            v1.x = acc[mt][nt][2] * INVS + b0; v1.y = acc[mt][nt][3] * INVS + b1;
            if (RELU) {
                v0.x = fmaxf(v0.x, 0.f); v0.y = fmaxf(v0.y, 0.f);
                v1.x = fmaxf(v1.x, 0.f); v1.y = fmaxf(v1.y, 0.f);
            }
            *(float2*)(C + (size_t)rr * N + cc)       = v0;
            *(float2*)(C + (size_t)(rr + 8) * N + cc) = v1;
            if (PARTIAL) {
                float2 x0 = *(const float2*)(X + (size_t)rr * N + cc);
                float2 x1 = *(const float2*)(X + (size_t)(rr + 8) * N + cc);
                float d0 = v0.x - x0.x, d1 = v0.y - x0.y;
                float d2 = v1.x - x1.x, d3 = v1.y - x1.y;
                psum[mt][0] += d0 * d0 + d1 * d1;
                psum[mt][1] += d2 * d2 + d3 * d3;
            }
        }
    }
    if (PARTIAL) {
#pragma unroll
        for (int mt = 0; mt < 4; mt++) {
#pragma unroll
            for (int h = 0; h < 2; h++) {
                float v = psum[mt][h];
                v += __shfl_xor_sync(0xffffffffu, v, 1);
                v += __shfl_xor_sync(0xffffffffu, v, 2);
                if ((lane & 3) == 0) {
                    int rr = row0 + mt * 16 + h * 8;
                    part[(size_t)rr * 64 + blockIdx.x * 4 + wn] = v;
                }
            }
        }
    }
}

// ---------------------------------------------------------------------------
// Prep: transpose + scale + split  W[K,N] f32 -> Thi/Tlo[N,K] half (x SB)
// ---------------------------------------------------------------------------
__global__ __launch_bounds__(256)
void transpose_convert(const float* __restrict__ W, __half* __restrict__ Thi,
                       __half* __restrict__ Tlo, int K, int N)
{
    __shared__ float tile[32][33];
    int n0 = blockIdx.x * 32;
    int k0 = blockIdx.y * 32;
#pragma unroll
    for (int i = 0; i < 32; i += 8)
        tile[threadIdx.y + i][threadIdx.x] =
            W[(size_t)(k0 + threadIdx.y + i) * N + n0 + threadIdx.x];
    __syncthreads();
#pragma unroll
    for (int i = 0; i < 32; i += 8) {
        float v = SB * tile[threadIdx.x][threadIdx.y + i];
        __half h = __float2half_rn(v);
        __half l = __float2half_rn(v - __half2float(h));
        size_t o = (size_t)(n0 + threadIdx.y + i) * K + k0 + threadIdx.x;
        Thi[o] = h;
        Tlo[o] = l;
    }
}

// Codebooks are already [N,K]; scores only need hi (NT=1).
__global__ __launch_bounds__(256)
void convert_cb_kernel(const float* __restrict__ cb0, const float* __restrict__ cb1,
                       const float* __restrict__ cb2, __half* __restrict__ out)
{
    int i = blockIdx.x * 256 + threadIdx.x;       // < 3*KCODE*DLAT
    const int S = KCODE * DLAT;
    const float* src = (i < S) ? cb0 : (i < 2 * S ? cb1 : cb2);
    out[i] = __float2half_rn(SB * src[i % S]);
}

// ---------------------------------------------------------------------------
// LayerNorm over DLAT=256, warp per row
// ---------------------------------------------------------------------------
__global__ __launch_bounds__(256)
void ln_kernel(float* __restrict__ z, const float* __restrict__ g,
               const float* __restrict__ b)
{
    int row  = blockIdx.x * 8 + (threadIdx.x >> 5);
    int lane = threadIdx.x & 31;
    float* zr = z + (size_t)row * DLAT;

    float v[8];
    float s = 0.f;
#pragma unroll
    for (int i = 0; i < 8; i++) { v[i] = zr[lane + 32 * i]; s += v[i]; }
#pragma unroll
    for (int o = 16; o; o >>= 1) s += __shfl_xor_sync(0xffffffffu, s, o);
    float mu = s * (1.0f / 256.0f);

    float s2 = 0.f;
#pragma unroll
    for (int i = 0; i < 8; i++) { float d = v[i] - mu; s2 += d * d; }
#pragma unroll
    for (int o = 16; o; o >>= 1) s2 += __shfl_xor_sync(0xffffffffu, s2, o);
    float var = s2 * (1.0f / 256.0f);
    float rs  = 1.0f / sqrtf(var + 1e-5f);

#pragma unroll
    for (int i = 0; i < 8; i++) {
        int col = lane + 32 * i;
        zr[col] = (v[i] - mu) * rs * g[col] + b[col];
    }
}

// ---------------------------------------------------------------------------
// Codebook row norms: warp per code (fp32 codebooks)
// ---------------------------------------------------------------------------
__global__ __launch_bounds__(256)
void cbnorm_kernel(const float* __restrict__ cb0, const float* __restrict__ cb1,
                   const float* __restrict__ cb2, float* __restrict__ cbn)
{
    int code = blockIdx.x * 8 + (threadIdx.x >> 5);
    int lane = threadIdx.x & 31;
    const float* cb = (code < KCODE) ? cb0 : (code < 2 * KCODE ? cb1 : cb2);
    const float* c  = cb + (size_t)(code & (KCODE - 1)) * DLAT;
    float s = 0.f;
#pragma unroll
    for (int i = 0; i < 8; i++) { float v = c[lane + 32 * i]; s += v * v; }
#pragma unroll
    for (int o = 16; o; o >>= 1) s += __shfl_xor_sync(0xffffffffu, s, o);
    if (lane == 0) cbn[code] = s;
}

// ---------------------------------------------------------------------------
// VQ step from candidate bitmasks: exact fp32 refinement over flagged codes
// (superset of the margin set; argmin with first-index tie-break), then
// straight-through update. Warp per row.
// ---------------------------------------------------------------------------
__global__ __launch_bounds__(256)
void vq_step(float* __restrict__ res, const uint32_t* __restrict__ gmask,
             const float* __restrict__ cbn, const float* __restrict__ cb,
             float* __restrict__ zq, float* __restrict__ out_loss,
             float* __restrict__ out_idx, int stage)
{
    int row  = blockIdx.x * 8 + (threadIdx.x >> 5);
    int lane = threadIdx.x & 31;

    float* r = res + (size_t)row * DLAT;
    float rv[8];
    float s = 0.f;
#pragma unroll
    for (int i = 0; i < 8; i++) { rv[i] = r[lane + 32 * i]; s += rv[i] * rv[i]; }
#pragma unroll
    for (int o = 16; o; o >>= 1) s += __shfl_xor_sync(0xffffffffu, s, o);
    const float rnorm = s;

    // lane w holds mask word w: block b = w>>2, sub-word w&3
    uint32_t cmask = __ldg(gmask + (size_t)row * 32 + lane);

    float bestv = INFINITY;
    int   bestn = KCODE;
    for (;;) {
        uint32_t ball = __ballot_sync(0xffffffffu, cmask != 0);
        if (!ball) break;
        int src = __ffs(ball) - 1;
        uint32_t m = __shfl_sync(0xffffffffu, cmask, src);
        int j = __ffs(m) - 1;
        if (lane == src) cmask &= cmask - 1;   // clear lowest bit
        int n = (src >> 2) * 128 + (src & 3) * 32 + j;

        const float* c = cb + (size_t)n * DLAT;
        float dot = 0.f;
#pragma unroll
        for (int i = 0; i < 8; i++) dot += rv[i] * c[lane + 32 * i];
#pragma unroll
        for (int o = 16; o; o >>= 1) dot += __shfl_xor_sync(0xffffffffu, dot, o);

        float d = (rnorm - 2.0f * dot) + cbn[n];
        if (d < bestv || (d == bestv && n < bestn)) { bestv = d; bestn = n; }
    }
    const int bi = bestn;
    if (lane == 0) out_idx[row * 3 + stage] = (float)bi;

    // straight-through update (replicates JAX numerics exactly)
    const float* c = cb + (size_t)bi * DLAT;
    float* q = zq + (size_t)row * DLAT;
    float se = 0.f;
#pragma unroll
    for (int i = 0; i < 8; i++) {
        int col = lane + 32 * i;
        float ev = c[col];
        float diff = rv[i] - ev;
        se += diff * diff;
        float t   = ev - rv[i];      // sg(e - r)
        float zqe = rv[i] + t;       // straight-through z_q
        r[col] = rv[i] - zqe;        // residual - sg(z_q)
        q[col] = (stage == 0) ? zqe : (q[col] + zqe);
    }
#pragma unroll
    for (int o = 16; o; o >>= 1) se += __shfl_xor_sync(0xffffffffu, se, o);
    if (lane == 0) {
        float m = se * (1.0f / 256.0f);
        float l = m + 0.25f * m;
        out_loss[row] = (stage == 0) ? l : (out_loss[row] + l);
    }
}

// ---------------------------------------------------------------------------
// Finalize2: out_loss[row] += sum(part[row][0..63]) / 2048. Warp per row.
// ---------------------------------------------------------------------------
__global__ __launch_bounds__(256)
void finalize2_kernel(const float* __restrict__ part, float* __restrict__ out_loss)
{
    int row  = blockIdx.x * 8 + (threadIdx.x >> 5);
    int lane = threadIdx.x & 31;
    const float* p = part + (size_t)row * 64;
    float s = p[lane] + p[lane + 32];
#pragma unroll
    for (int o = 16; o; o >>= 1) s += __shfl_xor_sync(0xffffffffu, s, o);
    if (lane == 0) out_loss[row] += s * (1.0f / 2048.0f);
}

// ---------------------------------------------------------------------------
// Launch
// ---------------------------------------------------------------------------
extern "C" void kernel_launch(void* const* d_in, const int* in_sizes, int n_in,
                              void* d_out, int out_size)
{
    const float* x      = (const float*)d_in[0];
    const float* encW1  = (const float*)d_in[1];
    const float* encb1  = (const float*)d_in[2];
    const float* encW2  = (const float*)d_in[3];
    const float* encb2  = (const float*)d_in[4];
    const float* encW3  = (const float*)d_in[5];
    const float* encb3  = (const float*)d_in[6];
    const float* ln_g   = (const float*)d_in[7];
    const float* ln_b   = (const float*)d_in[8];
    const float* cb0    = (const float*)d_in[9];
    const float* cb1    = (const float*)d_in[10];
    const float* cb2    = (const float*)d_in[11];
    const float* decW1  = (const float*)d_in[12];
    const float* decb1  = (const float*)d_in[13];
    const float* decW2  = (const float*)d_in[14];
    const float* decb2  = (const float*)d_in[15];
    const float* decW3  = (const float*)d_in[16];
    const float* decb3  = (const float*)d_in[17];

    float *h1, *h2, *res, *zq, *cbn, *partp;
    uint32_t* maskp;
    __half *w1h, *w1l, *w2h, *w2l, *w3h, *w3l;
    __half *d1h, *d1l, *d2h, *d2l, *d3h, *d3l, *cbh;
    cudaGetSymbolAddress((void**)&h1, g_h1);
    cudaGetSymbolAddress((void**)&h2, g_h2);
    cudaGetSymbolAddress((void**)&res, g_res);
    cudaGetSymbolAddress((void**)&zq, g_zq);
    cudaGetSymbolAddress((void**)&cbn, g_cbn);
    cudaGetSymbolAddress((void**)&partp, g_part);
    cudaGetSymbolAddress((void**)&maskp, g_mask);
    cudaGetSymbolAddress((void**)&w1h, g_w1h); cudaGetSymbolAddress((void**)&w1l, g_w1l);
    cudaGetSymbolAddress((void**)&w2h, g_w2h); cudaGetSymbolAddress((void**)&w2l, g_w2l);
    cudaGetSymbolAddress((void**)&w3h, g_w3h); cudaGetSymbolAddress((void**)&w3l, g_w3l);
    cudaGetSymbolAddress((void**)&d1h, g_d1h); cudaGetSymbolAddress((void**)&d1l, g_d1l);
    cudaGetSymbolAddress((void**)&d2h, g_d2h); cudaGetSymbolAddress((void**)&d2l, g_d2l);
    cudaGetSymbolAddress((void**)&d3h, g_d3h); cudaGetSymbolAddress((void**)&d3l, g_d3l);
    cudaGetSymbolAddress((void**)&cbh, g_cbh);

    float* xhat     = (float*)d_out;
    float* out_loss = xhat + (size_t)BATCH * D_IN;
    float* out_idx  = out_loss + BATCH;

    const int SMEM3 = 2 * 16384;   // 32 KB
    const int SMEM1 = 2 * 8192;    // 16 KB
    cudaFuncSetAttribute((const void*)mma_gemm_h<3, true,  true,  false, false>, cudaFuncAttributeMaxDynamicSharedMemorySize, SMEM3);
    cudaFuncSetAttribute((const void*)mma_gemm_h<3, false, true,  false, false>, cudaFuncAttributeMaxDynamicSharedMemorySize, SMEM3);
    cudaFuncSetAttribute((const void*)mma_gemm_h<1, false, false, false, true >, cudaFuncAttributeMaxDynamicSharedMemorySize, SMEM1);
    cudaFuncSetAttribute((const void*)mma_gemm_h<1, true,  true,  false, false>, cudaFuncAttributeMaxDynamicSharedMemorySize, SMEM1);
    cudaFuncSetAttribute((const void*)mma_gemm_h<1, false, true,  true,  false>, cudaFuncAttributeMaxDynamicSharedMemorySize, SMEM1);

    const dim3 blk(256);
    const dim3 tblk(32, 8);
    const int MB = BATCH / 128;          // 128
    const int warpGrid = BATCH / 8;      // 2048

    // ---- prep: transpose+split weights; codebook hi; codebook norms ----
    transpose_convert<<<dim3(H1D / 32, D_IN / 32), tblk>>>(encW1, w1h, w1l, D_IN, H1D);
    transpose_convert<<<dim3(H2D / 32, H1D / 32), tblk>>>(encW2, w2h, w2l, H1D, H2D);
    transpose_convert<<<dim3(DLAT / 32, H2D / 32), tblk>>>(encW3, w3h, w3l, H2D, DLAT);
    transpose_convert<<<dim3(H2D / 32, DLAT / 32), tblk>>>(decW1, d1h, d1l, DLAT, H2D);
    transpose_convert<<<dim3(H1D / 32, H2D / 32), tblk>>>(decW2, d2h, d2l, H2D, H1D);
    transpose_convert<<<dim3(D_IN / 32, H1D / 32), tblk>>>(decW3, d3h, d3l, H1D, D_IN);
    convert_cb_kernel<<<3 * KCODE * DLAT / 256, blk>>>(cb0, cb1, cb2, cbh);
    cbnorm_kernel<<<3 * KCODE / 8, blk>>>(cb0, cb1, cb2, cbn);

    // ---- encoder (fp16 split x3 ~ fp32 accuracy; feeds argmin) ----
    mma_gemm_h<3, true,  true,  false, false><<<dim3(H1D / 128, MB), blk, SMEM3>>>(x,  w1h, w1l, encb1, h1,  H1D,  D_IN, nullptr, nullptr, nullptr, nullptr);
    mma_gemm_h<3, true,  true,  false, false><<<dim3(H2D / 128, MB), blk, SMEM3>>>(h1, w2h, w2l, encb2, h2,  H2D,  H1D,  nullptr, nullptr, nullptr, nullptr);
    mma_gemm_h<3, false, true,  false, false><<<dim3(DLAT / 128, MB), blk, SMEM3>>>(h2, w3h, w3l, encb3, res, DLAT, H2D,  nullptr, nullptr, nullptr, nullptr);

    ln_kernel<<<warpGrid, blk>>>(res, ln_g, ln_b);

    // ---- residual VQ: fused score+candidate-mask GEMM, then exact refine ----
    for (int s = 0; s < 3; s++) {
        const float* cb = (s == 0) ? cb0 : (s == 1 ? cb1 : cb2);
        mma_gemm_h<1, false, false, false, true><<<dim3(KCODE / 128, MB), blk, SMEM1>>>(
            res, cbh + (size_t)s * KCODE * DLAT, nullptr, nullptr, nullptr, KCODE, DLAT,
            nullptr, nullptr, cbn + s * KCODE, maskp);
        vq_step<<<warpGrid, blk>>>(res, maskp, cbn + s * KCODE, cb, zq, out_loss, out_idx, s);
    }

    // ---- decoder (fp16 single-pass; L3 fuses recon-SSE partials) ----
    mma_gemm_h<1, true,  true,  false, false><<<dim3(H2D / 128, MB), blk, SMEM1>>>(zq, d1h, nullptr, decb1, h2,   H2D,  DLAT, nullptr, nullptr, nullptr, nullptr);
    mma_gemm_h<1, true,  true,  false, false><<<dim3(H1D / 128, MB), blk, SMEM1>>>(h2, d2h, nullptr, decb2, h1,   H1D,  H2D,  nullptr, nullptr, nullptr, nullptr);
    mma_gemm_h<1, false, true,  true,  false><<<dim3(D_IN / 128, MB), blk, SMEM1>>>(h1, d3h, nullptr, decb3, xhat, D_IN, H1D,  x, partp, nullptr, nullptr);

    finalize2_kernel<<<warpGrid, blk>>>(partp, out_loss);
}

// round 13
// speedup vs baseline: 1.2181x; 1.0245x over previous
#include <cuda_runtime.h>
#include <cuda_fp16.h>
#include <math.h>
#include <stdint.h>

// Problem dims (fixed by the dataset)
constexpr int BATCH = 16384;
constexpr int D_IN  = 2048;
constexpr int H1D   = 1024;
constexpr int H2D   = 512;
constexpr int DLAT  = 256;
constexpr int KCODE = 1024;

// fp16 staging scales (powers of 2; exact rescale in epilogue)
constexpr float SA = 16.0f;
constexpr float SB = 32.0f;
constexpr float INVS = 1.0f / (16.0f * 32.0f);

constexpr float VQ_MARGIN = 0.05f;

// ---------------------------------------------------------------------------
// Scratch (allocation-free contract: __device__ globals)
// ---------------------------------------------------------------------------
__device__ float g_h1[(size_t)BATCH * H1D];     // enc h1 / dec h1
__device__ float g_h2[(size_t)BATCH * H2D];     // enc h2 / dec h2
__device__ float g_res[(size_t)BATCH * DLAT];   // z after LN, then running residual
__device__ float g_zq[(size_t)BATCH * DLAT];    // z_q_total
__device__ float g_part[(size_t)BATCH * 64];    // per-row recon SSE partials
__device__ uint32_t g_mask[(size_t)BATCH * 32]; // VQ candidate bitmasks (128b x 8 blk)
__device__ float g_bmin[(size_t)BATCH * 8];     // per-row per-block score mins
__device__ float g_cbn[3 * KCODE];
// pre-split fp16 weights, [N,K] row-major, scaled by SB
__device__ __half g_w1h[(size_t)H1D * D_IN], g_w1l[(size_t)H1D * D_IN];
__device__ __half g_w2h[(size_t)H2D * H1D], g_w2l[(size_t)H2D * H1D];
__device__ __half g_w3h[(size_t)DLAT * H2D], g_w3l[(size_t)DLAT * H2D];
__device__ __half g_d1h[(size_t)H2D * DLAT];
__device__ __half g_d2h[(size_t)H1D * H2D];
__device__ __half g_d3h[(size_t)D_IN * H1D];
__device__ __half g_cbh[(size_t)3 * KCODE * DLAT];   // hi-only, scaled by SB

// ---------------------------------------------------------------------------
// Helpers
// ---------------------------------------------------------------------------
__device__ __forceinline__ uint32_t smem_u32(const void* p) {
    uint32_t a;
    asm("{ .reg .u64 t; cvta.to.shared.u64 t, %1; cvt.u32.u64 %0, t; }"
        : "=r"(a) : "l"(p));
    return a;
}

__device__ __forceinline__ uint32_t pack_h2(__half a, __half b) {
    __half2 h = __halves2half2(a, b);
    return *(uint32_t*)&h;
}

// split x,y (pre-scaled) into packed fp16 hi and lo half2
__device__ __forceinline__ void split2(float x, float y,
                                       uint32_t& hi, uint32_t& lo) {
    __half hx = __float2half_rn(x), hy = __float2half_rn(y);
    __half lx = __float2half_rn(x - __half2float(hx));
    __half ly = __float2half_rn(y - __half2float(hy));
    hi = pack_h2(hx, hy);
    lo = pack_h2(lx, ly);
}

// m16n8k16 fp16 MMA (row.col), fp32 accumulate
__device__ __forceinline__ void mma16(float d[4], const uint32_t a[4],
                                      const uint32_t b[2]) {
    asm volatile(
        "mma.sync.aligned.m16n8k16.row.col.f32.f16.f16.f32 "
        "{%0,%1,%2,%3}, {%4,%5,%6,%7}, {%8,%9}, {%0,%1,%2,%3};\n"
        : "+f"(d[0]), "+f"(d[1]), "+f"(d[2]), "+f"(d[3])
        : "r"(a[0]), "r"(a[1]), "r"(a[2]), "r"(a[3]),
          "r"(b[0]), "r"(b[1]));
}

__device__ __forceinline__ void ldsm4(uint32_t& r0, uint32_t& r1,
                                      uint32_t& r2, uint32_t& r3, uint32_t addr) {
    asm volatile("ldmatrix.sync.aligned.m8n8.x4.shared.b16 {%0,%1,%2,%3}, [%4];"
                 : "=r"(r0), "=r"(r1), "=r"(r2), "=r"(r3) : "r"(addr));
}

// fp16 tile: [128 rows][16 halves] = 32B rows.
// 16B group g of row r stored at group (g ^ ((r>>2)&1)).  (R8-proven layout.)
__device__ __forceinline__ uint32_t tile_addr(uint32_t row, uint32_t g) {
    return row * 32 + ((g ^ ((row >> 2) & 1u)) << 4);
}

// identical expression used in both min-pass and flag-pass (determinism)
__device__ __forceinline__ float dd_of(float accv, float cbnv) {
    return fmaf(accv, -2.0f * INVS, cbnv);
}

// ---------------------------------------------------------------------------
// fp16 mma.sync GEMM with pre-split B: C = act((A @ B^T)*INVS + bias)
//   NTERMS==3: A split (hi+lo) x B (hi+lo), products hh + hl + lh
//   NTERMS==1: single-pass (A rounded, Bhi)
//   PARTIAL: also emit per-row partial SSE of (C - X) to part[row][bx*4+wn]
//   SCOREMIN: VQ mode — no C write; emit per-row candidate bitmask and
//             per-row block-min value
// Tile 128x128, BK=16, 256 threads, 8 warps (2m x 4n).  (R8-proven core.)
// ---------------------------------------------------------------------------
template <int NTERMS, bool RELU, bool HASBIAS, bool PARTIAL, bool SCOREMIN>
__global__ __launch_bounds__(256, 2)
void mma_gemm_h(const float* __restrict__ A, const __half* __restrict__ Bhi,
                const __half* __restrict__ Blo, const float* __restrict__ bias,
                float* __restrict__ C, int N, int Kd,
                const float* __restrict__ X, float* __restrict__ part,
                const float* __restrict__ cbnb, uint32_t* __restrict__ gmask,
                float* __restrict__ gbmin)
{
    extern __shared__ char smem[];
    const uint32_t smb = smem_u32(smem);
    constexpr int TILEB = 4096;
    constexpr int STAGE = (NTERMS == 3) ? 16384 : 8192;

    const int tid  = threadIdx.x;
    const int wid  = tid >> 5;
    const int lane = tid & 31;
    const int wm   = wid & 1;       // 0..1 -> 64 rows
    const int wn   = wid >> 1;      // 0..3 -> 32 cols

    const int nk = Kd >> 4;         // BK=16 chunks
    const float* Ag  = A   + (size_t)(blockIdx.y * 128) * Kd;
    const __half* Bh = Bhi + (size_t)(blockIdx.x * 128) * Kd;
    const __half* Bl = (NTERMS == 3) ? Blo + (size_t)(blockIdx.x * 128) * Kd : nullptr;

    // staging role: thread -> (row r, 8-element group hf of the 16-wide chunk)
    const int r  = tid >> 1;
    const int hf = tid & 1;
    const uint32_t soff = tile_addr((uint32_t)r, (uint32_t)hf);

    // ldmatrix per-lane address components
    const uint32_t amat   = (uint32_t)lane >> 3;
    const uint32_t arow_l = (uint32_t)(lane & 7) + ((amat & 1u) << 3);
    const uint32_t ag     = amat >> 1;
    const uint32_t bmat   = (uint32_t)lane >> 3;
    const uint32_t brow_l = (uint32_t)(lane & 7) + ((bmat >> 1) << 3);
    const uint32_t bg     = bmat & 1u;

    float acc[4][4][4];
#pragma unroll
    for (int i = 0; i < 4; i++)
#pragma unroll
        for (int j = 0; j < 4; j++)
#pragma unroll
            for (int q = 0; q < 4; q++) acc[i][j][q] = 0.0f;

    float4 va[2];
    uint4 vbh, vbl;

    auto ldg = [&](int k0) {
        const float4* pa = (const float4*)(Ag + (size_t)r * Kd + k0 * 16 + hf * 8);
        va[0] = pa[0]; va[1] = pa[1];
        vbh = *(const uint4*)(Bh + (size_t)r * Kd + k0 * 16 + hf * 8);
        if (NTERMS == 3)
            vbl = *(const uint4*)(Bl + (size_t)r * Kd + k0 * 16 + hf * 8);
    };

    auto stage_store = [&](int s) {
        char* st = smem + s * STAGE;
        uint4 ha;
        if (NTERMS == 3) {
            uint4 la;
            split2(SA * va[0].x, SA * va[0].y, ha.x, la.x);
            split2(SA * va[0].z, SA * va[0].w, ha.y, la.y);
            split2(SA * va[1].x, SA * va[1].y, ha.z, la.z);
            split2(SA * va[1].z, SA * va[1].w, ha.w, la.w);
            *(uint4*)(st + soff)             = ha;
            *(uint4*)(st + TILEB + soff)     = vbh;
            *(uint4*)(st + 2 * TILEB + soff) = la;
            *(uint4*)(st + 3 * TILEB + soff) = vbl;
        } else {
            ha.x = pack_h2(__float2half_rn(SA * va[0].x), __float2half_rn(SA * va[0].y));
            ha.y = pack_h2(__float2half_rn(SA * va[0].z), __float2half_rn(SA * va[0].w));
            ha.z = pack_h2(__float2half_rn(SA * va[1].x), __float2half_rn(SA * va[1].y));
            ha.w = pack_h2(__float2half_rn(SA * va[1].z), __float2half_rn(SA * va[1].w));
            *(uint4*)(st + soff)         = ha;
            *(uint4*)(st + TILEB + soff) = vbh;
        }
    };

    ldg(0);
    stage_store(0);
    __syncthreads();

    for (int k0 = 0; k0 < nk; k0++) {
        if (k0 + 1 < nk) ldg(k0 + 1);

        const uint32_t stb = smb + (uint32_t)((k0 & 1) * STAGE);

        uint32_t bhf[4][2], blf[4][2];
#pragma unroll
        for (int p = 0; p < 2; p++) {
            uint32_t nrow = (uint32_t)(wn * 32 + p * 16) + brow_l;
            uint32_t ba = stb + TILEB + tile_addr(nrow, bg);
            ldsm4(bhf[p * 2][0], bhf[p * 2][1], bhf[p * 2 + 1][0], bhf[p * 2 + 1][1], ba);
            if (NTERMS == 3)
                ldsm4(blf[p * 2][0], blf[p * 2][1], blf[p * 2 + 1][0], blf[p * 2 + 1][1],
                      ba + 2 * TILEB);
        }
#pragma unroll
        for (int mt = 0; mt < 4; mt++) {
            uint32_t arow = (uint32_t)(wm * 64 + mt * 16) + arow_l;
            uint32_t aa = stb + tile_addr(arow, ag);
            uint32_t ah[4], al[4];
            ldsm4(ah[0], ah[1], ah[2], ah[3], aa);
            if (NTERMS == 3)
                ldsm4(al[0], al[1], al[2], al[3], aa + 2 * TILEB);
            // per-accumulator order hh, hl, lh (bit-identical numerics)
#pragma unroll
            for (int nt = 0; nt < 4; nt++) {
                mma16(acc[mt][nt], ah, bhf[nt]);
                if (NTERMS == 3) {
                    mma16(acc[mt][nt], ah, blf[nt]);
                    mma16(acc[mt][nt], al, bhf[nt]);
                }
            }
        }

        if (k0 + 1 < nk) stage_store((k0 + 1) & 1);
        __syncthreads();
    }

    if (SCOREMIN) {
        // ---- VQ scoring epilogue: block-row min + candidate bitmask ----
        float* wmin = (float*)smem;                   // [128][4]
        float* bmin = (float*)(smem + 2048);          // [128]
        uint32_t* msk = (uint32_t*)(smem + 2560);     // [128][4]
        msk[tid] = 0; msk[tid + 256] = 0;

        const int codec0 = blockIdx.x * 128 + wn * 32 + (lane & 3) * 2;
        float cbnv[4][2];
#pragma unroll
        for (int nt = 0; nt < 4; nt++) {
            cbnv[nt][0] = __ldg(cbnb + codec0 + nt * 8);
            cbnv[nt][1] = __ldg(cbnb + codec0 + nt * 8 + 1);
        }

#pragma unroll
        for (int mt = 0; mt < 4; mt++) {
#pragma unroll
            for (int h = 0; h < 2; h++) {
                float lm = INFINITY;
#pragma unroll
                for (int nt = 0; nt < 4; nt++) {
                    lm = fminf(lm, dd_of(acc[mt][nt][h * 2 + 0], cbnv[nt][0]));
                    lm = fminf(lm, dd_of(acc[mt][nt][h * 2 + 1], cbnv[nt][1]));
                }
                lm = fminf(lm, __shfl_xor_sync(0xffffffffu, lm, 1));
                lm = fminf(lm, __shfl_xor_sync(0xffffffffu, lm, 2));
                if ((lane & 3) == 0) {
                    int rl = wm * 64 + mt * 16 + h * 8 + (lane >> 2);
                    wmin[rl * 4 + wn] = lm;
                }
            }
        }
        __syncthreads();
        if (tid < 128) {
            float v = fminf(fminf(wmin[tid * 4], wmin[tid * 4 + 1]),
                            fminf(wmin[tid * 4 + 2], wmin[tid * 4 + 3]));
            gbmin[(size_t)(blockIdx.y * 128 + tid) * 8 + blockIdx.x] = v;
            bmin[tid] = v + VQ_MARGIN;
        }
        __syncthreads();
#pragma unroll
        for (int mt = 0; mt < 4; mt++) {
#pragma unroll
            for (int h = 0; h < 2; h++) {
                int rl = wm * 64 + mt * 16 + h * 8 + (lane >> 2);
                float th = bmin[rl];
#pragma unroll
                for (int nt = 0; nt < 4; nt++) {
#pragma unroll
                    for (int q = 0; q < 2; q++) {
                        float d = dd_of(acc[mt][nt][h * 2 + q], cbnv[nt][q]);
                        if (d <= th) {
                            int bit = nt * 8 + (lane & 3) * 2 + q;
                            atomicOr(&msk[rl * 4 + wn], 1u << bit);
                        }
                    }
                }
            }
        }
        __syncthreads();
        {
            int w0 = tid;
            gmask[(size_t)(blockIdx.y * 128 + (w0 >> 2)) * 32 + blockIdx.x * 4 + (w0 & 3)] = msk[w0];
            int w1 = tid + 256;
            gmask[(size_t)(blockIdx.y * 128 + (w1 >> 2)) * 32 + blockIdx.x * 4 + (w1 & 3)] = msk[w1];
        }
        return;
    }

    // ---- standard epilogue (rescale by INVS, bias/ReLU; optional SSE partials) ----
    const int row0 = blockIdx.y * 128 + wm * 64 + (lane >> 2);
    const int col0 = blockIdx.x * 128 + wn * 32 + (lane & 3) * 2;
    float psum[4][2];
    if (PARTIAL) {
#pragma unroll
        for (int mt = 0; mt < 4; mt++) { psum[mt][0] = 0.f; psum[mt][1] = 0.f; }
    }
#pragma unroll
    for (int mt = 0; mt < 4; mt++) {
#pragma unroll
        for (int nt = 0; nt < 4; nt++) {
            int rr = row0 + mt * 16;
            int cc = col0 + nt * 8;
            float b0 = 0.f, b1 = 0.f;
            if (HASBIAS) { b0 = __ldg(bias + cc); b1 = __ldg(bias + cc + 1); }
            float2 v0, v1;
            v0.x = acc[mt][nt][0] * INVS + b0; v0.y = acc[mt][nt][1] * INVS + b1;
            v1.x = acc[mt][nt][2] * INVS + b0; v1.y = acc[mt][nt][3] * INVS + b1;
            if (RELU) {
                v0.x = fmaxf(v0.x, 0.f); v0.y = fmaxf(v0.y, 0.f);
                v1.x = fmaxf(v1.x, 0.f); v1.y = fmaxf(v1.y, 0.f);
            }
            *(float2*)(C + (size_t)rr * N + cc)       = v0;
            *(float2*)(C + (size_t)(rr + 8) * N + cc) = v1;
            if (PARTIAL) {
                float2 x0 = *(const float2*)(X + (size_t)rr * N + cc);
                float2 x1 = *(const float2*)(X + (size_t)(rr + 8) * N + cc);
                float d0 = v0.x - x0.x, d1 = v0.y - x0.y;
                float d2 = v1.x - x1.x, d3 = v1.y - x1.y;
                psum[mt][0] += d0 * d0 + d1 * d1;
                psum[mt][1] += d2 * d2 + d3 * d3;
            }
        }
    }
    if (PARTIAL) {
#pragma unroll
        for (int mt = 0; mt < 4; mt++) {
#pragma unroll
            for (int h = 0; h < 2; h++) {
                float v = psum[mt][h];
                v += __shfl_xor_sync(0xffffffffu, v, 1);
                v += __shfl_xor_sync(0xffffffffu, v, 2);
                if ((lane & 3) == 0) {
                    int rr = row0 + mt * 16 + h * 8;
                    part[(size_t)rr * 64 + blockIdx.x * 4 + wn] = v;
                }
            }
        }
    }
}

// ---------------------------------------------------------------------------
// Prep: transpose + scale + split  W[K,N] f32 -> Thi[/Tlo][N,K] half (x SB)
// ---------------------------------------------------------------------------
template <bool WLO>
__global__ __launch_bounds__(256)
void transpose_convert(const float* __restrict__ W, __half* __restrict__ Thi,
                       __half* __restrict__ Tlo, int K, int N)
{
    __shared__ float tile[32][33];
    int n0 = blockIdx.x * 32;
    int k0 = blockIdx.y * 32;
#pragma unroll
    for (int i = 0; i < 32; i += 8)
        tile[threadIdx.y + i][threadIdx.x] =
            W[(size_t)(k0 + threadIdx.y + i) * N + n0 + threadIdx.x];
    __syncthreads();
#pragma unroll
    for (int i = 0; i < 32; i += 8) {
        float v = SB * tile[threadIdx.x][threadIdx.y + i];
        __half h = __float2half_rn(v);
        size_t o = (size_t)(n0 + threadIdx.y + i) * K + k0 + threadIdx.x;
        Thi[o] = h;
        if (WLO) Tlo[o] = __float2half_rn(v - __half2float(h));
    }
}

// Codebooks: warp per code — fp32 row norm + scaled fp16 hi conversion.
__global__ __launch_bounds__(256)
void cb_prep_kernel(const float* __restrict__ cb0, const float* __restrict__ cb1,
                    const float* __restrict__ cb2, __half* __restrict__ outh,
                    float* __restrict__ cbn)
{
    int code = blockIdx.x * 8 + (threadIdx.x >> 5);   // 0..3071
    int lane = threadIdx.x & 31;
    const float* cb = (code < KCODE) ? cb0 : (code < 2 * KCODE ? cb1 : cb2);
    const float* c  = cb + (size_t)(code & (KCODE - 1)) * DLAT;
    __half* oh = outh + (size_t)code * DLAT;
    float s = 0.f;
#pragma unroll
    for (int i = 0; i < 8; i++) {
        float v = c[lane + 32 * i];
        s += v * v;
        oh[lane + 32 * i] = __float2half_rn(SB * v);
    }
#pragma unroll
    for (int o = 16; o; o >>= 1) s += __shfl_xor_sync(0xffffffffu, s, o);
    if (lane == 0) cbn[code] = s;
}

// ---------------------------------------------------------------------------
// LayerNorm over DLAT=256, warp per row
// ---------------------------------------------------------------------------
__global__ __launch_bounds__(256)
void ln_kernel(float* __restrict__ z, const float* __restrict__ g,
               const float* __restrict__ b)
{
    int row  = blockIdx.x * 8 + (threadIdx.x >> 5);
    int lane = threadIdx.x & 31;
    float* zr = z + (size_t)row * DLAT;

    float v[8];
    float s = 0.f;
#pragma unroll
    for (int i = 0; i < 8; i++) { v[i] = zr[lane + 32 * i]; s += v[i]; }
#pragma unroll
    for (int o = 16; o; o >>= 1) s += __shfl_xor_sync(0xffffffffu, s, o);
    float mu = s * (1.0f / 256.0f);

    float s2 = 0.f;
#pragma unroll
    for (int i = 0; i < 8; i++) { float d = v[i] - mu; s2 += d * d; }
#pragma unroll
    for (int o = 16; o; o >>= 1) s2 += __shfl_xor_sync(0xffffffffu, s2, o);
    float var = s2 * (1.0f / 256.0f);
    float rs  = 1.0f / sqrtf(var + 1e-5f);

#pragma unroll
    for (int i = 0; i < 8; i++) {
        int col = lane + 32 * i;
        zr[col] = (v[i] - mu) * rs * g[col] + b[col];
    }
}

// ---------------------------------------------------------------------------
// VQ step from candidate bitmasks + block mins: prune blocks above
// gmin + MARGIN, exact fp32 refinement over surviving flagged codes, then
// straight-through update. Warp per row. LAST: skip dead residual write.
// ---------------------------------------------------------------------------
__global__ __launch_bounds__(256)
void vq_step(float* __restrict__ res, const uint32_t* __restrict__ gmask,
             const float* __restrict__ gbmin,
             const float* __restrict__ cbn, const float* __restrict__ cb,
             float* __restrict__ zq, float* __restrict__ out_loss,
             float* __restrict__ out_idx, int stage)
{
    int row  = blockIdx.x * 8 + (threadIdx.x >> 5);
    int lane = threadIdx.x & 31;

    float* r = res + (size_t)row * DLAT;
    float rv[8];
    float s = 0.f;
#pragma unroll
    for (int i = 0; i < 8; i++) { rv[i] = r[lane + 32 * i]; s += rv[i] * rv[i]; }
#pragma unroll
    for (int o = 16; o; o >>= 1) s += __shfl_xor_sync(0xffffffffu, s, o);
    const float rnorm = s;

    // block mins -> global threshold; prune mask words of implausible blocks
    float bm = (lane < 8) ? __ldg(gbmin + (size_t)row * 8 + lane) : INFINITY;
    float gmin = bm;
#pragma unroll
    for (int o = 16; o; o >>= 1) gmin = fminf(gmin, __shfl_xor_sync(0xffffffffu, gmin, o));
    const float th = gmin + VQ_MARGIN;
    float myblk = __shfl_sync(0xffffffffu, bm, lane >> 2);  // block of word `lane`

    uint32_t cmask = __ldg(gmask + (size_t)row * 32 + lane);
    if (myblk > th) cmask = 0;

    float bestv = INFINITY;
    int   bestn = KCODE;
    for (;;) {
        uint32_t ball = __ballot_sync(0xffffffffu, cmask != 0);
        if (!ball) break;
        int src = __ffs(ball) - 1;
        uint32_t m = __shfl_sync(0xffffffffu, cmask, src);
        int j = __ffs(m) - 1;
        if (lane == src) cmask &= cmask - 1;   // clear lowest bit
        int n = (src >> 2) * 128 + (src & 3) * 32 + j;

        const float* c = cb + (size_t)n * DLAT;
        float dot = 0.f;
#pragma unroll
        for (int i = 0; i < 8; i++) dot += rv[i] * c[lane + 32 * i];
#pragma unroll
        for (int o = 16; o; o >>= 1) dot += __shfl_xor_sync(0xffffffffu, dot, o);

        float d = (rnorm - 2.0f * dot) + cbn[n];
        if (d < bestv || (d == bestv && n < bestn)) { bestv = d; bestn = n; }
    }
    const int bi = bestn;
    if (lane == 0) out_idx[row * 3 + stage] = (float)bi;

    // straight-through update (replicates JAX numerics exactly)
    const float* c = cb + (size_t)bi * DLAT;
    float* q = zq + (size_t)row * DLAT;
    float se = 0.f;
#pragma unroll
    for (int i = 0; i < 8; i++) {
        int col = lane + 32 * i;
        float ev = c[col];
        float diff = rv[i] - ev;
        se += diff * diff;
        float t   = ev - rv[i];      // sg(e - r)
        float zqe = rv[i] + t;       // straight-through z_q
        if (stage < 2) r[col] = rv[i] - zqe;   // residual dead after stage 2
        q[col] = (stage == 0) ? zqe : (q[col] + zqe);
    }
#pragma unroll
    for (int o = 16; o; o >>= 1) se += __shfl_xor_sync(0xffffffffu, se, o);
    if (lane == 0) {
        float m = se * (1.0f / 256.0f);
        float l = m + 0.25f * m;
        out_loss[row] = (stage == 0) ? l : (out_loss[row] + l);
    }
}

// ---------------------------------------------------------------------------
// Finalize2: out_loss[row] += sum(part[row][0..63]) / 2048. Warp per row.
// ---------------------------------------------------------------------------
__global__ __launch_bounds__(256)
void finalize2_kernel(const float* __restrict__ part, float* __restrict__ out_loss)
{
    int row  = blockIdx.x * 8 + (threadIdx.x >> 5);
    int lane = threadIdx.x & 31;
    const float* p = part + (size_t)row * 64;
    float s = p[lane] + p[lane + 32];
#pragma unroll
    for (int o = 16; o; o >>= 1) s += __shfl_xor_sync(0xffffffffu, s, o);
    if (lane == 0) out_loss[row] += s * (1.0f / 2048.0f);
}

// ---------------------------------------------------------------------------
// Launch
// ---------------------------------------------------------------------------
extern "C" void kernel_launch(void* const* d_in, const int* in_sizes, int n_in,
                              void* d_out, int out_size)
{
    const float* x      = (const float*)d_in[0];
    const float* encW1  = (const float*)d_in[1];
    const float* encb1  = (const float*)d_in[2];
    const float* encW2  = (const float*)d_in[3];
    const float* encb2  = (const float*)d_in[4];
    const float* encW3  = (const float*)d_in[5];
    const float* encb3  = (const float*)d_in[6];
    const float* ln_g   = (const float*)d_in[7];
    const float* ln_b   = (const float*)d_in[8];
    const float* cb0    = (const float*)d_in[9];
    const float* cb1    = (const float*)d_in[10];
    const float* cb2    = (const float*)d_in[11];
    const float* decW1  = (const float*)d_in[12];
    const float* decb1  = (const float*)d_in[13];
    const float* decW2  = (const float*)d_in[14];
    const float* decb2  = (const float*)d_in[15];
    const float* decW3  = (const float*)d_in[16];
    const float* decb3  = (const float*)d_in[17];

    float *h1, *h2, *res, *zq, *cbn, *partp, *bminp;
    uint32_t* maskp;
    __half *w1h, *w1l, *w2h, *w2l, *w3h, *w3l;
    __half *d1h, *d2h, *d3h, *cbh;
    cudaGetSymbolAddress((void**)&h1, g_h1);
    cudaGetSymbolAddress((void**)&h2, g_h2);
    cudaGetSymbolAddress((void**)&res, g_res);
    cudaGetSymbolAddress((void**)&zq, g_zq);
    cudaGetSymbolAddress((void**)&cbn, g_cbn);
    cudaGetSymbolAddress((void**)&partp, g_part);
    cudaGetSymbolAddress((void**)&maskp, g_mask);
    cudaGetSymbolAddress((void**)&bminp, g_bmin);
    cudaGetSymbolAddress((void**)&w1h, g_w1h); cudaGetSymbolAddress((void**)&w1l, g_w1l);
    cudaGetSymbolAddress((void**)&w2h, g_w2h); cudaGetSymbolAddress((void**)&w2l, g_w2l);
    cudaGetSymbolAddress((void**)&w3h, g_w3h); cudaGetSymbolAddress((void**)&w3l, g_w3l);
    cudaGetSymbolAddress((void**)&d1h, g_d1h);
    cudaGetSymbolAddress((void**)&d2h, g_d2h);
    cudaGetSymbolAddress((void**)&d3h, g_d3h);
    cudaGetSymbolAddress((void**)&cbh, g_cbh);

    float* xhat     = (float*)d_out;
    float* out_loss = xhat + (size_t)BATCH * D_IN;
    float* out_idx  = out_loss + BATCH;

    const int SMEM3 = 2 * 16384;   // 32 KB
    const int SMEM1 = 2 * 8192;    // 16 KB
    cudaFuncSetAttribute((const void*)mma_gemm_h<3, true,  true,  false, false>, cudaFuncAttributeMaxDynamicSharedMemorySize, SMEM3);
    cudaFuncSetAttribute((const void*)mma_gemm_h<3, false, true,  false, false>, cudaFuncAttributeMaxDynamicSharedMemorySize, SMEM3);
    cudaFuncSetAttribute((const void*)mma_gemm_h<1, false, false, false, true >, cudaFuncAttributeMaxDynamicSharedMemorySize, SMEM1);
    cudaFuncSetAttribute((const void*)mma_gemm_h<1, true,  true,  false, false>, cudaFuncAttributeMaxDynamicSharedMemorySize, SMEM1);
    cudaFuncSetAttribute((const void*)mma_gemm_h<1, false, true,  true,  false>, cudaFuncAttributeMaxDynamicSharedMemorySize, SMEM1);

    const dim3 blk(256);
    const dim3 tblk(32, 8);
    const int MB = BATCH / 128;          // 128
    const int warpGrid = BATCH / 8;      // 2048

    // ---- prep: transpose+split weights; codebook hi + norms ----
    transpose_convert<true ><<<dim3(H1D / 32, D_IN / 32), tblk>>>(encW1, w1h, w1l, D_IN, H1D);
    transpose_convert<true ><<<dim3(H2D / 32, H1D / 32), tblk>>>(encW2, w2h, w2l, H1D, H2D);
    transpose_convert<true ><<<dim3(DLAT / 32, H2D / 32), tblk>>>(encW3, w3h, w3l, H2D, DLAT);
    transpose_convert<false><<<dim3(H2D / 32, DLAT / 32), tblk>>>(decW1, d1h, nullptr, DLAT, H2D);
    transpose_convert<false><<<dim3(H1D / 32, H2D / 32), tblk>>>(decW2, d2h, nullptr, H2D, H1D);
    transpose_convert<false><<<dim3(D_IN / 32, H1D / 32), tblk>>>(decW3, d3h, nullptr, H1D, D_IN);
    cb_prep_kernel<<<3 * KCODE / 8, blk>>>(cb0, cb1, cb2, cbh, cbn);

    // ---- encoder (fp16 split x3 ~ fp32 accuracy; feeds argmin) ----
    mma_gemm_h<3, true,  true,  false, false><<<dim3(H1D / 128, MB), blk, SMEM3>>>(x,  w1h, w1l, encb1, h1,  H1D,  D_IN, nullptr, nullptr, nullptr, nullptr, nullptr);
    mma_gemm_h<3, true,  true,  false, false><<<dim3(H2D / 128, MB), blk, SMEM3>>>(h1, w2h, w2l, encb2, h2,  H2D,  H1D,  nullptr, nullptr, nullptr, nullptr, nullptr);
    mma_gemm_h<3, false, true,  false, false><<<dim3(DLAT / 128, MB), blk, SMEM3>>>(h2, w3h, w3l, encb3, res, DLAT, H2D,  nullptr, nullptr, nullptr, nullptr, nullptr);

    ln_kernel<<<warpGrid, blk>>>(res, ln_g, ln_b);

    // ---- residual VQ: fused score+mask+blockmin GEMM, pruned exact refine ----
    for (int s = 0; s < 3; s++) {
        const float* cb = (s == 0) ? cb0 : (s == 1 ? cb1 : cb2);
        mma_gemm_h<1, false, false, false, true><<<dim3(KCODE / 128, MB), blk, SMEM1>>>(
            res, cbh + (size_t)s * KCODE * DLAT, nullptr, nullptr, nullptr, KCODE, DLAT,
            nullptr, nullptr, cbn + s * KCODE, maskp, bminp);
        vq_step<<<warpGrid, blk>>>(res, maskp, bminp, cbn + s * KCODE, cb, zq, out_loss, out_idx, s);
    }

    // ---- decoder (fp16 single-pass; L3 fuses recon-SSE partials) ----
    mma_gemm_h<1, true,  true,  false, false><<<dim3(H2D / 128, MB), blk, SMEM1>>>(zq, d1h, nullptr, decb1, h2,   H2D,  DLAT, nullptr, nullptr, nullptr, nullptr, nullptr);
    mma_gemm_h<1, true,  true,  false, false><<<dim3(H1D / 128, MB), blk, SMEM1>>>(h2, d2h, nullptr, decb2, h1,   H1D,  H2D,  nullptr, nullptr, nullptr, nullptr, nullptr);
    mma_gemm_h<1, false, true,  true,  false><<<dim3(D_IN / 128, MB), blk, SMEM1>>>(h1, d3h, nullptr, decb3, xhat, D_IN, H1D,  x, partp, nullptr, nullptr, nullptr);

    finalize2_kernel<<<warpGrid, blk>>>(partp, out_loss);
}

// round 14
// speedup vs baseline: 1.2207x; 1.0021x over previous
#include <cuda_runtime.h>
#include <cuda_fp16.h>
#include <math.h>
#include <stdint.h>

// Problem dims (fixed by the dataset)
constexpr int BATCH = 16384;
constexpr int D_IN  = 2048;
constexpr int H1D   = 1024;
constexpr int H2D   = 512;
constexpr int DLAT  = 256;
constexpr int KCODE = 1024;

// fp16 staging scales (powers of 2; exact rescale in epilogue)
constexpr float SA = 16.0f;
constexpr float SB = 32.0f;
constexpr float INVS = 1.0f / (16.0f * 32.0f);

constexpr float VQ_MARGIN = 0.05f;

constexpr int GEMM_GRID = 296;   // 2 CTAs/SM x 148 SMs

// ---------------------------------------------------------------------------
// Scratch (allocation-free contract: __device__ globals)
// ---------------------------------------------------------------------------
__device__ float g_h1[(size_t)BATCH * H1D];     // enc h1 / dec h1
__device__ float g_h2[(size_t)BATCH * H2D];     // enc h2 / dec h2
__device__ float g_res[(size_t)BATCH * DLAT];   // z after LN, then running residual
__device__ float g_zq[(size_t)BATCH * DLAT];    // z_q_total
__device__ float g_part[(size_t)BATCH * 64];    // per-row recon SSE partials
__device__ uint32_t g_mask[(size_t)BATCH * 32]; // VQ candidate bitmasks (128b x 8 blk)
__device__ float g_bmin[(size_t)BATCH * 8];     // per-row per-block score mins
__device__ float g_cbn[3 * KCODE];
__device__ uint32_t g_tile_ctr[16];             // dynamic tile counters
// pre-split fp16 weights, [N,K] row-major, scaled by SB
__device__ __half g_w1h[(size_t)H1D * D_IN], g_w1l[(size_t)H1D * D_IN];
__device__ __half g_w2h[(size_t)H2D * H1D], g_w2l[(size_t)H2D * H1D];
__device__ __half g_w3h[(size_t)DLAT * H2D], g_w3l[(size_t)DLAT * H2D];
__device__ __half g_d1h[(size_t)H2D * DLAT];
__device__ __half g_d2h[(size_t)H1D * H2D];
__device__ __half g_d3h[(size_t)D_IN * H1D];
__device__ __half g_cbh[(size_t)3 * KCODE * DLAT];   // hi-only, scaled by SB

// ---------------------------------------------------------------------------
// Helpers
// ---------------------------------------------------------------------------
__device__ __forceinline__ uint32_t smem_u32(const void* p) {
    uint32_t a;
    asm("{ .reg .u64 t; cvta.to.shared.u64 t, %1; cvt.u32.u64 %0, t; }"
        : "=r"(a) : "l"(p));
    return a;
}

__device__ __forceinline__ uint32_t pack_h2(__half a, __half b) {
    __half2 h = __halves2half2(a, b);
    return *(uint32_t*)&h;
}

// split x,y (pre-scaled) into packed fp16 hi and lo half2
__device__ __forceinline__ void split2(float x, float y,
                                       uint32_t& hi, uint32_t& lo) {
    __half hx = __float2half_rn(x), hy = __float2half_rn(y);
    __half lx = __float2half_rn(x - __half2float(hx));
    __half ly = __float2half_rn(y - __half2float(hy));
    hi = pack_h2(hx, hy);
    lo = pack_h2(lx, ly);
}

// m16n8k16 fp16 MMA (row.col), fp32 accumulate
__device__ __forceinline__ void mma16(float d[4], const uint32_t a[4],
                                      const uint32_t b[2]) {
    asm volatile(
        "mma.sync.aligned.m16n8k16.row.col.f32.f16.f16.f32 "
        "{%0,%1,%2,%3}, {%4,%5,%6,%7}, {%8,%9}, {%0,%1,%2,%3};\n"
        : "+f"(d[0]), "+f"(d[1]), "+f"(d[2]), "+f"(d[3])
        : "r"(a[0]), "r"(a[1]), "r"(a[2]), "r"(a[3]),
          "r"(b[0]), "r"(b[1]));
}

__device__ __forceinline__ void ldsm4(uint32_t& r0, uint32_t& r1,
                                      uint32_t& r2, uint32_t& r3, uint32_t addr) {
    asm volatile("ldmatrix.sync.aligned.m8n8.x4.shared.b16 {%0,%1,%2,%3}, [%4];"
                 : "=r"(r0), "=r"(r1), "=r"(r2), "=r"(r3) : "r"(addr));
}

// fp16 tile: [128 rows][16 halves] = 32B rows.
// 16B group g of row r stored at group (g ^ ((r>>2)&1)).  (R8-proven layout.)
__device__ __forceinline__ uint32_t tile_addr(uint32_t row, uint32_t g) {
    return row * 32 + ((g ^ ((row >> 2) & 1u)) << 4);
}

// identical expression used in both min-pass and flag-pass (determinism)
__device__ __forceinline__ float dd_of(float accv, float cbnv) {
    return fmaf(accv, -2.0f * INVS, cbnv);
}

// ---------------------------------------------------------------------------
// Counter reset (runs each replay; graph-capture-safe)
// ---------------------------------------------------------------------------
__global__ void reset_ctr_kernel() {
    if (threadIdx.x < 16) g_tile_ctr[threadIdx.x] = 0;
}

// ---------------------------------------------------------------------------
// fp16 mma.sync GEMM, persistent CTAs with dynamic tile scheduling.
//   C = act((A @ B^T)*INVS + bias)
//   NTERMS==3: A split (hi+lo) x B (hi+lo), products hh + hl + lh
//   NTERMS==1: single-pass (A rounded, Bhi)
//   PARTIAL: also emit per-row partial SSE of (C - X)
//   SCOREMIN: VQ mode — no C write; candidate bitmask + block-min value
// Tile 128x128, BK=16, 256 threads, 8 warps (2m x 4n).  (R8-proven core.)
// Grid = GEMM_GRID CTAs; tiles claimed via g_tile_ctr[cid].
// SMEM: [0..1024) tile broadcast + epilogue scratch base; stages at +1024.
// ---------------------------------------------------------------------------
template <int NTERMS, bool RELU, bool HASBIAS, bool PARTIAL, bool SCOREMIN>
__global__ __launch_bounds__(256, 2)
void mma_gemm_h(const float* __restrict__ A, const __half* __restrict__ Bhi,
                const __half* __restrict__ Blo, const float* __restrict__ bias,
                float* __restrict__ C, int N, int Kd,
                int nbx, int ntiles, int cid,
                const float* __restrict__ X, float* __restrict__ part,
                const float* __restrict__ cbnb, uint32_t* __restrict__ gmask,
                float* __restrict__ gbmin)
{
    extern __shared__ char smem[];
    char* sb = smem + 1024;                       // stage base
    const uint32_t smb = smem_u32(smem) + 1024;
    volatile uint32_t* s_tile = (volatile uint32_t*)smem;
    constexpr int TILEB = 4096;
    constexpr int STAGE = (NTERMS == 3) ? 16384 : 8192;

    const int tid  = threadIdx.x;
    const int wid  = tid >> 5;
    const int lane = tid & 31;
    const int wm   = wid & 1;       // 0..1 -> 64 rows
    const int wn   = wid >> 1;      // 0..3 -> 32 cols

    const int nk = Kd >> 4;         // BK=16 chunks

    // staging role: thread -> (row r, 8-element group hf of the 16-wide chunk)
    const int r  = tid >> 1;
    const int hf = tid & 1;
    const uint32_t soff = tile_addr((uint32_t)r, (uint32_t)hf);

    // ldmatrix per-lane address components
    const uint32_t amat   = (uint32_t)lane >> 3;
    const uint32_t arow_l = (uint32_t)(lane & 7) + ((amat & 1u) << 3);
    const uint32_t ag     = amat >> 1;
    const uint32_t bmat   = (uint32_t)lane >> 3;
    const uint32_t brow_l = (uint32_t)(lane & 7) + ((bmat >> 1) << 3);
    const uint32_t bg     = bmat & 1u;

    for (;;) {
        __syncthreads();
        if (tid == 0) *s_tile = atomicAdd(&g_tile_ctr[cid], 1u);
        __syncthreads();
        const uint32_t t = *s_tile;
        if (t >= (uint32_t)ntiles) break;
        const int bx = (int)(t % (uint32_t)nbx);
        const int by = (int)(t / (uint32_t)nbx);

        const float* Ag  = A   + (size_t)(by * 128) * Kd;
        const __half* Bh = Bhi + (size_t)(bx * 128) * Kd;
        const __half* Bl = (NTERMS == 3) ? Blo + (size_t)(bx * 128) * Kd : nullptr;

        float acc[4][4][4];
#pragma unroll
        for (int i = 0; i < 4; i++)
#pragma unroll
            for (int j = 0; j < 4; j++)
#pragma unroll
                for (int q = 0; q < 4; q++) acc[i][j][q] = 0.0f;

        float4 va[2];
        uint4 vbh, vbl;

        auto ldg = [&](int k0) {
            const float4* pa = (const float4*)(Ag + (size_t)r * Kd + k0 * 16 + hf * 8);
            va[0] = pa[0]; va[1] = pa[1];
            vbh = *(const uint4*)(Bh + (size_t)r * Kd + k0 * 16 + hf * 8);
            if (NTERMS == 3)
                vbl = *(const uint4*)(Bl + (size_t)r * Kd + k0 * 16 + hf * 8);
        };

        auto stage_store = [&](int s) {
            char* st = sb + s * STAGE;
            uint4 ha;
            if (NTERMS == 3) {
                uint4 la;
                split2(SA * va[0].x, SA * va[0].y, ha.x, la.x);
                split2(SA * va[0].z, SA * va[0].w, ha.y, la.y);
                split2(SA * va[1].x, SA * va[1].y, ha.z, la.z);
                split2(SA * va[1].z, SA * va[1].w, ha.w, la.w);
                *(uint4*)(st + soff)             = ha;
                *(uint4*)(st + TILEB + soff)     = vbh;
                *(uint4*)(st + 2 * TILEB + soff) = la;
                *(uint4*)(st + 3 * TILEB + soff) = vbl;
            } else {
                ha.x = pack_h2(__float2half_rn(SA * va[0].x), __float2half_rn(SA * va[0].y));
                ha.y = pack_h2(__float2half_rn(SA * va[0].z), __float2half_rn(SA * va[0].w));
                ha.z = pack_h2(__float2half_rn(SA * va[1].x), __float2half_rn(SA * va[1].y));
                ha.w = pack_h2(__float2half_rn(SA * va[1].z), __float2half_rn(SA * va[1].w));
                *(uint4*)(st + soff)         = ha;
                *(uint4*)(st + TILEB + soff) = vbh;
            }
        };

        ldg(0);
        stage_store(0);
        __syncthreads();

        for (int k0 = 0; k0 < nk; k0++) {
            if (k0 + 1 < nk) ldg(k0 + 1);

            const uint32_t stb = smb + (uint32_t)((k0 & 1) * STAGE);

            uint32_t bhf[4][2], blf[4][2];
#pragma unroll
            for (int p = 0; p < 2; p++) {
                uint32_t nrow = (uint32_t)(wn * 32 + p * 16) + brow_l;
                uint32_t ba = stb + TILEB + tile_addr(nrow, bg);
                ldsm4(bhf[p * 2][0], bhf[p * 2][1], bhf[p * 2 + 1][0], bhf[p * 2 + 1][1], ba);
                if (NTERMS == 3)
                    ldsm4(blf[p * 2][0], blf[p * 2][1], blf[p * 2 + 1][0], blf[p * 2 + 1][1],
                          ba + 2 * TILEB);
            }
#pragma unroll
            for (int mt = 0; mt < 4; mt++) {
                uint32_t arow = (uint32_t)(wm * 64 + mt * 16) + arow_l;
                uint32_t aa = stb + tile_addr(arow, ag);
                uint32_t ah[4], al[4];
                ldsm4(ah[0], ah[1], ah[2], ah[3], aa);
                if (NTERMS == 3)
                    ldsm4(al[0], al[1], al[2], al[3], aa + 2 * TILEB);
                // per-accumulator order hh, hl, lh (bit-identical numerics)
#pragma unroll
                for (int nt = 0; nt < 4; nt++) {
                    mma16(acc[mt][nt], ah, bhf[nt]);
                    if (NTERMS == 3) {
                        mma16(acc[mt][nt], ah, blf[nt]);
                        mma16(acc[mt][nt], al, bhf[nt]);
                    }
                }
            }

            if (k0 + 1 < nk) stage_store((k0 + 1) & 1);
            __syncthreads();
        }

        if (SCOREMIN) {
            // ---- VQ scoring epilogue: block-row min + candidate bitmask ----
            float* wmin = (float*)sb;                   // [128][4]
            float* bmin = (float*)(sb + 2048);          // [128]
            uint32_t* msk = (uint32_t*)(sb + 2560);     // [128][4]
            msk[tid] = 0; msk[tid + 256] = 0;

            const int codec0 = bx * 128 + wn * 32 + (lane & 3) * 2;
            float cbnv[4][2];
#pragma unroll
            for (int nt = 0; nt < 4; nt++) {
                cbnv[nt][0] = __ldg(cbnb + codec0 + nt * 8);
                cbnv[nt][1] = __ldg(cbnb + codec0 + nt * 8 + 1);
            }

#pragma unroll
            for (int mt = 0; mt < 4; mt++) {
#pragma unroll
                for (int h = 0; h < 2; h++) {
                    float lm = INFINITY;
#pragma unroll
                    for (int nt = 0; nt < 4; nt++) {
                        lm = fminf(lm, dd_of(acc[mt][nt][h * 2 + 0], cbnv[nt][0]));
                        lm = fminf(lm, dd_of(acc[mt][nt][h * 2 + 1], cbnv[nt][1]));
                    }
                    lm = fminf(lm, __shfl_xor_sync(0xffffffffu, lm, 1));
                    lm = fminf(lm, __shfl_xor_sync(0xffffffffu, lm, 2));
                    if ((lane & 3) == 0) {
                        int rl = wm * 64 + mt * 16 + h * 8 + (lane >> 2);
                        wmin[rl * 4 + wn] = lm;
                    }
                }
            }
            __syncthreads();
            if (tid < 128) {
                float v = fminf(fminf(wmin[tid * 4], wmin[tid * 4 + 1]),
                                fminf(wmin[tid * 4 + 2], wmin[tid * 4 + 3]));
                gbmin[(size_t)(by * 128 + tid) * 8 + bx] = v;
                bmin[tid] = v + VQ_MARGIN;
            }
            __syncthreads();
#pragma unroll
            for (int mt = 0; mt < 4; mt++) {
#pragma unroll
                for (int h = 0; h < 2; h++) {
                    int rl = wm * 64 + mt * 16 + h * 8 + (lane >> 2);
                    float th = bmin[rl];
#pragma unroll
                    for (int nt = 0; nt < 4; nt++) {
#pragma unroll
                        for (int q = 0; q < 2; q++) {
                            float d = dd_of(acc[mt][nt][h * 2 + q], cbnv[nt][q]);
                            if (d <= th) {
                                int bit = nt * 8 + (lane & 3) * 2 + q;
                                atomicOr(&msk[rl * 4 + wn], 1u << bit);
                            }
                        }
                    }
                }
            }
            __syncthreads();
            {
                int w0 = tid;
                gmask[(size_t)(by * 128 + (w0 >> 2)) * 32 + bx * 4 + (w0 & 3)] = msk[w0];
                int w1 = tid + 256;
                gmask[(size_t)(by * 128 + (w1 >> 2)) * 32 + bx * 4 + (w1 & 3)] = msk[w1];
            }
            continue;   // next tile
        }

        // ---- standard epilogue ----
        const int row0 = by * 128 + wm * 64 + (lane >> 2);
        const int col0 = bx * 128 + wn * 32 + (lane & 3) * 2;
        float psum[4][2];
        if (PARTIAL) {
#pragma unroll
            for (int mt = 0; mt < 4; mt++) { psum[mt][0] = 0.f; psum[mt][1] = 0.f; }
        }
#pragma unroll
        for (int mt = 0; mt < 4; mt++) {
#pragma unroll
            for (int nt = 0; nt < 4; nt++) {
                int rr = row0 + mt * 16;
                int cc = col0 + nt * 8;
                float b0 = 0.f, b1 = 0.f;
                if (HASBIAS) { b0 = __ldg(bias + cc); b1 = __ldg(bias + cc + 1); }
                float2 v0, v1;
                v0.x = acc[mt][nt][0] * INVS + b0; v0.y = acc[mt][nt][1] * INVS + b1;
                v1.x = acc[mt][nt][2] * INVS + b0; v1.y = acc[mt][nt][3] * INVS + b1;
                if (RELU) {
                    v0.x = fmaxf(v0.x, 0.f); v0.y = fmaxf(v0.y, 0.f);
                    v1.x = fmaxf(v1.x, 0.f); v1.y = fmaxf(v1.y, 0.f);
                }
                *(float2*)(C + (size_t)rr * N + cc)       = v0;
                *(float2*)(C + (size_t)(rr + 8) * N + cc) = v1;
                if (PARTIAL) {
                    float2 x0 = *(const float2*)(X + (size_t)rr * N + cc);
                    float2 x1 = *(const float2*)(X + (size_t)(rr + 8) * N + cc);
                    float d0 = v0.x - x0.x, d1 = v0.y - x0.y;
                    float d2 = v1.x - x1.x, d3 = v1.y - x1.y;
                    psum[mt][0] += d0 * d0 + d1 * d1;
                    psum[mt][1] += d2 * d2 + d3 * d3;
                }
            }
        }
        if (PARTIAL) {
#pragma unroll
            for (int mt = 0; mt < 4; mt++) {
#pragma unroll
                for (int h = 0; h < 2; h++) {
                    float v = psum[mt][h];
                    v += __shfl_xor_sync(0xffffffffu, v, 1);
                    v += __shfl_xor_sync(0xffffffffu, v, 2);
                    if ((lane & 3) == 0) {
                        int rr = row0 + mt * 16 + h * 8;
                        part[(size_t)rr * 64 + bx * 4 + wn] = v;
                    }
                }
            }
        }
    }
}

// ---------------------------------------------------------------------------
// Prep: transpose + scale + split  W[K,N] f32 -> Thi[/Tlo][N,K] half (x SB)
// ---------------------------------------------------------------------------
template <bool WLO>
__global__ __launch_bounds__(256)
void transpose_convert(const float* __restrict__ W, __half* __restrict__ Thi,
                       __half* __restrict__ Tlo, int K, int N)
{
    __shared__ float tile[32][33];
    int n0 = blockIdx.x * 32;
    int k0 = blockIdx.y * 32;
#pragma unroll
    for (int i = 0; i < 32; i += 8)
        tile[threadIdx.y + i][threadIdx.x] =
            W[(size_t)(k0 + threadIdx.y + i) * N + n0 + threadIdx.x];
    __syncthreads();
#pragma unroll
    for (int i = 0; i < 32; i += 8) {
        float v = SB * tile[threadIdx.x][threadIdx.y + i];
        __half h = __float2half_rn(v);
        size_t o = (size_t)(n0 + threadIdx.y + i) * K + k0 + threadIdx.x;
        Thi[o] = h;
        if (WLO) Tlo[o] = __float2half_rn(v - __half2float(h));
    }
}

// Codebooks: warp per code — fp32 row norm + scaled fp16 hi conversion.
__global__ __launch_bounds__(256)
void cb_prep_kernel(const float* __restrict__ cb0, const float* __restrict__ cb1,
                    const float* __restrict__ cb2, __half* __restrict__ outh,
                    float* __restrict__ cbn)
{
    int code = blockIdx.x * 8 + (threadIdx.x >> 5);   // 0..3071
    int lane = threadIdx.x & 31;
    const float* cb = (code < KCODE) ? cb0 : (code < 2 * KCODE ? cb1 : cb2);
    const float* c  = cb + (size_t)(code & (KCODE - 1)) * DLAT;
    __half* oh = outh + (size_t)code * DLAT;
    float s = 0.f;
#pragma unroll
    for (int i = 0; i < 8; i++) {
        float v = c[lane + 32 * i];
        s += v * v;
        oh[lane + 32 * i] = __float2half_rn(SB * v);
    }
#pragma unroll
    for (int o = 16; o; o >>= 1) s += __shfl_xor_sync(0xffffffffu, s, o);
    if (lane == 0) cbn[code] = s;
}

// ---------------------------------------------------------------------------
// LayerNorm over DLAT=256, warp per row
// ---------------------------------------------------------------------------
__global__ __launch_bounds__(256)
void ln_kernel(float* __restrict__ z, const float* __restrict__ g,
               const float* __restrict__ b)
{
    int row  = blockIdx.x * 8 + (threadIdx.x >> 5);
    int lane = threadIdx.x & 31;
    float* zr = z + (size_t)row * DLAT;

    float v[8];
    float s = 0.f;
#pragma unroll
    for (int i = 0; i < 8; i++) { v[i] = zr[lane + 32 * i]; s += v[i]; }
#pragma unroll
    for (int o = 16; o; o >>= 1) s += __shfl_xor_sync(0xffffffffu, s, o);
    float mu = s * (1.0f / 256.0f);

    float s2 = 0.f;
#pragma unroll
    for (int i = 0; i < 8; i++) { float d = v[i] - mu; s2 += d * d; }
#pragma unroll
    for (int o = 16; o; o >>= 1) s2 += __shfl_xor_sync(0xffffffffu, s2, o);
    float var = s2 * (1.0f / 256.0f);
    float rs  = 1.0f / sqrtf(var + 1e-5f);

#pragma unroll
    for (int i = 0; i < 8; i++) {
        int col = lane + 32 * i;
        zr[col] = (v[i] - mu) * rs * g[col] + b[col];
    }
}

// ---------------------------------------------------------------------------
// VQ step from candidate bitmasks + block mins (R13-proven).
// ---------------------------------------------------------------------------
__global__ __launch_bounds__(256)
void vq_step(float* __restrict__ res, const uint32_t* __restrict__ gmask,
             const float* __restrict__ gbmin,
             const float* __restrict__ cbn, const float* __restrict__ cb,
             float* __restrict__ zq, float* __restrict__ out_loss,
             float* __restrict__ out_idx, int stage)
{
    int row  = blockIdx.x * 8 + (threadIdx.x >> 5);
    int lane = threadIdx.x & 31;

    float* r = res + (size_t)row * DLAT;
    float rv[8];
    float s = 0.f;
#pragma unroll
    for (int i = 0; i < 8; i++) { rv[i] = r[lane + 32 * i]; s += rv[i] * rv[i]; }
#pragma unroll
    for (int o = 16; o; o >>= 1) s += __shfl_xor_sync(0xffffffffu, s, o);
    const float rnorm = s;

    float bm = (lane < 8) ? __ldg(gbmin + (size_t)row * 8 + lane) : INFINITY;
    float gmin = bm;
#pragma unroll
    for (int o = 16; o; o >>= 1) gmin = fminf(gmin, __shfl_xor_sync(0xffffffffu, gmin, o));
    const float th = gmin + VQ_MARGIN;
    float myblk = __shfl_sync(0xffffffffu, bm, lane >> 2);

    uint32_t cmask = __ldg(gmask + (size_t)row * 32 + lane);
    if (myblk > th) cmask = 0;

    float bestv = INFINITY;
    int   bestn = KCODE;
    for (;;) {
        uint32_t ball = __ballot_sync(0xffffffffu, cmask != 0);
        if (!ball) break;
        int src = __ffs(ball) - 1;
        uint32_t m = __shfl_sync(0xffffffffu, cmask, src);
        int j = __ffs(m) - 1;
        if (lane == src) cmask &= cmask - 1;
        int n = (src >> 2) * 128 + (src & 3) * 32 + j;

        const float* c = cb + (size_t)n * DLAT;
        float dot = 0.f;
#pragma unroll
        for (int i = 0; i < 8; i++) dot += rv[i] * c[lane + 32 * i];
#pragma unroll
        for (int o = 16; o; o >>= 1) dot += __shfl_xor_sync(0xffffffffu, dot, o);

        float d = (rnorm - 2.0f * dot) + cbn[n];
        if (d < bestv || (d == bestv && n < bestn)) { bestv = d; bestn = n; }
    }
    const int bi = bestn;
    if (lane == 0) out_idx[row * 3 + stage] = (float)bi;

    const float* c = cb + (size_t)bi * DLAT;
    float* q = zq + (size_t)row * DLAT;
    float se = 0.f;
#pragma unroll
    for (int i = 0; i < 8; i++) {
        int col = lane + 32 * i;
        float ev = c[col];
        float diff = rv[i] - ev;
        se += diff * diff;
        float t   = ev - rv[i];
        float zqe = rv[i] + t;
        if (stage < 2) r[col] = rv[i] - zqe;
        q[col] = (stage == 0) ? zqe : (q[col] + zqe);
    }
#pragma unroll
    for (int o = 16; o; o >>= 1) se += __shfl_xor_sync(0xffffffffu, se, o);
    if (lane == 0) {
        float m = se * (1.0f / 256.0f);
        float l = m + 0.25f * m;
        out_loss[row] = (stage == 0) ? l : (out_loss[row] + l);
    }
}

// ---------------------------------------------------------------------------
// Finalize2: out_loss[row] += sum(part[row][0..63]) / 2048. Warp per row.
// ---------------------------------------------------------------------------
__global__ __launch_bounds__(256)
void finalize2_kernel(const float* __restrict__ part, float* __restrict__ out_loss)
{
    int row  = blockIdx.x * 8 + (threadIdx.x >> 5);
    int lane = threadIdx.x & 31;
    const float* p = part + (size_t)row * 64;
    float s = p[lane] + p[lane + 32];
#pragma unroll
    for (int o = 16; o; o >>= 1) s += __shfl_xor_sync(0xffffffffu, s, o);
    if (lane == 0) out_loss[row] += s * (1.0f / 2048.0f);
}

// ---------------------------------------------------------------------------
// Launch
// ---------------------------------------------------------------------------
extern "C" void kernel_launch(void* const* d_in, const int* in_sizes, int n_in,
                              void* d_out, int out_size)
{
    const float* x      = (const float*)d_in[0];
    const float* encW1  = (const float*)d_in[1];
    const float* encb1  = (const float*)d_in[2];
    const float* encW2  = (const float*)d_in[3];
    const float* encb2  = (const float*)d_in[4];
    const float* encW3  = (const float*)d_in[5];
    const float* encb3  = (const float*)d_in[6];
    const float* ln_g   = (const float*)d_in[7];
    const float* ln_b   = (const float*)d_in[8];
    const float* cb0    = (const float*)d_in[9];
    const float* cb1    = (const float*)d_in[10];
    const float* cb2    = (const float*)d_in[11];
    const float* decW1  = (const float*)d_in[12];
    const float* decb1  = (const float*)d_in[13];
    const float* decW2  = (const float*)d_in[14];
    const float* decb2  = (const float*)d_in[15];
    const float* decW3  = (const float*)d_in[16];
    const float* decb3  = (const float*)d_in[17];

    float *h1, *h2, *res, *zq, *cbn, *partp, *bminp;
    uint32_t* maskp;
    __half *w1h, *w1l, *w2h, *w2l, *w3h, *w3l;
    __half *d1h, *d2h, *d3h, *cbh;
    cudaGetSymbolAddress((void**)&h1, g_h1);
    cudaGetSymbolAddress((void**)&h2, g_h2);
    cudaGetSymbolAddress((void**)&res, g_res);
    cudaGetSymbolAddress((void**)&zq, g_zq);
    cudaGetSymbolAddress((void**)&cbn, g_cbn);
    cudaGetSymbolAddress((void**)&partp, g_part);
    cudaGetSymbolAddress((void**)&maskp, g_mask);
    cudaGetSymbolAddress((void**)&bminp, g_bmin);
    cudaGetSymbolAddress((void**)&w1h, g_w1h); cudaGetSymbolAddress((void**)&w1l, g_w1l);
    cudaGetSymbolAddress((void**)&w2h, g_w2h); cudaGetSymbolAddress((void**)&w2l, g_w2l);
    cudaGetSymbolAddress((void**)&w3h, g_w3h); cudaGetSymbolAddress((void**)&w3l, g_w3l);
    cudaGetSymbolAddress((void**)&d1h, g_d1h);
    cudaGetSymbolAddress((void**)&d2h, g_d2h);
    cudaGetSymbolAddress((void**)&d3h, g_d3h);
    cudaGetSymbolAddress((void**)&cbh, g_cbh);

    float* xhat     = (float*)d_out;
    float* out_loss = xhat + (size_t)BATCH * D_IN;
    float* out_idx  = out_loss + BATCH;

    const int SMEM3 = 1024 + 2 * 16384;  // 33792
    const int SMEM1 = 1024 + 2 * 8192;   // 17408
    cudaFuncSetAttribute((const void*)mma_gemm_h<3, true,  true,  false, false>, cudaFuncAttributeMaxDynamicSharedMemorySize, SMEM3);
    cudaFuncSetAttribute((const void*)mma_gemm_h<3, false, true,  false, false>, cudaFuncAttributeMaxDynamicSharedMemorySize, SMEM3);
    cudaFuncSetAttribute((const void*)mma_gemm_h<1, false, false, false, true >, cudaFuncAttributeMaxDynamicSharedMemorySize, SMEM1);
    cudaFuncSetAttribute((const void*)mma_gemm_h<1, true,  true,  false, false>, cudaFuncAttributeMaxDynamicSharedMemorySize, SMEM1);
    cudaFuncSetAttribute((const void*)mma_gemm_h<1, false, true,  true,  false>, cudaFuncAttributeMaxDynamicSharedMemorySize, SMEM1);

    const dim3 blk(256);
    const dim3 tblk(32, 8);
    const dim3 ggrid(GEMM_GRID);
    const int MB = BATCH / 128;          // 128
    const int warpGrid = BATCH / 8;      // 2048

    // ---- counters + prep ----
    reset_ctr_kernel<<<1, 32>>>();
    transpose_convert<true ><<<dim3(H1D / 32, D_IN / 32), tblk>>>(encW1, w1h, w1l, D_IN, H1D);
    transpose_convert<true ><<<dim3(H2D / 32, H1D / 32), tblk>>>(encW2, w2h, w2l, H1D, H2D);
    transpose_convert<true ><<<dim3(DLAT / 32, H2D / 32), tblk>>>(encW3, w3h, w3l, H2D, DLAT);
    transpose_convert<false><<<dim3(H2D / 32, DLAT / 32), tblk>>>(decW1, d1h, nullptr, DLAT, H2D);
    transpose_convert<false><<<dim3(H1D / 32, H2D / 32), tblk>>>(decW2, d2h, nullptr, H2D, H1D);
    transpose_convert<false><<<dim3(D_IN / 32, H1D / 32), tblk>>>(decW3, d3h, nullptr, H1D, D_IN);
    cb_prep_kernel<<<3 * KCODE / 8, blk>>>(cb0, cb1, cb2, cbh, cbn);

    // ---- encoder (fp16 split x3 ~ fp32 accuracy; feeds argmin) ----
    mma_gemm_h<3, true,  true,  false, false><<<ggrid, blk, SMEM3>>>(x,  w1h, w1l, encb1, h1,  H1D,  D_IN, H1D / 128, (H1D / 128) * MB, 0, nullptr, nullptr, nullptr, nullptr, nullptr);
    mma_gemm_h<3, true,  true,  false, false><<<ggrid, blk, SMEM3>>>(h1, w2h, w2l, encb2, h2,  H2D,  H1D,  H2D / 128, (H2D / 128) * MB, 1, nullptr, nullptr, nullptr, nullptr, nullptr);
    mma_gemm_h<3, false, true,  false, false><<<ggrid, blk, SMEM3>>>(h2, w3h, w3l, encb3, res, DLAT, H2D,  DLAT / 128, (DLAT / 128) * MB, 2, nullptr, nullptr, nullptr, nullptr, nullptr);

    ln_kernel<<<warpGrid, blk>>>(res, ln_g, ln_b);

    // ---- residual VQ: fused score+mask+blockmin GEMM, pruned exact refine ----
    for (int s = 0; s < 3; s++) {
        const float* cb = (s == 0) ? cb0 : (s == 1 ? cb1 : cb2);
        mma_gemm_h<1, false, false, false, true><<<ggrid, blk, SMEM1>>>(
            res, cbh + (size_t)s * KCODE * DLAT, nullptr, nullptr, nullptr, KCODE, DLAT,
            KCODE / 128, (KCODE / 128) * MB, 3 + s,
            nullptr, nullptr, cbn + s * KCODE, maskp, bminp);
        vq_step<<<warpGrid, blk>>>(res, maskp, bminp, cbn + s * KCODE, cb, zq, out_loss, out_idx, s);
    }

    // ---- decoder (fp16 single-pass; L3 fuses recon-SSE partials) ----
    mma_gemm_h<1, true,  true,  false, false><<<ggrid, blk, SMEM1>>>(zq, d1h, nullptr, decb1, h2,   H2D,  DLAT, H2D / 128, (H2D / 128) * MB, 6, nullptr, nullptr, nullptr, nullptr, nullptr);
    mma_gemm_h<1, true,  true,  false, false><<<ggrid, blk, SMEM1>>>(h2, d2h, nullptr, decb2, h1,   H1D,  H2D,  H1D / 128, (H1D / 128) * MB, 7, nullptr, nullptr, nullptr, nullptr, nullptr);
    mma_gemm_h<1, false, true,  true,  false><<<ggrid, blk, SMEM1>>>(h1, d3h, nullptr, decb3, xhat, D_IN, H1D,  D_IN / 128, (D_IN / 128) * MB, 8, x, partp, nullptr, nullptr, nullptr);

    finalize2_kernel<<<warpGrid, blk>>>(partp, out_loss);
}

// round 15
// speedup vs baseline: 1.2245x; 1.0031x over previous
#include <cuda_runtime.h>
#include <cuda_fp16.h>
#include <math.h>
#include <stdint.h>

// Problem dims (fixed by the dataset)
constexpr int BATCH = 16384;
constexpr int D_IN  = 2048;
constexpr int H1D   = 1024;
constexpr int H2D   = 512;
constexpr int DLAT  = 256;
constexpr int KCODE = 1024;

// fp16 staging scales (powers of 2; exact rescale in epilogue)
constexpr float SA = 16.0f;
constexpr float SB = 32.0f;
constexpr float INVS = 1.0f / (16.0f * 32.0f);

constexpr float VQ_MARGIN = 0.05f;

constexpr int GEMM_GRID = 296;   // 2 CTAs/SM x 148 SMs

// ---------------------------------------------------------------------------
// Scratch (allocation-free contract: __device__ globals)
// ---------------------------------------------------------------------------
__device__ float g_h1[(size_t)BATCH * H1D];     // enc h1 / dec h1
__device__ float g_h2[(size_t)BATCH * H2D];     // enc h2 / dec h2
__device__ float g_res[(size_t)BATCH * DLAT];   // z after LN, then running residual
__device__ float g_zq[(size_t)BATCH * DLAT];    // z_q_total
__device__ float g_part[(size_t)BATCH * 64];    // per-row recon SSE partials
__device__ uint32_t g_mask[(size_t)BATCH * 32]; // VQ candidate bitmasks (128b x 8 blk)
__device__ float g_bmin[(size_t)BATCH * 8];     // per-row per-block score mins
__device__ float g_cbn[3 * KCODE];
__device__ uint32_t g_tile_ctr[16];             // dynamic tile counters
// pre-split fp16 weights, [N,K] row-major, scaled by SB
__device__ __half g_w1h[(size_t)H1D * D_IN], g_w1l[(size_t)H1D * D_IN];
__device__ __half g_w2h[(size_t)H2D * H1D], g_w2l[(size_t)H2D * H1D];
__device__ __half g_w3h[(size_t)DLAT * H2D], g_w3l[(size_t)DLAT * H2D];
__device__ __half g_d1h[(size_t)H2D * DLAT];
__device__ __half g_d2h[(size_t)H1D * H2D];
__device__ __half g_d3h[(size_t)D_IN * H1D];
__device__ __half g_cbh[(size_t)3 * KCODE * DLAT];   // hi-only, scaled by SB

// ---------------------------------------------------------------------------
// Helpers
// ---------------------------------------------------------------------------
__device__ __forceinline__ uint32_t smem_u32(const void* p) {
    uint32_t a;
    asm("{ .reg .u64 t; cvta.to.shared.u64 t, %1; cvt.u32.u64 %0, t; }"
        : "=r"(a) : "l"(p));
    return a;
}

__device__ __forceinline__ uint32_t pack_h2(__half a, __half b) {
    __half2 h = __halves2half2(a, b);
    return *(uint32_t*)&h;
}

// split x,y (pre-scaled) into packed fp16 hi and lo half2
__device__ __forceinline__ void split2(float x, float y,
                                       uint32_t& hi, uint32_t& lo) {
    __half hx = __float2half_rn(x), hy = __float2half_rn(y);
    __half lx = __float2half_rn(x - __half2float(hx));
    __half ly = __float2half_rn(y - __half2float(hy));
    hi = pack_h2(hx, hy);
    lo = pack_h2(lx, ly);
}

// m16n8k16 fp16 MMA (row.col), fp32 accumulate
__device__ __forceinline__ void mma16(float d[4], const uint32_t a[4],
                                      const uint32_t b[2]) {
    asm volatile(
        "mma.sync.aligned.m16n8k16.row.col.f32.f16.f16.f32 "
        "{%0,%1,%2,%3}, {%4,%5,%6,%7}, {%8,%9}, {%0,%1,%2,%3};\n"
        : "+f"(d[0]), "+f"(d[1]), "+f"(d[2]), "+f"(d[3])
        : "r"(a[0]), "r"(a[1]), "r"(a[2]), "r"(a[3]),
          "r"(b[0]), "r"(b[1]));
}

__device__ __forceinline__ void ldsm4(uint32_t& r0, uint32_t& r1,
                                      uint32_t& r2, uint32_t& r3, uint32_t addr) {
    asm volatile("ldmatrix.sync.aligned.m8n8.x4.shared.b16 {%0,%1,%2,%3}, [%4];"
                 : "=r"(r0), "=r"(r1), "=r"(r2), "=r"(r3) : "r"(addr));
}

// fp16 tile: [128 rows][16 halves] = 32B rows.
// 16B group g of row r stored at group (g ^ ((r>>2)&1)).  (R8-proven layout.)
__device__ __forceinline__ uint32_t tile_addr(uint32_t row, uint32_t g) {
    return row * 32 + ((g ^ ((row >> 2) & 1u)) << 4);
}

// identical expression used in both min-pass and flag-pass (determinism)
__device__ __forceinline__ float dd_of(float accv, float cbnv) {
    return fmaf(accv, -2.0f * INVS, cbnv);
}

// ---------------------------------------------------------------------------
// fp16 mma.sync GEMM, persistent CTAs with dynamic tile scheduling.
//   C = act((A @ B^T)*INVS + bias)
//   NTERMS==3: A split (hi+lo) x B (hi+lo), products hh + hl + lh
//   NTERMS==1: single-pass (A rounded, Bhi)
//   PARTIAL: also emit per-row partial SSE of (C - X)
//   SCOREMIN: VQ mode — no C write; candidate bitmask + block-min value
// Tile 128x128, BK=16, 256 threads, 8 warps (2m x 4n).  (R8-proven core.)
// Grid = GEMM_GRID CTAs; tiles claimed via g_tile_ctr[cid].
// SMEM: [0..1024) tile broadcast; stages at +1024.
// ---------------------------------------------------------------------------
template <int NTERMS, bool RELU, bool HASBIAS, bool PARTIAL, bool SCOREMIN>
__global__ __launch_bounds__(256, 2)
void mma_gemm_h(const float* __restrict__ A, const __half* __restrict__ Bhi,
                const __half* __restrict__ Blo, const float* __restrict__ bias,
                float* __restrict__ C, int N, int Kd,
                int nbx, int ntiles, int cid,
                const float* __restrict__ X, float* __restrict__ part,
                const float* __restrict__ cbnb, uint32_t* __restrict__ gmask,
                float* __restrict__ gbmin)
{
    extern __shared__ char smem[];
    char* sb = smem + 1024;                       // stage base
    const uint32_t smb = smem_u32(smem) + 1024;
    volatile uint32_t* s_tile = (volatile uint32_t*)smem;
    constexpr int TILEB = 4096;
    constexpr int STAGE = (NTERMS == 3) ? 16384 : 8192;

    const int tid  = threadIdx.x;
    const int wid  = tid >> 5;
    const int lane = tid & 31;
    const int wm   = wid & 1;       // 0..1 -> 64 rows
    const int wn   = wid >> 1;      // 0..3 -> 32 cols

    const int nk = Kd >> 4;         // BK=16 chunks

    // staging role: thread -> (row r, 8-element group hf of the 16-wide chunk)
    const int r  = tid >> 1;
    const int hf = tid & 1;
    const uint32_t soff = tile_addr((uint32_t)r, (uint32_t)hf);

    // ldmatrix per-lane address components
    const uint32_t amat   = (uint32_t)lane >> 3;
    const uint32_t arow_l = (uint32_t)(lane & 7) + ((amat & 1u) << 3);
    const uint32_t ag     = amat >> 1;
    const uint32_t bmat   = (uint32_t)lane >> 3;
    const uint32_t brow_l = (uint32_t)(lane & 7) + ((bmat >> 1) << 3);
    const uint32_t bg     = bmat & 1u;

    for (;;) {
        __syncthreads();
        if (tid == 0) *s_tile = atomicAdd(&g_tile_ctr[cid], 1u);
        __syncthreads();
        const uint32_t t = *s_tile;
        if (t >= (uint32_t)ntiles) break;
        const int bx = (int)(t % (uint32_t)nbx);
        const int by = (int)(t / (uint32_t)nbx);

        const float* Ag  = A   + (size_t)(by * 128) * Kd;
        const __half* Bh = Bhi + (size_t)(bx * 128) * Kd;
        const __half* Bl = (NTERMS == 3) ? Blo + (size_t)(bx * 128) * Kd : nullptr;

        float acc[4][4][4];
#pragma unroll
        for (int i = 0; i < 4; i++)
#pragma unroll
            for (int j = 0; j < 4; j++)
#pragma unroll
                for (int q = 0; q < 4; q++) acc[i][j][q] = 0.0f;

        float4 va[2];
        uint4 vbh, vbl;

        auto ldg = [&](int k0) {
            const float4* pa = (const float4*)(Ag + (size_t)r * Kd + k0 * 16 + hf * 8);
            va[0] = pa[0]; va[1] = pa[1];
            vbh = *(const uint4*)(Bh + (size_t)r * Kd + k0 * 16 + hf * 8);
            if (NTERMS == 3)
                vbl = *(const uint4*)(Bl + (size_t)r * Kd + k0 * 16 + hf * 8);
        };

        auto stage_store = [&](int s) {
            char* st = sb + s * STAGE;
            uint4 ha;
            if (NTERMS == 3) {
                uint4 la;
                split2(SA * va[0].x, SA * va[0].y, ha.x, la.x);
                split2(SA * va[0].z, SA * va[0].w, ha.y, la.y);
                split2(SA * va[1].x, SA * va[1].y, ha.z, la.z);
                split2(SA * va[1].z, SA * va[1].w, ha.w, la.w);
                *(uint4*)(st + soff)             = ha;
                *(uint4*)(st + TILEB + soff)     = vbh;
                *(uint4*)(st + 2 * TILEB + soff) = la;
                *(uint4*)(st + 3 * TILEB + soff) = vbl;
            } else {
                ha.x = pack_h2(__float2half_rn(SA * va[0].x), __float2half_rn(SA * va[0].y));
                ha.y = pack_h2(__float2half_rn(SA * va[0].z), __float2half_rn(SA * va[0].w));
                ha.z = pack_h2(__float2half_rn(SA * va[1].x), __float2half_rn(SA * va[1].y));
                ha.w = pack_h2(__float2half_rn(SA * va[1].z), __float2half_rn(SA * va[1].w));
                *(uint4*)(st + soff)         = ha;
                *(uint4*)(st + TILEB + soff) = vbh;
            }
        };

        ldg(0);
        stage_store(0);
        __syncthreads();

        for (int k0 = 0; k0 < nk; k0++) {
            if (k0 + 1 < nk) ldg(k0 + 1);

            const uint32_t stb = smb + (uint32_t)((k0 & 1) * STAGE);

            uint32_t bhf[4][2], blf[4][2];
#pragma unroll
            for (int p = 0; p < 2; p++) {
                uint32_t nrow = (uint32_t)(wn * 32 + p * 16) + brow_l;
                uint32_t ba = stb + TILEB + tile_addr(nrow, bg);
                ldsm4(bhf[p * 2][0], bhf[p * 2][1], bhf[p * 2 + 1][0], bhf[p * 2 + 1][1], ba);
                if (NTERMS == 3)
                    ldsm4(blf[p * 2][0], blf[p * 2][1], blf[p * 2 + 1][0], blf[p * 2 + 1][1],
                          ba + 2 * TILEB);
            }
#pragma unroll
            for (int mt = 0; mt < 4; mt++) {
                uint32_t arow = (uint32_t)(wm * 64 + mt * 16) + arow_l;
                uint32_t aa = stb + tile_addr(arow, ag);
                uint32_t ah[4], al[4];
                ldsm4(ah[0], ah[1], ah[2], ah[3], aa);
                if (NTERMS == 3)
                    ldsm4(al[0], al[1], al[2], al[3], aa + 2 * TILEB);
                // per-accumulator order hh, hl, lh (bit-identical numerics)
#pragma unroll
                for (int nt = 0; nt < 4; nt++) {
                    mma16(acc[mt][nt], ah, bhf[nt]);
                    if (NTERMS == 3) {
                        mma16(acc[mt][nt], ah, blf[nt]);
                        mma16(acc[mt][nt], al, bhf[nt]);
                    }
                }
            }

            if (k0 + 1 < nk) stage_store((k0 + 1) & 1);
            __syncthreads();
        }

        if (SCOREMIN) {
            // ---- VQ scoring epilogue: block-row min + candidate bitmask ----
            float* wmin = (float*)sb;                   // [128][4]
            float* bmin = (float*)(sb + 2048);          // [128]
            uint32_t* msk = (uint32_t*)(sb + 2560);     // [128][4]
            msk[tid] = 0; msk[tid + 256] = 0;

            const int codec0 = bx * 128 + wn * 32 + (lane & 3) * 2;
            float cbnv[4][2];
#pragma unroll
            for (int nt = 0; nt < 4; nt++) {
                cbnv[nt][0] = __ldg(cbnb + codec0 + nt * 8);
                cbnv[nt][1] = __ldg(cbnb + codec0 + nt * 8 + 1);
            }

#pragma unroll
            for (int mt = 0; mt < 4; mt++) {
#pragma unroll
                for (int h = 0; h < 2; h++) {
                    float lm = INFINITY;
#pragma unroll
                    for (int nt = 0; nt < 4; nt++) {
                        lm = fminf(lm, dd_of(acc[mt][nt][h * 2 + 0], cbnv[nt][0]));
                        lm = fminf(lm, dd_of(acc[mt][nt][h * 2 + 1], cbnv[nt][1]));
                    }
                    lm = fminf(lm, __shfl_xor_sync(0xffffffffu, lm, 1));
                    lm = fminf(lm, __shfl_xor_sync(0xffffffffu, lm, 2));
                    if ((lane & 3) == 0) {
                        int rl = wm * 64 + mt * 16 + h * 8 + (lane >> 2);
                        wmin[rl * 4 + wn] = lm;
                    }
                }
            }
            __syncthreads();
            if (tid < 128) {
                float v = fminf(fminf(wmin[tid * 4], wmin[tid * 4 + 1]),
                                fminf(wmin[tid * 4 + 2], wmin[tid * 4 + 3]));
                gbmin[(size_t)(by * 128 + tid) * 8 + bx] = v;
                bmin[tid] = v + VQ_MARGIN;
            }
            __syncthreads();
#pragma unroll
            for (int mt = 0; mt < 4; mt++) {
#pragma unroll
                for (int h = 0; h < 2; h++) {
                    int rl = wm * 64 + mt * 16 + h * 8 + (lane >> 2);
                    float th = bmin[rl];
#pragma unroll
                    for (int nt = 0; nt < 4; nt++) {
#pragma unroll
                        for (int q = 0; q < 2; q++) {
                            float d = dd_of(acc[mt][nt][h * 2 + q], cbnv[nt][q]);
                            if (d <= th) {
                                int bit = nt * 8 + (lane & 3) * 2 + q;
                                atomicOr(&msk[rl * 4 + wn], 1u << bit);
                            }
                        }
                    }
                }
            }
            __syncthreads();
            {
                int w0 = tid;
                gmask[(size_t)(by * 128 + (w0 >> 2)) * 32 + bx * 4 + (w0 & 3)] = msk[w0];
                int w1 = tid + 256;
                gmask[(size_t)(by * 128 + (w1 >> 2)) * 32 + bx * 4 + (w1 & 3)] = msk[w1];
            }
            continue;   // next tile
        }

        // ---- standard epilogue ----
        const int row0 = by * 128 + wm * 64 + (lane >> 2);
        const int col0 = bx * 128 + wn * 32 + (lane & 3) * 2;
        float psum[4][2];
        if (PARTIAL) {
#pragma unroll
            for (int mt = 0; mt < 4; mt++) { psum[mt][0] = 0.f; psum[mt][1] = 0.f; }
        }
#pragma unroll
        for (int mt = 0; mt < 4; mt++) {
#pragma unroll
            for (int nt = 0; nt < 4; nt++) {
                int rr = row0 + mt * 16;
                int cc = col0 + nt * 8;
                float b0 = 0.f, b1 = 0.f;
                if (HASBIAS) { b0 = __ldg(bias + cc); b1 = __ldg(bias + cc + 1); }
                float2 v0, v1;
                v0.x = acc[mt][nt][0] * INVS + b0; v0.y = acc[mt][nt][1] * INVS + b1;
                v1.x = acc[mt][nt][2] * INVS + b0; v1.y = acc[mt][nt][3] * INVS + b1;
                if (RELU) {
                    v0.x = fmaxf(v0.x, 0.f); v0.y = fmaxf(v0.y, 0.f);
                    v1.x = fmaxf(v1.x, 0.f); v1.y = fmaxf(v1.y, 0.f);
                }
                *(float2*)(C + (size_t)rr * N + cc)       = v0;
                *(float2*)(C + (size_t)(rr + 8) * N + cc) = v1;
                if (PARTIAL) {
                    float2 x0 = *(const float2*)(X + (size_t)rr * N + cc);
                    float2 x1 = *(const float2*)(X + (size_t)(rr + 8) * N + cc);
                    float d0 = v0.x - x0.x, d1 = v0.y - x0.y;
                    float d2 = v1.x - x1.x, d3 = v1.y - x1.y;
                    psum[mt][0] += d0 * d0 + d1 * d1;
                    psum[mt][1] += d2 * d2 + d3 * d3;
                }
            }
        }
        if (PARTIAL) {
#pragma unroll
            for (int mt = 0; mt < 4; mt++) {
#pragma unroll
                for (int h = 0; h < 2; h++) {
                    float v = psum[mt][h];
                    v += __shfl_xor_sync(0xffffffffu, v, 1);
                    v += __shfl_xor_sync(0xffffffffu, v, 2);
                    if ((lane & 3) == 0) {
                        int rr = row0 + mt * 16 + h * 8;
                        part[(size_t)rr * 64 + bx * 4 + wn] = v;
                    }
                }
            }
        }
    }
}

// ---------------------------------------------------------------------------
// Mega-prep: all weight transposes + codebook prep + counter reset in ONE
// kernel. Segments decoded from blockIdx.x; per-segment code is identical to
// the previous separate kernels (bit-identical outputs).
// Block = 256 threads (treated as 32x8 for transpose segments).
// ---------------------------------------------------------------------------
__device__ __forceinline__ void do_transpose(
    const float* __restrict__ W, __half* __restrict__ Thi,
    __half* __restrict__ Tlo, int K, int N, int bx, int by, bool wlo,
    float (*tile)[33])
{
    int tx = threadIdx.x & 31;
    int ty = threadIdx.x >> 5;
    int n0 = bx * 32;
    int k0 = by * 32;
#pragma unroll
    for (int i = 0; i < 32; i += 8)
        tile[ty + i][tx] = W[(size_t)(k0 + ty + i) * N + n0 + tx];
    __syncthreads();
#pragma unroll
    for (int i = 0; i < 32; i += 8) {
        float v = SB * tile[tx][ty + i];
        __half h = __float2half_rn(v);
        size_t o = (size_t)(n0 + ty + i) * K + k0 + tx;
        Thi[o] = h;
        if (wlo) Tlo[o] = __float2half_rn(v - __half2float(h));
    }
}

__global__ __launch_bounds__(256)
void mega_prep(const float* __restrict__ encW1, const float* __restrict__ encW2,
               const float* __restrict__ encW3, const float* __restrict__ decW1,
               const float* __restrict__ decW2, const float* __restrict__ decW3,
               const float* __restrict__ cb0, const float* __restrict__ cb1,
               const float* __restrict__ cb2,
               __half* __restrict__ w1h, __half* __restrict__ w1l,
               __half* __restrict__ w2h, __half* __restrict__ w2l,
               __half* __restrict__ w3h, __half* __restrict__ w3l,
               __half* __restrict__ d1h, __half* __restrict__ d2h,
               __half* __restrict__ d3h, __half* __restrict__ cbh,
               float* __restrict__ cbn)
{
    __shared__ float tile[32][33];
    int b = blockIdx.x;

    if (b == 0 && threadIdx.x < 16) g_tile_ctr[threadIdx.x] = 0;

    // segment sizes (blocks): w1 2048, w2 512, w3 128, d1 128, d2 512, d3 2048, cb 384
    if (b < 2048) {                               // w1: [D_IN,H1D] -> [H1D,D_IN]
        do_transpose(encW1, w1h, w1l, D_IN, H1D, b % (H1D / 32), b / (H1D / 32), true, tile);
        return;
    }
    b -= 2048;
    if (b < 512) {                                // w2
        do_transpose(encW2, w2h, w2l, H1D, H2D, b % (H2D / 32), b / (H2D / 32), true, tile);
        return;
    }
    b -= 512;
    if (b < 128) {                                // w3
        do_transpose(encW3, w3h, w3l, H2D, DLAT, b % (DLAT / 32), b / (DLAT / 32), true, tile);
        return;
    }
    b -= 128;
    if (b < 128) {                                // d1 (hi only)
        do_transpose(decW1, d1h, nullptr, DLAT, H2D, b % (H2D / 32), b / (H2D / 32), false, tile);
        return;
    }
    b -= 128;
    if (b < 512) {                                // d2
        do_transpose(decW2, d2h, nullptr, H2D, H1D, b % (H1D / 32), b / (H1D / 32), false, tile);
        return;
    }
    b -= 512;
    if (b < 2048) {                               // d3
        do_transpose(decW3, d3h, nullptr, H1D, D_IN, b % (D_IN / 32), b / (D_IN / 32), false, tile);
        return;
    }
    b -= 2048;
    {                                             // cb prep: 384 blocks, warp/code
        int code = b * 8 + ((int)threadIdx.x >> 5);    // 0..3071
        int lane = threadIdx.x & 31;
        const float* cb = (code < KCODE) ? cb0 : (code < 2 * KCODE ? cb1 : cb2);
        const float* c  = cb + (size_t)(code & (KCODE - 1)) * DLAT;
        __half* oh = cbh + (size_t)code * DLAT;
        float s = 0.f;
#pragma unroll
        for (int i = 0; i < 8; i++) {
            float v = c[lane + 32 * i];
            s += v * v;
            oh[lane + 32 * i] = __float2half_rn(SB * v);
        }
#pragma unroll
        for (int o = 16; o; o >>= 1) s += __shfl_xor_sync(0xffffffffu, s, o);
        if (lane == 0) cbn[code] = s;
    }
}

// ---------------------------------------------------------------------------
// LayerNorm over DLAT=256, warp per row
// ---------------------------------------------------------------------------
__global__ __launch_bounds__(256)
void ln_kernel(float* __restrict__ z, const float* __restrict__ g,
               const float* __restrict__ b)
{
    int row  = blockIdx.x * 8 + (threadIdx.x >> 5);
    int lane = threadIdx.x & 31;
    float* zr = z + (size_t)row * DLAT;

    float v[8];
    float s = 0.f;
#pragma unroll
    for (int i = 0; i < 8; i++) { v[i] = zr[lane + 32 * i]; s += v[i]; }
#pragma unroll
    for (int o = 16; o; o >>= 1) s += __shfl_xor_sync(0xffffffffu, s, o);
    float mu = s * (1.0f / 256.0f);

    float s2 = 0.f;
#pragma unroll
    for (int i = 0; i < 8; i++) { float d = v[i] - mu; s2 += d * d; }
#pragma unroll
    for (int o = 16; o; o >>= 1) s2 += __shfl_xor_sync(0xffffffffu, s2, o);
    float var = s2 * (1.0f / 256.0f);
    float rs  = 1.0f / sqrtf(var + 1e-5f);

#pragma unroll
    for (int i = 0; i < 8; i++) {
        int col = lane + 32 * i;
        zr[col] = (v[i] - mu) * rs * g[col] + b[col];
    }
}

// ---------------------------------------------------------------------------
// VQ step from candidate bitmasks + block mins (R13-proven).
// ---------------------------------------------------------------------------
__global__ __launch_bounds__(256)
void vq_step(float* __restrict__ res, const uint32_t* __restrict__ gmask,
             const float* __restrict__ gbmin,
             const float* __restrict__ cbn, const float* __restrict__ cb,
             float* __restrict__ zq, float* __restrict__ out_loss,
             float* __restrict__ out_idx, int stage)
{
    int row  = blockIdx.x * 8 + (threadIdx.x >> 5);
    int lane = threadIdx.x & 31;

    float* r = res + (size_t)row * DLAT;
    float rv[8];
    float s = 0.f;
#pragma unroll
    for (int i = 0; i < 8; i++) { rv[i] = r[lane + 32 * i]; s += rv[i] * rv[i]; }
#pragma unroll
    for (int o = 16; o; o >>= 1) s += __shfl_xor_sync(0xffffffffu, s, o);
    const float rnorm = s;

    float bm = (lane < 8) ? __ldg(gbmin + (size_t)row * 8 + lane) : INFINITY;
    float gmin = bm;
#pragma unroll
    for (int o = 16; o; o >>= 1) gmin = fminf(gmin, __shfl_xor_sync(0xffffffffu, gmin, o));
    const float th = gmin + VQ_MARGIN;
    float myblk = __shfl_sync(0xffffffffu, bm, lane >> 2);

    uint32_t cmask = __ldg(gmask + (size_t)row * 32 + lane);
    if (myblk > th) cmask = 0;

    float bestv = INFINITY;
    int   bestn = KCODE;
    for (;;) {
        uint32_t ball = __ballot_sync(0xffffffffu, cmask != 0);
        if (!ball) break;
        int src = __ffs(ball) - 1;
        uint32_t m = __shfl_sync(0xffffffffu, cmask, src);
        int j = __ffs(m) - 1;
        if (lane == src) cmask &= cmask - 1;
        int n = (src >> 2) * 128 + (src & 3) * 32 + j;

        const float* c = cb + (size_t)n * DLAT;
        float dot = 0.f;
#pragma unroll
        for (int i = 0; i < 8; i++) dot += rv[i] * c[lane + 32 * i];
#pragma unroll
        for (int o = 16; o; o >>= 1) dot += __shfl_xor_sync(0xffffffffu, dot, o);

        float d = (rnorm - 2.0f * dot) + cbn[n];
        if (d < bestv || (d == bestv && n < bestn)) { bestv = d; bestn = n; }
    }
    const int bi = bestn;
    if (lane == 0) out_idx[row * 3 + stage] = (float)bi;

    const float* c = cb + (size_t)bi * DLAT;
    float* q = zq + (size_t)row * DLAT;
    float se = 0.f;
#pragma unroll
    for (int i = 0; i < 8; i++) {
        int col = lane + 32 * i;
        float ev = c[col];
        float diff = rv[i] - ev;
        se += diff * diff;
        float t   = ev - rv[i];
        float zqe = rv[i] + t;
        if (stage < 2) r[col] = rv[i] - zqe;
        q[col] = (stage == 0) ? zqe : (q[col] + zqe);
    }
#pragma unroll
    for (int o = 16; o; o >>= 1) se += __shfl_xor_sync(0xffffffffu, se, o);
    if (lane == 0) {
        float m = se * (1.0f / 256.0f);
        float l = m + 0.25f * m;
        out_loss[row] = (stage == 0) ? l : (out_loss[row] + l);
    }
}

// ---------------------------------------------------------------------------
// Finalize2: out_loss[row] += sum(part[row][0..63]) / 2048. Warp per row.
// ---------------------------------------------------------------------------
__global__ __launch_bounds__(256)
void finalize2_kernel(const float* __restrict__ part, float* __restrict__ out_loss)
{
    int row  = blockIdx.x * 8 + (threadIdx.x >> 5);
    int lane = threadIdx.x & 31;
    const float* p = part + (size_t)row * 64;
    float s = p[lane] + p[lane + 32];
#pragma unroll
    for (int o = 16; o; o >>= 1) s += __shfl_xor_sync(0xffffffffu, s, o);
    if (lane == 0) out_loss[row] += s * (1.0f / 2048.0f);
}

// ---------------------------------------------------------------------------
// Launch
// ---------------------------------------------------------------------------
extern "C" void kernel_launch(void* const* d_in, const int* in_sizes, int n_in,
                              void* d_out, int out_size)
{
    const float* x      = (const float*)d_in[0];
    const float* encW1  = (const float*)d_in[1];
    const float* encb1  = (const float*)d_in[2];
    const float* encW2  = (const float*)d_in[3];
    const float* encb2  = (const float*)d_in[4];
    const float* encW3  = (const float*)d_in[5];
    const float* encb3  = (const float*)d_in[6];
    const float* ln_g   = (const float*)d_in[7];
    const float* ln_b   = (const float*)d_in[8];
    const float* cb0    = (const float*)d_in[9];
    const float* cb1    = (const float*)d_in[10];
    const float* cb2    = (const float*)d_in[11];
    const float* decW1  = (const float*)d_in[12];
    const float* decb1  = (const float*)d_in[13];
    const float* decW2  = (const float*)d_in[14];
    const float* decb2  = (const float*)d_in[15];
    const float* decW3  = (const float*)d_in[16];
    const float* decb3  = (const float*)d_in[17];

    float *h1, *h2, *res, *zq, *cbn, *partp, *bminp;
    uint32_t* maskp;
    __half *w1h, *w1l, *w2h, *w2l, *w3h, *w3l;
    __half *d1h, *d2h, *d3h, *cbh;
    cudaGetSymbolAddress((void**)&h1, g_h1);
    cudaGetSymbolAddress((void**)&h2, g_h2);
    cudaGetSymbolAddress((void**)&res, g_res);
    cudaGetSymbolAddress((void**)&zq, g_zq);
    cudaGetSymbolAddress((void**)&cbn, g_cbn);
    cudaGetSymbolAddress((void**)&partp, g_part);
    cudaGetSymbolAddress((void**)&maskp, g_mask);
    cudaGetSymbolAddress((void**)&bminp, g_bmin);
    cudaGetSymbolAddress((void**)&w1h, g_w1h); cudaGetSymbolAddress((void**)&w1l, g_w1l);
    cudaGetSymbolAddress((void**)&w2h, g_w2h); cudaGetSymbolAddress((void**)&w2l, g_w2l);
    cudaGetSymbolAddress((void**)&w3h, g_w3h); cudaGetSymbolAddress((void**)&w3l, g_w3l);
    cudaGetSymbolAddress((void**)&d1h, g_d1h);
    cudaGetSymbolAddress((void**)&d2h, g_d2h);
    cudaGetSymbolAddress((void**)&d3h, g_d3h);
    cudaGetSymbolAddress((void**)&cbh, g_cbh);

    float* xhat     = (float*)d_out;
    float* out_loss = xhat + (size_t)BATCH * D_IN;
    float* out_idx  = out_loss + BATCH;

    const int SMEM3 = 1024 + 2 * 16384;  // 33792
    const int SMEM1 = 1024 + 2 * 8192;   // 17408
    cudaFuncSetAttribute((const void*)mma_gemm_h<3, true,  true,  false, false>, cudaFuncAttributeMaxDynamicSharedMemorySize, SMEM3);
    cudaFuncSetAttribute((const void*)mma_gemm_h<3, false, true,  false, false>, cudaFuncAttributeMaxDynamicSharedMemorySize, SMEM3);
    cudaFuncSetAttribute((const void*)mma_gemm_h<1, false, false, false, true >, cudaFuncAttributeMaxDynamicSharedMemorySize, SMEM1);
    cudaFuncSetAttribute((const void*)mma_gemm_h<1, true,  true,  false, false>, cudaFuncAttributeMaxDynamicSharedMemorySize, SMEM1);
    cudaFuncSetAttribute((const void*)mma_gemm_h<1, false, true,  true,  false>, cudaFuncAttributeMaxDynamicSharedMemorySize, SMEM1);

    const dim3 blk(256);
    const dim3 ggrid(GEMM_GRID);
    const int MB = BATCH / 128;          // 128
    const int warpGrid = BATCH / 8;      // 2048

    // ---- fused prep (transposes + codebook prep + counter reset), 1 launch ----
    mega_prep<<<2048 + 512 + 128 + 128 + 512 + 2048 + 384, blk>>>(
        encW1, encW2, encW3, decW1, decW2, decW3, cb0, cb1, cb2,
        w1h, w1l, w2h, w2l, w3h, w3l, d1h, d2h, d3h, cbh, cbn);

    // ---- encoder (fp16 split x3 ~ fp32 accuracy; feeds argmin) ----
    mma_gemm_h<3, true,  true,  false, false><<<ggrid, blk, SMEM3>>>(x,  w1h, w1l, encb1, h1,  H1D,  D_IN, H1D / 128, (H1D / 128) * MB, 0, nullptr, nullptr, nullptr, nullptr, nullptr);
    mma_gemm_h<3, true,  true,  false, false><<<ggrid, blk, SMEM3>>>(h1, w2h, w2l, encb2, h2,  H2D,  H1D,  H2D / 128, (H2D / 128) * MB, 1, nullptr, nullptr, nullptr, nullptr, nullptr);
    mma_gemm_h<3, false, true,  false, false><<<ggrid, blk, SMEM3>>>(h2, w3h, w3l, encb3, res, DLAT, H2D,  DLAT / 128, (DLAT / 128) * MB, 2, nullptr, nullptr, nullptr, nullptr, nullptr);

    ln_kernel<<<warpGrid, blk>>>(res, ln_g, ln_b);

    // ---- residual VQ: fused score+mask+blockmin GEMM, pruned exact refine ----
    for (int s = 0; s < 3; s++) {
        const float* cb = (s == 0) ? cb0 : (s == 1 ? cb1 : cb2);
        mma_gemm_h<1, false, false, false, true><<<ggrid, blk, SMEM1>>>(
            res, cbh + (size_t)s * KCODE * DLAT, nullptr, nullptr, nullptr, KCODE, DLAT,
            KCODE / 128, (KCODE / 128) * MB, 3 + s,
            nullptr, nullptr, cbn + s * KCODE, maskp, bminp);
        vq_step<<<warpGrid, blk>>>(res, maskp, bminp, cbn + s * KCODE, cb, zq, out_loss, out_idx, s);
    }

    // ---- decoder (fp16 single-pass; L3 fuses recon-SSE partials) ----
    mma_gemm_h<1, true,  true,  false, false><<<ggrid, blk, SMEM1>>>(zq, d1h, nullptr, decb1, h2,   H2D,  DLAT, H2D / 128, (H2D / 128) * MB, 6, nullptr, nullptr, nullptr, nullptr, nullptr);
    mma_gemm_h<1, true,  true,  false, false><<<ggrid, blk, SMEM1>>>(h2, d2h, nullptr, decb2, h1,   H1D,  H2D,  H1D / 128, (H1D / 128) * MB, 7, nullptr, nullptr, nullptr, nullptr, nullptr);
    mma_gemm_h<1, false, true,  true,  false><<<ggrid, blk, SMEM1>>>(h1, d3h, nullptr, decb3, xhat, D_IN, H1D,  D_IN / 128, (D_IN / 128) * MB, 8, x, partp, nullptr, nullptr, nullptr);

    finalize2_kernel<<<warpGrid, blk>>>(partp, out_loss);
}

// round 16
// speedup vs baseline: 1.2460x; 1.0176x over previous
#include <cuda_runtime.h>
#include <cuda_fp16.h>
#include <math.h>
#include <stdint.h>

// Problem dims (fixed by the dataset)
constexpr int BATCH = 16384;
constexpr int D_IN  = 2048;
constexpr int H1D   = 1024;
constexpr int H2D   = 512;
constexpr int DLAT  = 256;
constexpr int KCODE = 1024;

// fp16 staging scales (powers of 2; exact rescale in epilogue)
constexpr float SA = 16.0f;
constexpr float SB = 32.0f;
constexpr float INVS = 1.0f / (16.0f * 32.0f);

constexpr float VQ_MARGIN = 0.05f;

constexpr int GEMM_GRID = 296;   // 2 CTAs/SM x 148 SMs

// ---------------------------------------------------------------------------
// Scratch (allocation-free contract: __device__ globals)
// ---------------------------------------------------------------------------
__device__ float g_h1[(size_t)BATCH * H1D];     // enc h1 / dec h1
__device__ float g_h2[(size_t)BATCH * H2D];     // enc h2 / dec h2
__device__ float g_res[(size_t)BATCH * DLAT];   // z after LN, then running residual
__device__ float g_zq[(size_t)BATCH * DLAT];    // z_q_total
__device__ float g_part[(size_t)BATCH * 64];    // per-row recon SSE partials
__device__ uint32_t g_mask[(size_t)BATCH * 32]; // VQ candidate bitmasks (128b x 8 blk)
__device__ float g_bmin[(size_t)BATCH * 8];     // per-row per-block score mins
__device__ float g_cbn[3 * KCODE];
__device__ uint32_t g_tile_ctr[16];             // dynamic tile counters
// pre-split fp16 weights, [N,K] row-major, scaled by SB
__device__ __half g_w1h[(size_t)H1D * D_IN], g_w1l[(size_t)H1D * D_IN];
__device__ __half g_w2h[(size_t)H2D * H1D], g_w2l[(size_t)H2D * H1D];
__device__ __half g_w3h[(size_t)DLAT * H2D], g_w3l[(size_t)DLAT * H2D];
__device__ __half g_d1h[(size_t)H2D * DLAT];
__device__ __half g_d2h[(size_t)H1D * H2D];
__device__ __half g_d3h[(size_t)D_IN * H1D];
__device__ __half g_cbh[(size_t)3 * KCODE * DLAT];   // hi-only, scaled by SB

// ---------------------------------------------------------------------------
// Helpers
// ---------------------------------------------------------------------------
__device__ __forceinline__ uint32_t smem_u32(const void* p) {
    uint32_t a;
    asm("{ .reg .u64 t; cvta.to.shared.u64 t, %1; cvt.u32.u64 %0, t; }"
        : "=r"(a) : "l"(p));
    return a;
}

__device__ __forceinline__ uint32_t pack_h2(__half a, __half b) {
    __half2 h = __halves2half2(a, b);
    return *(uint32_t*)&h;
}

// split x,y (pre-scaled) into packed fp16 hi and lo half2
__device__ __forceinline__ void split2(float x, float y,
                                       uint32_t& hi, uint32_t& lo) {
    __half hx = __float2half_rn(x), hy = __float2half_rn(y);
    __half lx = __float2half_rn(x - __half2float(hx));
    __half ly = __float2half_rn(y - __half2float(hy));
    hi = pack_h2(hx, hy);
    lo = pack_h2(lx, ly);
}

// m16n8k16 fp16 MMA (row.col), fp32 accumulate
__device__ __forceinline__ void mma16(float d[4], const uint32_t a[4],
                                      const uint32_t b[2]) {
    asm volatile(
        "mma.sync.aligned.m16n8k16.row.col.f32.f16.f16.f32 "
        "{%0,%1,%2,%3}, {%4,%5,%6,%7}, {%8,%9}, {%0,%1,%2,%3};\n"
        : "+f"(d[0]), "+f"(d[1]), "+f"(d[2]), "+f"(d[3])
        : "r"(a[0]), "r"(a[1]), "r"(a[2]), "r"(a[3]),
          "r"(b[0]), "r"(b[1]));
}

__device__ __forceinline__ void ldsm4(uint32_t& r0, uint32_t& r1,
                                      uint32_t& r2, uint32_t& r3, uint32_t addr) {
    asm volatile("ldmatrix.sync.aligned.m8n8.x4.shared.b16 {%0,%1,%2,%3}, [%4];"
                 : "=r"(r0), "=r"(r1), "=r"(r2), "=r"(r3) : "r"(addr));
}

// fp16 tile: [128 rows][16 halves] = 32B rows.
// 16B group g of row r stored at group (g ^ ((r>>2)&1)).  (R8-proven layout.)
__device__ __forceinline__ uint32_t tile_addr(uint32_t row, uint32_t g) {
    return row * 32 + ((g ^ ((row >> 2) & 1u)) << 4);
}

// identical expression used in both min-pass and flag-pass (determinism)
__device__ __forceinline__ float dd_of(float accv, float cbnv) {
    return fmaf(accv, -2.0f * INVS, cbnv);
}

// ---------------------------------------------------------------------------
// fp16 mma.sync GEMM, persistent CTAs with dynamic tile scheduling.
//   C = act((A @ B^T)*INVS + bias)
//   NTERMS==3: A split (hi+lo) x B (hi+lo); 1-deep prefetch (reg-cap bound)
//   NTERMS==1: single-pass; 2-deep register prefetch (covers DRAM latency)
//   PARTIAL: also emit per-row partial SSE of (C - X)
//   SCOREMIN: VQ mode — no C write; candidate bitmask + block-min value
// Tile 128x128, BK=16, 256 threads, 8 warps (2m x 4n).  (R8-proven core.)
// Grid = GEMM_GRID CTAs; tiles claimed via g_tile_ctr[cid].
// SMEM: [0..1024) tile broadcast; stages at +1024.
// ---------------------------------------------------------------------------
template <int NTERMS, bool RELU, bool HASBIAS, bool PARTIAL, bool SCOREMIN>
__global__ __launch_bounds__(256, 2)
void mma_gemm_h(const float* __restrict__ A, const __half* __restrict__ Bhi,
                const __half* __restrict__ Blo, const float* __restrict__ bias,
                float* __restrict__ C, int N, int Kd,
                int nbx, int ntiles, int cid,
                const float* __restrict__ X, float* __restrict__ part,
                const float* __restrict__ cbnb, uint32_t* __restrict__ gmask,
                float* __restrict__ gbmin)
{
    extern __shared__ char smem[];
    char* sb = smem + 1024;                       // stage base
    const uint32_t smb = smem_u32(smem) + 1024;
    volatile uint32_t* s_tile = (volatile uint32_t*)smem;
    constexpr int TILEB = 4096;
    constexpr int STAGE = (NTERMS == 3) ? 16384 : 8192;

    const int tid  = threadIdx.x;
    const int wid  = tid >> 5;
    const int lane = tid & 31;
    const int wm   = wid & 1;       // 0..1 -> 64 rows
    const int wn   = wid >> 1;      // 0..3 -> 32 cols

    const int nk = Kd >> 4;         // BK=16 chunks (even for all our shapes)

    // staging role: thread -> (row r, 8-element group hf of the 16-wide chunk)
    const int r  = tid >> 1;
    const int hf = tid & 1;
    const uint32_t soff = tile_addr((uint32_t)r, (uint32_t)hf);

    // ldmatrix per-lane address components
    const uint32_t amat   = (uint32_t)lane >> 3;
    const uint32_t arow_l = (uint32_t)(lane & 7) + ((amat & 1u) << 3);
    const uint32_t ag     = amat >> 1;
    const uint32_t bmat   = (uint32_t)lane >> 3;
    const uint32_t brow_l = (uint32_t)(lane & 7) + ((bmat >> 1) << 3);
    const uint32_t bg     = bmat & 1u;

    for (;;) {
        __syncthreads();
        if (tid == 0) *s_tile = atomicAdd(&g_tile_ctr[cid], 1u);
        __syncthreads();
        const uint32_t t = *s_tile;
        if (t >= (uint32_t)ntiles) break;
        const int bx = (int)(t % (uint32_t)nbx);
        const int by = (int)(t / (uint32_t)nbx);

        const float* Ag  = A   + (size_t)(by * 128) * Kd;
        const __half* Bh = Bhi + (size_t)(bx * 128) * Kd;
        const __half* Bl = (NTERMS == 3) ? Blo + (size_t)(bx * 128) * Kd : nullptr;

        float acc[4][4][4];
#pragma unroll
        for (int i = 0; i < 4; i++)
#pragma unroll
            for (int j = 0; j < 4; j++)
#pragma unroll
                for (int q = 0; q < 4; q++) acc[i][j][q] = 0.0f;

        // MMA body for one staged chunk (shared between both pipelines)
        auto mma_body = [&](uint32_t stb) {
            uint32_t bhf[4][2], blf[4][2];
#pragma unroll
            for (int p = 0; p < 2; p++) {
                uint32_t nrow = (uint32_t)(wn * 32 + p * 16) + brow_l;
                uint32_t ba = stb + TILEB + tile_addr(nrow, bg);
                ldsm4(bhf[p * 2][0], bhf[p * 2][1], bhf[p * 2 + 1][0], bhf[p * 2 + 1][1], ba);
                if (NTERMS == 3)
                    ldsm4(blf[p * 2][0], blf[p * 2][1], blf[p * 2 + 1][0], blf[p * 2 + 1][1],
                          ba + 2 * TILEB);
            }
#pragma unroll
            for (int mt = 0; mt < 4; mt++) {
                uint32_t arow = (uint32_t)(wm * 64 + mt * 16) + arow_l;
                uint32_t aa = stb + tile_addr(arow, ag);
                uint32_t ah[4], al[4];
                ldsm4(ah[0], ah[1], ah[2], ah[3], aa);
                if (NTERMS == 3)
                    ldsm4(al[0], al[1], al[2], al[3], aa + 2 * TILEB);
                // per-accumulator order hh, hl, lh (bit-identical numerics)
#pragma unroll
                for (int nt = 0; nt < 4; nt++) {
                    mma16(acc[mt][nt], ah, bhf[nt]);
                    if (NTERMS == 3) {
                        mma16(acc[mt][nt], ah, blf[nt]);
                        mma16(acc[mt][nt], al, bhf[nt]);
                    }
                }
            }
        };

        if (NTERMS == 3) {
            // ---- 1-deep prefetch (register-cap bound path; R8-proven) ----
            float4 va[2];
            uint4 vbh, vbl;

            auto ldg = [&](int k0) {
                const float4* pa = (const float4*)(Ag + (size_t)r * Kd + k0 * 16 + hf * 8);
                va[0] = pa[0]; va[1] = pa[1];
                vbh = *(const uint4*)(Bh + (size_t)r * Kd + k0 * 16 + hf * 8);
                vbl = *(const uint4*)(Bl + (size_t)r * Kd + k0 * 16 + hf * 8);
            };
            auto stage_store = [&](int s) {
                char* st = sb + s * STAGE;
                uint4 ha, la;
                split2(SA * va[0].x, SA * va[0].y, ha.x, la.x);
                split2(SA * va[0].z, SA * va[0].w, ha.y, la.y);
                split2(SA * va[1].x, SA * va[1].y, ha.z, la.z);
                split2(SA * va[1].z, SA * va[1].w, ha.w, la.w);
                *(uint4*)(st + soff)             = ha;
                *(uint4*)(st + TILEB + soff)     = vbh;
                *(uint4*)(st + 2 * TILEB + soff) = la;
                *(uint4*)(st + 3 * TILEB + soff) = vbl;
            };

            ldg(0);
            stage_store(0);
            __syncthreads();
            for (int k0 = 0; k0 < nk; k0++) {
                if (k0 + 1 < nk) ldg(k0 + 1);
                mma_body(smb + (uint32_t)((k0 & 1) * STAGE));
                if (k0 + 1 < nk) stage_store((k0 + 1) & 1);
                __syncthreads();
            }
        } else {
            // ---- 2-deep register prefetch (covers DRAM latency on short-K) ----
            float4 vaA[2], vaB[2];
            uint4 vbA, vbB;

            auto ldgA = [&](int k0) {
                const float4* pa = (const float4*)(Ag + (size_t)r * Kd + k0 * 16 + hf * 8);
                vaA[0] = pa[0]; vaA[1] = pa[1];
                vbA = *(const uint4*)(Bh + (size_t)r * Kd + k0 * 16 + hf * 8);
            };
            auto ldgB = [&](int k0) {
                const float4* pa = (const float4*)(Ag + (size_t)r * Kd + k0 * 16 + hf * 8);
                vaB[0] = pa[0]; vaB[1] = pa[1];
                vbB = *(const uint4*)(Bh + (size_t)r * Kd + k0 * 16 + hf * 8);
            };
            auto storeA = [&](int s) {
                char* st = sb + s * STAGE;
                uint4 ha;
                ha.x = pack_h2(__float2half_rn(SA * vaA[0].x), __float2half_rn(SA * vaA[0].y));
                ha.y = pack_h2(__float2half_rn(SA * vaA[0].z), __float2half_rn(SA * vaA[0].w));
                ha.z = pack_h2(__float2half_rn(SA * vaA[1].x), __float2half_rn(SA * vaA[1].y));
                ha.w = pack_h2(__float2half_rn(SA * vaA[1].z), __float2half_rn(SA * vaA[1].w));
                *(uint4*)(st + soff)         = ha;
                *(uint4*)(st + TILEB + soff) = vbA;
            };
            auto storeB = [&](int s) {
                char* st = sb + s * STAGE;
                uint4 ha;
                ha.x = pack_h2(__float2half_rn(SA * vaB[0].x), __float2half_rn(SA * vaB[0].y));
                ha.y = pack_h2(__float2half_rn(SA * vaB[0].z), __float2half_rn(SA * vaB[0].w));
                ha.z = pack_h2(__float2half_rn(SA * vaB[1].x), __float2half_rn(SA * vaB[1].y));
                ha.w = pack_h2(__float2half_rn(SA * vaB[1].z), __float2half_rn(SA * vaB[1].w));
                *(uint4*)(st + soff)         = ha;
                *(uint4*)(st + TILEB + soff) = vbB;
            };

            // prologue: stage chunk 0 (set A), hold chunk 1 in set B
            ldgA(0);
            storeA(0);
            if (nk > 1) ldgB(1);
            __syncthreads();

            for (int k0 = 0; k0 < nk; k0 += 2) {
                // chunk k0 (even stage): prefetch k0+2 into set A, store set B (k0+1)
                if (k0 + 2 < nk) ldgA(k0 + 2);
                mma_body(smb);                       // stage 0
                if (k0 + 1 < nk) storeB(1);
                __syncthreads();
                if (k0 + 1 >= nk) break;
                // chunk k0+1 (odd stage): prefetch k0+3 into set B, store set A (k0+2)
                if (k0 + 3 < nk) ldgB(k0 + 3);
                mma_body(smb + STAGE);               // stage 1
                if (k0 + 2 < nk) storeA(0);
                __syncthreads();
            }
        }

        if (SCOREMIN) {
            // ---- VQ scoring epilogue: block-row min + candidate bitmask ----
            float* wmin = (float*)sb;                   // [128][4]
            float* bmin = (float*)(sb + 2048);          // [128]
            uint32_t* msk = (uint32_t*)(sb + 2560);     // [128][4]
            msk[tid] = 0; msk[tid + 256] = 0;

            const int codec0 = bx * 128 + wn * 32 + (lane & 3) * 2;
            float cbnv[4][2];
#pragma unroll
            for (int nt = 0; nt < 4; nt++) {
                cbnv[nt][0] = __ldg(cbnb + codec0 + nt * 8);
                cbnv[nt][1] = __ldg(cbnb + codec0 + nt * 8 + 1);
            }

#pragma unroll
            for (int mt = 0; mt < 4; mt++) {
#pragma unroll
                for (int h = 0; h < 2; h++) {
                    float lm = INFINITY;
#pragma unroll
                    for (int nt = 0; nt < 4; nt++) {
                        lm = fminf(lm, dd_of(acc[mt][nt][h * 2 + 0], cbnv[nt][0]));
                        lm = fminf(lm, dd_of(acc[mt][nt][h * 2 + 1], cbnv[nt][1]));
                    }
                    lm = fminf(lm, __shfl_xor_sync(0xffffffffu, lm, 1));
                    lm = fminf(lm, __shfl_xor_sync(0xffffffffu, lm, 2));
                    if ((lane & 3) == 0) {
                        int rl = wm * 64 + mt * 16 + h * 8 + (lane >> 2);
                        wmin[rl * 4 + wn] = lm;
                    }
                }
            }
            __syncthreads();
            if (tid < 128) {
                float v = fminf(fminf(wmin[tid * 4], wmin[tid * 4 + 1]),
                                fminf(wmin[tid * 4 + 2], wmin[tid * 4 + 3]));
                gbmin[(size_t)(by * 128 + tid) * 8 + bx] = v;
                bmin[tid] = v + VQ_MARGIN;
            }
            __syncthreads();
#pragma unroll
            for (int mt = 0; mt < 4; mt++) {
#pragma unroll
                for (int h = 0; h < 2; h++) {
                    int rl = wm * 64 + mt * 16 + h * 8 + (lane >> 2);
                    float th = bmin[rl];
#pragma unroll
                    for (int nt = 0; nt < 4; nt++) {
#pragma unroll
                        for (int q = 0; q < 2; q++) {
                            float d = dd_of(acc[mt][nt][h * 2 + q], cbnv[nt][q]);
                            if (d <= th) {
                                int bit = nt * 8 + (lane & 3) * 2 + q;
                                atomicOr(&msk[rl * 4 + wn], 1u << bit);
                            }
                        }
                    }
                }
            }
            __syncthreads();
            {
                int w0 = tid;
                gmask[(size_t)(by * 128 + (w0 >> 2)) * 32 + bx * 4 + (w0 & 3)] = msk[w0];
                int w1 = tid + 256;
                gmask[(size_t)(by * 128 + (w1 >> 2)) * 32 + bx * 4 + (w1 & 3)] = msk[w1];
            }
            continue;   // next tile
        }

        // ---- standard epilogue ----
        const int row0 = by * 128 + wm * 64 + (lane >> 2);
        const int col0 = bx * 128 + wn * 32 + (lane & 3) * 2;
        float psum[4][2];
        if (PARTIAL) {
#pragma unroll
            for (int mt = 0; mt < 4; mt++) { psum[mt][0] = 0.f; psum[mt][1] = 0.f; }
        }
#pragma unroll
        for (int mt = 0; mt < 4; mt++) {
#pragma unroll
            for (int nt = 0; nt < 4; nt++) {
                int rr = row0 + mt * 16;
                int cc = col0 + nt * 8;
                float b0 = 0.f, b1 = 0.f;
                if (HASBIAS) { b0 = __ldg(bias + cc); b1 = __ldg(bias + cc + 1); }
                float2 v0, v1;
                v0.x = acc[mt][nt][0] * INVS + b0; v0.y = acc[mt][nt][1] * INVS + b1;
                v1.x = acc[mt][nt][2] * INVS + b0; v1.y = acc[mt][nt][3] * INVS + b1;
                if (RELU) {
                    v0.x = fmaxf(v0.x, 0.f); v0.y = fmaxf(v0.y, 0.f);
                    v1.x = fmaxf(v1.x, 0.f); v1.y = fmaxf(v1.y, 0.f);
                }
                *(float2*)(C + (size_t)rr * N + cc)       = v0;
                *(float2*)(C + (size_t)(rr + 8) * N + cc) = v1;
                if (PARTIAL) {
                    float2 x0 = *(const float2*)(X + (size_t)rr * N + cc);
                    float2 x1 = *(const float2*)(X + (size_t)(rr + 8) * N + cc);
                    float d0 = v0.x - x0.x, d1 = v0.y - x0.y;
                    float d2 = v1.x - x1.x, d3 = v1.y - x1.y;
                    psum[mt][0] += d0 * d0 + d1 * d1;
                    psum[mt][1] += d2 * d2 + d3 * d3;
                }
            }
        }
        if (PARTIAL) {
#pragma unroll
            for (int mt = 0; mt < 4; mt++) {
#pragma unroll
                for (int h = 0; h < 2; h++) {
                    float v = psum[mt][h];
                    v += __shfl_xor_sync(0xffffffffu, v, 1);
                    v += __shfl_xor_sync(0xffffffffu, v, 2);
                    if ((lane & 3) == 0) {
                        int rr = row0 + mt * 16 + h * 8;
                        part[(size_t)rr * 64 + bx * 4 + wn] = v;
                    }
                }
            }
        }
    }
}

// ---------------------------------------------------------------------------
// Mega-prep: all weight transposes + codebook prep + counter reset in ONE
// kernel (R15-proven; bit-identical per-segment outputs).
// ---------------------------------------------------------------------------
__device__ __forceinline__ void do_transpose(
    const float* __restrict__ W, __half* __restrict__ Thi,
    __half* __restrict__ Tlo, int K, int N, int bx, int by, bool wlo,
    float (*tile)[33])
{
    int tx = threadIdx.x & 31;
    int ty = threadIdx.x >> 5;
    int n0 = bx * 32;
    int k0 = by * 32;
#pragma unroll
    for (int i = 0; i < 32; i += 8)
        tile[ty + i][tx] = W[(size_t)(k0 + ty + i) * N + n0 + tx];
    __syncthreads();
#pragma unroll
    for (int i = 0; i < 32; i += 8) {
        float v = SB * tile[tx][ty + i];
        __half h = __float2half_rn(v);
        size_t o = (size_t)(n0 + ty + i) * K + k0 + tx;
        Thi[o] = h;
        if (wlo) Tlo[o] = __float2half_rn(v - __half2float(h));
    }
}

__global__ __launch_bounds__(256)
void mega_prep(const float* __restrict__ encW1, const float* __restrict__ encW2,
               const float* __restrict__ encW3, const float* __restrict__ decW1,
               const float* __restrict__ decW2, const float* __restrict__ decW3,
               const float* __restrict__ cb0, const float* __restrict__ cb1,
               const float* __restrict__ cb2,
               __half* __restrict__ w1h, __half* __restrict__ w1l,
               __half* __restrict__ w2h, __half* __restrict__ w2l,
               __half* __restrict__ w3h, __half* __restrict__ w3l,
               __half* __restrict__ d1h, __half* __restrict__ d2h,
               __half* __restrict__ d3h, __half* __restrict__ cbh,
               float* __restrict__ cbn)
{
    __shared__ float tile[32][33];
    int b = blockIdx.x;

    if (b == 0 && threadIdx.x < 16) g_tile_ctr[threadIdx.x] = 0;

    if (b < 2048) {
        do_transpose(encW1, w1h, w1l, D_IN, H1D, b % (H1D / 32), b / (H1D / 32), true, tile);
        return;
    }
    b -= 2048;
    if (b < 512) {
        do_transpose(encW2, w2h, w2l, H1D, H2D, b % (H2D / 32), b / (H2D / 32), true, tile);
        return;
    }
    b -= 512;
    if (b < 128) {
        do_transpose(encW3, w3h, w3l, H2D, DLAT, b % (DLAT / 32), b / (DLAT / 32), true, tile);
        return;
    }
    b -= 128;
    if (b < 128) {
        do_transpose(decW1, d1h, nullptr, DLAT, H2D, b % (H2D / 32), b / (H2D / 32), false, tile);
        return;
    }
    b -= 128;
    if (b < 512) {
        do_transpose(decW2, d2h, nullptr, H2D, H1D, b % (H1D / 32), b / (H1D / 32), false, tile);
        return;
    }
    b -= 512;
    if (b < 2048) {
        do_transpose(decW3, d3h, nullptr, H1D, D_IN, b % (D_IN / 32), b / (D_IN / 32), false, tile);
        return;
    }
    b -= 2048;
    {
        int code = b * 8 + ((int)threadIdx.x >> 5);
        int lane = threadIdx.x & 31;
        const float* cb = (code < KCODE) ? cb0 : (code < 2 * KCODE ? cb1 : cb2);
        const float* c  = cb + (size_t)(code & (KCODE - 1)) * DLAT;
        __half* oh = cbh + (size_t)code * DLAT;
        float s = 0.f;
#pragma unroll
        for (int i = 0; i < 8; i++) {
            float v = c[lane + 32 * i];
            s += v * v;
            oh[lane + 32 * i] = __float2half_rn(SB * v);
        }
#pragma unroll
        for (int o = 16; o; o >>= 1) s += __shfl_xor_sync(0xffffffffu, s, o);
        if (lane == 0) cbn[code] = s;
    }
}

// ---------------------------------------------------------------------------
// LayerNorm over DLAT=256, warp per row
// ---------------------------------------------------------------------------
__global__ __launch_bounds__(256)
void ln_kernel(float* __restrict__ z, const float* __restrict__ g,
               const float* __restrict__ b)
{
    int row  = blockIdx.x * 8 + (threadIdx.x >> 5);
    int lane = threadIdx.x & 31;
    float* zr = z + (size_t)row * DLAT;

    float v[8];
    float s = 0.f;
#pragma unroll
    for (int i = 0; i < 8; i++) { v[i] = zr[lane + 32 * i]; s += v[i]; }
#pragma unroll
    for (int o = 16; o; o >>= 1) s += __shfl_xor_sync(0xffffffffu, s, o);
    float mu = s * (1.0f / 256.0f);

    float s2 = 0.f;
#pragma unroll
    for (int i = 0; i < 8; i++) { float d = v[i] - mu; s2 += d * d; }
#pragma unroll
    for (int o = 16; o; o >>= 1) s2 += __shfl_xor_sync(0xffffffffu, s2, o);
    float var = s2 * (1.0f / 256.0f);
    float rs  = 1.0f / sqrtf(var + 1e-5f);

#pragma unroll
    for (int i = 0; i < 8; i++) {
        int col = lane + 32 * i;
        zr[col] = (v[i] - mu) * rs * g[col] + b[col];
    }
}

// ---------------------------------------------------------------------------
// VQ step from candidate bitmasks + block mins (R13-proven).
// ---------------------------------------------------------------------------
__global__ __launch_bounds__(256)
void vq_step(float* __restrict__ res, const uint32_t* __restrict__ gmask,
             const float* __restrict__ gbmin,
             const float* __restrict__ cbn, const float* __restrict__ cb,
             float* __restrict__ zq, float* __restrict__ out_loss,
             float* __restrict__ out_idx, int stage)
{
    int row  = blockIdx.x * 8 + (threadIdx.x >> 5);
    int lane = threadIdx.x & 31;

    float* r = res + (size_t)row * DLAT;
    float rv[8];
    float s = 0.f;
#pragma unroll
    for (int i = 0; i < 8; i++) { rv[i] = r[lane + 32 * i]; s += rv[i] * rv[i]; }
#pragma unroll
    for (int o = 16; o; o >>= 1) s += __shfl_xor_sync(0xffffffffu, s, o);
    const float rnorm = s;

    float bm = (lane < 8) ? __ldg(gbmin + (size_t)row * 8 + lane) : INFINITY;
    float gmin = bm;
#pragma unroll
    for (int o = 16; o; o >>= 1) gmin = fminf(gmin, __shfl_xor_sync(0xffffffffu, gmin, o));
    const float th = gmin + VQ_MARGIN;
    float myblk = __shfl_sync(0xffffffffu, bm, lane >> 2);

    uint32_t cmask = __ldg(gmask + (size_t)row * 32 + lane);
    if (myblk > th) cmask = 0;

    float bestv = INFINITY;
    int   bestn = KCODE;
    for (;;) {
        uint32_t ball = __ballot_sync(0xffffffffu, cmask != 0);
        if (!ball) break;
        int src = __ffs(ball) - 1;
        uint32_t m = __shfl_sync(0xffffffffu, cmask, src);
        int j = __ffs(m) - 1;
        if (lane == src) cmask &= cmask - 1;
        int n = (src >> 2) * 128 + (src & 3) * 32 + j;

        const float* c = cb + (size_t)n * DLAT;
        float dot = 0.f;
#pragma unroll
        for (int i = 0; i < 8; i++) dot += rv[i] * c[lane + 32 * i];
#pragma unroll
        for (int o = 16; o; o >>= 1) dot += __shfl_xor_sync(0xffffffffu, dot, o);

        float d = (rnorm - 2.0f * dot) + cbn[n];
        if (d < bestv || (d == bestv && n < bestn)) { bestv = d; bestn = n; }
    }
    const int bi = bestn;
    if (lane == 0) out_idx[row * 3 + stage] = (float)bi;

    const float* c = cb + (size_t)bi * DLAT;
    float* q = zq + (size_t)row * DLAT;
    float se = 0.f;
#pragma unroll
    for (int i = 0; i < 8; i++) {
        int col = lane + 32 * i;
        float ev = c[col];
        float diff = rv[i] - ev;
        se += diff * diff;
        float t   = ev - rv[i];
        float zqe = rv[i] + t;
        if (stage < 2) r[col] = rv[i] - zqe;
        q[col] = (stage == 0) ? zqe : (q[col] + zqe);
    }
#pragma unroll
    for (int o = 16; o; o >>= 1) se += __shfl_xor_sync(0xffffffffu, se, o);
    if (lane == 0) {
        float m = se * (1.0f / 256.0f);
        float l = m + 0.25f * m;
        out_loss[row] = (stage == 0) ? l : (out_loss[row] + l);
    }
}

// ---------------------------------------------------------------------------
// Finalize2: out_loss[row] += sum(part[row][0..63]) / 2048. Warp per row.
// ---------------------------------------------------------------------------
__global__ __launch_bounds__(256)
void finalize2_kernel(const float* __restrict__ part, float* __restrict__ out_loss)
{
    int row  = blockIdx.x * 8 + (threadIdx.x >> 5);
    int lane = threadIdx.x & 31;
    const float* p = part + (size_t)row * 64;
    float s = p[lane] + p[lane + 32];
#pragma unroll
    for (int o = 16; o; o >>= 1) s += __shfl_xor_sync(0xffffffffu, s, o);
    if (lane == 0) out_loss[row] += s * (1.0f / 2048.0f);
}

// ---------------------------------------------------------------------------
// Launch
// ---------------------------------------------------------------------------
extern "C" void kernel_launch(void* const* d_in, const int* in_sizes, int n_in,
                              void* d_out, int out_size)
{
    const float* x      = (const float*)d_in[0];
    const float* encW1  = (const float*)d_in[1];
    const float* encb1  = (const float*)d_in[2];
    const float* encW2  = (const float*)d_in[3];
    const float* encb2  = (const float*)d_in[4];
    const float* encW3  = (const float*)d_in[5];
    const float* encb3  = (const float*)d_in[6];
    const float* ln_g   = (const float*)d_in[7];
    const float* ln_b   = (const float*)d_in[8];
    const float* cb0    = (const float*)d_in[9];
    const float* cb1    = (const float*)d_in[10];
    const float* cb2    = (const float*)d_in[11];
    const float* decW1  = (const float*)d_in[12];
    const float* decb1  = (const float*)d_in[13];
    const float* decW2  = (const float*)d_in[14];
    const float* decb2  = (const float*)d_in[15];
    const float* decW3  = (const float*)d_in[16];
    const float* decb3  = (const float*)d_in[17];

    float *h1, *h2, *res, *zq, *cbn, *partp, *bminp;
    uint32_t* maskp;
    __half *w1h, *w1l, *w2h, *w2l, *w3h, *w3l;
    __half *d1h, *d2h, *d3h, *cbh;
    cudaGetSymbolAddress((void**)&h1, g_h1);
    cudaGetSymbolAddress((void**)&h2, g_h2);
    cudaGetSymbolAddress((void**)&res, g_res);
    cudaGetSymbolAddress((void**)&zq, g_zq);
    cudaGetSymbolAddress((void**)&cbn, g_cbn);
    cudaGetSymbolAddress((void**)&partp, g_part);
    cudaGetSymbolAddress((void**)&maskp, g_mask);
    cudaGetSymbolAddress((void**)&bminp, g_bmin);
    cudaGetSymbolAddress((void**)&w1h, g_w1h); cudaGetSymbolAddress((void**)&w1l, g_w1l);
    cudaGetSymbolAddress((void**)&w2h, g_w2h); cudaGetSymbolAddress((void**)&w2l, g_w2l);
    cudaGetSymbolAddress((void**)&w3h, g_w3h); cudaGetSymbolAddress((void**)&w3l, g_w3l);
    cudaGetSymbolAddress((void**)&d1h, g_d1h);
    cudaGetSymbolAddress((void**)&d2h, g_d2h);
    cudaGetSymbolAddress((void**)&d3h, g_d3h);
    cudaGetSymbolAddress((void**)&cbh, g_cbh);

    float* xhat     = (float*)d_out;
    float* out_loss = xhat + (size_t)BATCH * D_IN;
    float* out_idx  = out_loss + BATCH;

    const int SMEM3 = 1024 + 2 * 16384;  // 33792
    const int SMEM1 = 1024 + 2 * 8192;   // 17408
    cudaFuncSetAttribute((const void*)mma_gemm_h<3, true,  true,  false, false>, cudaFuncAttributeMaxDynamicSharedMemorySize, SMEM3);
    cudaFuncSetAttribute((const void*)mma_gemm_h<3, false, true,  false, false>, cudaFuncAttributeMaxDynamicSharedMemorySize, SMEM3);
    cudaFuncSetAttribute((const void*)mma_gemm_h<1, false, false, false, true >, cudaFuncAttributeMaxDynamicSharedMemorySize, SMEM1);
    cudaFuncSetAttribute((const void*)mma_gemm_h<1, true,  true,  false, false>, cudaFuncAttributeMaxDynamicSharedMemorySize, SMEM1);
    cudaFuncSetAttribute((const void*)mma_gemm_h<1, false, true,  true,  false>, cudaFuncAttributeMaxDynamicSharedMemorySize, SMEM1);

    const dim3 blk(256);
    const dim3 ggrid(GEMM_GRID);
    const int MB = BATCH / 128;          // 128
    const int warpGrid = BATCH / 8;      // 2048

    // ---- fused prep (transposes + codebook prep + counter reset), 1 launch ----
    mega_prep<<<2048 + 512 + 128 + 128 + 512 + 2048 + 384, blk>>>(
        encW1, encW2, encW3, decW1, decW2, decW3, cb0, cb1, cb2,
        w1h, w1l, w2h, w2l, w3h, w3l, d1h, d2h, d3h, cbh, cbn);

    // ---- encoder (fp16 split x3 ~ fp32 accuracy; feeds argmin) ----
    mma_gemm_h<3, true,  true,  false, false><<<ggrid, blk, SMEM3>>>(x,  w1h, w1l, encb1, h1,  H1D,  D_IN, H1D / 128, (H1D / 128) * MB, 0, nullptr, nullptr, nullptr, nullptr, nullptr);
    mma_gemm_h<3, true,  true,  false, false><<<ggrid, blk, SMEM3>>>(h1, w2h, w2l, encb2, h2,  H2D,  H1D,  H2D / 128, (H2D / 128) * MB, 1, nullptr, nullptr, nullptr, nullptr, nullptr);
    mma_gemm_h<3, false, true,  false, false><<<ggrid, blk, SMEM3>>>(h2, w3h, w3l, encb3, res, DLAT, H2D,  DLAT / 128, (DLAT / 128) * MB, 2, nullptr, nullptr, nullptr, nullptr, nullptr);

    ln_kernel<<<warpGrid, blk>>>(res, ln_g, ln_b);

    // ---- residual VQ: fused score+mask+blockmin GEMM, pruned exact refine ----
    for (int s = 0; s < 3; s++) {
        const float* cb = (s == 0) ? cb0 : (s == 1 ? cb1 : cb2);
        mma_gemm_h<1, false, false, false, true><<<ggrid, blk, SMEM1>>>(
            res, cbh + (size_t)s * KCODE * DLAT, nullptr, nullptr, nullptr, KCODE, DLAT,
            KCODE / 128, (KCODE / 128) * MB, 3 + s,
            nullptr, nullptr, cbn + s * KCODE, maskp, bminp);
        vq_step<<<warpGrid, blk>>>(res, maskp, bminp, cbn + s * KCODE, cb, zq, out_loss, out_idx, s);
    }

    // ---- decoder (fp16 single-pass; L3 fuses recon-SSE partials) ----
    mma_gemm_h<1, true,  true,  false, false><<<ggrid, blk, SMEM1>>>(zq, d1h, nullptr, decb1, h2,   H2D,  DLAT, H2D / 128, (H2D / 128) * MB, 6, nullptr, nullptr, nullptr, nullptr, nullptr);
    mma_gemm_h<1, true,  true,  false, false><<<ggrid, blk, SMEM1>>>(h2, d2h, nullptr, decb2, h1,   H1D,  H2D,  H1D / 128, (H1D / 128) * MB, 7, nullptr, nullptr, nullptr, nullptr, nullptr);
    mma_gemm_h<1, false, true,  true,  false><<<ggrid, blk, SMEM1>>>(h1, d3h, nullptr, decb3, xhat, D_IN, H1D,  D_IN / 128, (D_IN / 128) * MB, 8, x, partp, nullptr, nullptr, nullptr);

    finalize2_kernel<<<warpGrid, blk>>>(partp, out_loss);
}